// round 3
// baseline (speedup 1.0000x reference)
#include <cuda_runtime.h>

typedef unsigned long long ull;

// ---------------- device scratch ----------------
__device__ float g_kT[16777216];   // [b][d][n] transposed K
__device__ float g_v [16777216];   // [b][n][d]
__device__ float g_slots[32768];   // [b][k][d]
__device__ float g_Up[262144];     // [chunk(8)][b][k][d]
__device__ float g_Sp[4096];       // [chunk(8)][b][k]
__device__ float g_WqT [4096];     // [d][e]
__device__ float g_wihT[12288];    // [d][j<192]
__device__ float g_whhT[12288];
__device__ float g_w1T [8192];     // [d][j<128]
__device__ float g_w2T [8192];     // [j<128][o<64]

#define FMA2(acc, a, b) asm("fma.rn.f32x2 %0, %1, %2, %0;" : "+l"(acc) : "l"(a), "l"(b))
#define PACK2(dst, x, y) asm("mov.b64 %0, {%1, %2};" : "=l"(dst) : "f"(x), "f"(y))

__device__ __forceinline__ float sigf(float x) { return 1.f / (1.f + __expf(-x)); }

// ---------------- prep: weight transposes + slots init (one launch) ----------------
__global__ void prep(const float* __restrict__ Wq, const float* __restrict__ wih,
                     const float* __restrict__ whh, const float* __restrict__ w1,
                     const float* __restrict__ w2, const float* __restrict__ noise,
                     const float* __restrict__ mu, const float* __restrict__ lsig) {
    int t = blockIdx.x * 256 + threadIdx.x;   // grid 128 -> 32768 threads
    { int d = t & 63; g_slots[t] = __ldg(mu + d) + __expf(__ldg(lsig + d)) * noise[t]; }
    if (t < 4096)  { int e = t >> 6, d = t & 63;  g_WqT[d*64 + e]  = Wq[t]; }
    if (t < 12288) { int j = t >> 6, d = t & 63;  g_wihT[d*192 + j] = wih[t];
                                                   g_whhT[d*192 + j] = whh[t]; }
    if (t < 8192)  { int j = t >> 6, d = t & 63;  g_w1T[d*128 + j] = w1[t]; }
    if (t < 8192)  { int o = t >> 7, j = t & 127; g_w2T[j*64 + o]  = w2[t]; }
}

// ---------------- fused input LN + K^T/V projection ----------------
__global__ void __launch_bounds__(256) ln_kv(const float* __restrict__ inp,
        const float* __restrict__ Wk, const float* __restrict__ Wv,
        const float* __restrict__ lng, const float* __restrict__ lnb) {
    __shared__ __align__(16) float xs[32 * 66];
    __shared__ __align__(16) float ws[128 * 64];  // Wk rows 0..63, Wv rows 64..127; reused as staging
    int t = threadIdx.x;
    int r0 = blockIdx.x * 32;
    const float* ip = inp + (size_t)r0 * 64;
    #pragma unroll
    for (int i = 0; i < 8; i++) { int id = t + 256*i; xs[(id>>6)*66 + (id&63)] = ip[id]; }
    #pragma unroll
    for (int i = 0; i < 16; i++) { int id = t + 256*i; ws[id] = Wk[id]; ws[4096+id] = Wv[id]; }
    __syncthreads();
    {   // LayerNorm: 8 threads/row
        int row = t >> 3, sub = t & 7;
        float s = 0.f, ss = 0.f;
        #pragma unroll
        for (int i = 0; i < 8; i++) { float x = xs[row*66 + sub*8 + i]; s += x; ss += x*x; }
        s += __shfl_xor_sync(~0u, s, 1); ss += __shfl_xor_sync(~0u, ss, 1);
        s += __shfl_xor_sync(~0u, s, 2); ss += __shfl_xor_sync(~0u, ss, 2);
        s += __shfl_xor_sync(~0u, s, 4); ss += __shfl_xor_sync(~0u, ss, 4);
        float mu = s * 0.015625f;
        float rstd = rsqrtf(ss * 0.015625f - mu*mu + 1e-5f);
        #pragma unroll
        for (int i = 0; i < 8; i++) {
            int f = sub*8 + i;
            xs[row*66 + f] = (xs[row*66 + f] - mu) * rstd * __ldg(lng+f) + __ldg(lnb+f);
        }
    }
    __syncthreads();
    // GEMM: thread (tx,ty): rows tx,tx+16; out dims ty*8..ty*8+7. Weight loads LDS.128.
    int tx = t & 15, ty = t >> 4;
    ull acc[8][2];
    #pragma unroll
    for (int j = 0; j < 8; j++) { acc[j][0] = 0ull; acc[j][1] = 0ull; }
    #pragma unroll 4
    for (int f4 = 0; f4 < 16; f4++) {           // 4 f-dims per step
        ull a0l = *(const ull*)&xs[tx*66 + 4*f4];
        ull a0h = *(const ull*)&xs[tx*66 + 4*f4 + 2];
        ull a1l = *(const ull*)&xs[(tx+16)*66 + 4*f4];
        ull a1h = *(const ull*)&xs[(tx+16)*66 + 4*f4 + 2];
        #pragma unroll
        for (int j = 0; j < 8; j++) {
            ulonglong2 bq = *(const ulonglong2*)&ws[(ty*8 + j)*64 + 4*f4];  // one LDS.128
            FMA2(acc[j][0], bq.x, a0l); FMA2(acc[j][0], bq.y, a0h);
            FMA2(acc[j][1], bq.x, a1l); FMA2(acc[j][1], bq.y, a1h);
        }
    }
    float cs[8][2];
    #pragma unroll
    for (int j = 0; j < 8; j++)
        #pragma unroll
        for (int i = 0; i < 2; i++) { float2 f = *reinterpret_cast<float2*>(&acc[j][i]); cs[j][i] = f.x + f.y; }

    int b = r0 >> 12, nn0 = r0 & 4095;
    float* os = ws;
    __syncthreads();
    if (ty < 8) {   // K wave -> transposed store
        #pragma unroll
        for (int j = 0; j < 8; j++) {
            int od = ty*8 + j;
            os[tx*66 + od] = cs[j][0];
            os[(tx+16)*66 + od] = cs[j][1];
        }
    }
    __syncthreads();
    #pragma unroll
    for (int i = 0; i < 8; i++) {
        int id = t + 256*i; int d = id >> 5, row = id & 31;
        g_kT[((size_t)b*64 + d)*4096 + nn0 + row] = os[row*66 + d];
    }
    __syncthreads();
    if (ty >= 8) {  // V wave -> natural store
        #pragma unroll
        for (int j = 0; j < 8; j++) {
            int od = ty*8 + j - 64;
            os[tx*66 + od] = cs[j][0];
            os[(tx+16)*66 + od] = cs[j][1];
        }
    }
    __syncthreads();
    #pragma unroll
    for (int i = 0; i < 8; i++) {
        int id = t + 256*i; int d = id & 63, row = id >> 6;
        g_v[((size_t)r0 + row)*64 + d] = os[row*66 + d];
    }
}

// ---------------- attention: fused slots-LN + q, logits+softmax, U/S partials ----------------
__global__ void __launch_bounds__(256) attn_kernel(const float* __restrict__ lng,
                                                   const float* __restrict__ lnb) {
    __shared__ __align__(16) float sn_s[512];      // LN'd slots [k][d]; later sred[64]
    __shared__ __align__(16) float qst[512];       // q transposed [e][j] stride 8
    __shared__ __align__(16) float attn2[8192];    // [n][j] float2 duplicated; later red[8][512]
    int t = threadIdx.x, b = blockIdx.y, n0 = blockIdx.x * 512;

    // slots LN: warp w -> slot row w
    {
        int w = t >> 5, lane = t & 31;
        float s0 = g_slots[b*512 + w*64 + lane];
        float s1 = g_slots[b*512 + w*64 + 32 + lane];
        float s = s0 + s1, ss = s0*s0 + s1*s1;
        #pragma unroll
        for (int o = 16; o > 0; o >>= 1) { s += __shfl_xor_sync(~0u, s, o); ss += __shfl_xor_sync(~0u, ss, o); }
        float mu = s * 0.015625f;
        float rstd = rsqrtf(ss * 0.015625f - mu*mu + 1e-5f);
        sn_s[w*64 + lane]      = (s0 - mu)*rstd*__ldg(lng+lane)    + __ldg(lnb+lane);
        sn_s[w*64 + 32 + lane] = (s1 - mu)*rstd*__ldg(lng+32+lane) + __ldg(lnb+32+lane);
    }
    __syncthreads();
    // q projection: thread computes q[kk][e] for kk = t>>6, t>>6 + 4; e = t&63
    {
        int e = t & 63, kk0 = t >> 6;
        #pragma unroll
        for (int kk = kk0; kk < 8; kk += 4) {
            float a = 0.f;
            #pragma unroll 16
            for (int d = 0; d < 64; d++) a += sn_s[kk*64 + d] * __ldg(&g_WqT[d*64 + e]);
            qst[e*8 + kk] = a;
        }
    }
    __syncthreads();

    // logits + softmax + eps; store attn duplicated (a,a) pairs
    float sacc[8];
    #pragma unroll
    for (int j = 0; j < 8; j++) sacc[j] = 0.f;
    #pragma unroll
    for (int rep = 0; rep < 2; rep++) {
        int nl = rep*256 + t;
        const float* kp = g_kT + (size_t)b*262144 + n0 + nl;
        float l[8];
        #pragma unroll
        for (int j = 0; j < 8; j++) l[j] = 0.f;
        #pragma unroll 8
        for (int e = 0; e < 64; e++) {
            float kd = __ldg(kp + e*4096);
            float4 qa = *(const float4*)&qst[e*8];
            float4 qb = *(const float4*)&qst[e*8 + 4];
            l[0] += kd*qa.x; l[1] += kd*qa.y; l[2] += kd*qa.z; l[3] += kd*qa.w;
            l[4] += kd*qb.x; l[5] += kd*qb.y; l[6] += kd*qb.z; l[7] += kd*qb.w;
        }
        float m = l[0];
        #pragma unroll
        for (int j = 1; j < 8; j++) m = fmaxf(m, l[j]);
        float s = 0.f, ex[8];
        #pragma unroll
        for (int j = 0; j < 8; j++) { ex[j] = __expf((l[j] - m) * 0.125f); s += ex[j]; }
        float inv = 1.0f / s;
        float a[8];
        #pragma unroll
        for (int j = 0; j < 8; j++) { a[j] = ex[j]*inv + 1e-8f; sacc[j] += a[j]; }
        *(float4*)&attn2[nl*16]      = make_float4(a[0], a[0], a[1], a[1]);
        *(float4*)&attn2[nl*16 + 4]  = make_float4(a[2], a[2], a[3], a[3]);
        *(float4*)&attn2[nl*16 + 8]  = make_float4(a[4], a[4], a[5], a[5]);
        *(float4*)&attn2[nl*16 + 12] = make_float4(a[6], a[6], a[7], a[7]);
    }
    // deterministic S reduce
    #pragma unroll
    for (int j = 0; j < 8; j++) {
        float v = sacc[j];
        #pragma unroll
        for (int o = 16; o > 0; o >>= 1) v += __shfl_xor_sync(~0u, v, o);
        if ((t & 31) == 0) sn_s[(t>>5)*8 + j] = v;
    }
    __syncthreads();
    if (t < 8) {
        float v = 0.f;
        #pragma unroll
        for (int w = 0; w < 8; w++) v += sn_s[w*8 + t];
        g_Sp[blockIdx.x*512 + b*8 + t] = v;
    }

    // update: warp = token group (64 tokens), lane = d-pair; FMA2
    int d2 = t & 31, grp = t >> 5;
    ull acc2[8];
    #pragma unroll
    for (int j = 0; j < 8; j++) acc2[j] = 0ull;
    const float2* vp = (const float2*)g_v + ((size_t)b*4096 + n0)*32 + d2;
    int nbeg = grp * 64;
    #pragma unroll 4
    for (int n = nbeg; n < nbeg + 64; n++) {
        float2 vv = __ldg(vp + (size_t)n*32);
        ull vu; PACK2(vu, vv.x, vv.y);
        const ulonglong2* ap = (const ulonglong2*)&attn2[n*16];
        ulonglong2 p01 = ap[0], p23 = ap[1], p45 = ap[2], p67 = ap[3];
        FMA2(acc2[0], p01.x, vu); FMA2(acc2[1], p01.y, vu);
        FMA2(acc2[2], p23.x, vu); FMA2(acc2[3], p23.y, vu);
        FMA2(acc2[4], p45.x, vu); FMA2(acc2[5], p45.y, vu);
        FMA2(acc2[6], p67.x, vu); FMA2(acc2[7], p67.y, vu);
    }
    __syncthreads();                // all attn2 reads done
    float* red = attn2;             // [grp][j*64 + d]
    #pragma unroll
    for (int j = 0; j < 8; j++) {
        float2 r = *reinterpret_cast<float2*>(&acc2[j]);
        *(float2*)&red[grp*512 + j*64 + d2*2] = r;
    }
    __syncthreads();
    #pragma unroll
    for (int rep = 0; rep < 2; rep++) {
        int idx = rep*256 + t;
        float v = 0.f;
        #pragma unroll
        for (int g = 0; g < 8; g++) v += red[g*512 + idx];
        g_Up[((size_t)blockIdx.x*64 + b)*512 + idx] = v;
    }
}

// ---------------- GRU + LN + MLP + residual ----------------
__global__ void __launch_bounds__(192) gru_mlp(const float* __restrict__ bih, const float* __restrict__ bhh,
        const float* __restrict__ b1, const float* __restrict__ b2,
        const float* __restrict__ lng, const float* __restrict__ lnb,
        float* __restrict__ out, int last) {
    __shared__ float u_s[64], h_s[64], gi_s[192], gh_s[192], hn_s[64], ln_s[64], h1_s[128];
    int row = blockIdx.x, t = threadIdx.x;
    if (t < 64) {
        float S = 0.f, U = 0.f;
        #pragma unroll
        for (int c = 0; c < 8; c++) { S += g_Sp[c*512 + row]; U += g_Up[c*32768 + row*64 + t]; }
        u_s[t] = U / S;
        h_s[t] = g_slots[row*64 + t];
    }
    __syncthreads();
    {
        float gi = __ldg(bih + t), gh = __ldg(bhh + t);
        #pragma unroll 8
        for (int d = 0; d < 64; d++) {
            gi += u_s[d] * __ldg(&g_wihT[d*192 + t]);
            gh += h_s[d] * __ldg(&g_whhT[d*192 + t]);
        }
        gi_s[t] = gi; gh_s[t] = gh;
    }
    __syncthreads();
    if (t < 64) {
        float r = sigf(gi_s[t] + gh_s[t]);
        float z = sigf(gi_s[64+t] + gh_s[64+t]);
        float n = tanhf(gi_s[128+t] + r * gh_s[128+t]);
        hn_s[t] = (1.f - z)*n + z*h_s[t];
    }
    __syncthreads();
    if (t < 64) {
        float s = 0.f, ss = 0.f;
        #pragma unroll 8
        for (int d = 0; d < 64; d++) { float x = hn_s[d]; s += x; ss += x*x; }
        float mu = s * 0.015625f;
        float rstd = rsqrtf(ss * 0.015625f - mu*mu + 1e-5f);
        ln_s[t] = (hn_s[t] - mu)*rstd*__ldg(lng+t) + __ldg(lnb+t);
    }
    __syncthreads();
    if (t < 128) {
        float h1 = __ldg(b1 + t);
        #pragma unroll 8
        for (int d = 0; d < 64; d++) h1 += ln_s[d] * __ldg(&g_w1T[d*128 + t]);
        h1_s[t] = fmaxf(h1, 0.f);
    }
    __syncthreads();
    if (t < 64) {
        float o = __ldg(b2 + t);
        #pragma unroll 8
        for (int j = 0; j < 128; j++) o += h1_s[j] * __ldg(&g_w2T[j*64 + t]);
        float res = hn_s[t] + o;
        g_slots[row*64 + t] = res;
        if (last) out[row*64 + t] = res;
    }
}

extern "C" void kernel_launch(void* const* d_in, const int* in_sizes, int n_in,
                              void* d_out, int out_size) {
    const float* inputs = (const float*)d_in[0];
    const float* noise  = (const float*)d_in[1];
    const float* mu     = (const float*)d_in[2];
    const float* lsig   = (const float*)d_in[3];
    const float* Wq     = (const float*)d_in[4];
    const float* Wk     = (const float*)d_in[5];
    const float* Wv     = (const float*)d_in[6];
    const float* wih    = (const float*)d_in[7];
    const float* whh    = (const float*)d_in[8];
    const float* bih    = (const float*)d_in[9];
    const float* bhh    = (const float*)d_in[10];
    const float* w1     = (const float*)d_in[11];
    const float* b1     = (const float*)d_in[12];
    const float* w2     = (const float*)d_in[13];
    const float* b2     = (const float*)d_in[14];
    const float* ln_in_g   = (const float*)d_in[15];
    const float* ln_in_b   = (const float*)d_in[16];
    const float* ln_sl_g   = (const float*)d_in[17];
    const float* ln_sl_b   = (const float*)d_in[18];
    const float* ln_mlp_g  = (const float*)d_in[19];
    const float* ln_mlp_b  = (const float*)d_in[20];
    float* out = (float*)d_out;

    prep<<<128, 256>>>(Wq, wih, whh, w1, w2, noise, mu, lsig);
    ln_kv<<<8192, 256>>>(inputs, Wk, Wv, ln_in_g, ln_in_b);
    for (int it = 0; it < 3; it++) {
        attn_kernel<<<dim3(8, 64), 256>>>(ln_sl_g, ln_sl_b);
        gru_mlp<<<512, 192>>>(bih, bhh, b1, b2, ln_mlp_g, ln_mlp_b, out, it == 2);
    }
}

// round 5
// speedup vs baseline: 1.3812x; 1.3812x over previous
#include <cuda_runtime.h>

typedef unsigned long long ull;

// ---------------- device scratch ----------------
__device__ float g_kT[16777216];   // [b][d][n] transposed K
__device__ float g_v [16777216];   // [b][n][d]
__device__ float g_slots[32768];   // [b][k][d]
__device__ float g_q[32768];
__device__ float g_Up[262144];     // [chunk(8)][b][k][d]
__device__ float g_Sp[4096];       // [chunk(8)][b*8+k]
__device__ float g_WqT [4096];     // [d][e]
__device__ float g_wihT[12288];    // [d][j<192]
__device__ float g_whhT[12288];
__device__ float g_w1T [8192];     // [d][j<128]
__device__ float g_w2T [8192];     // [j<128][o<64]

#define FMA2(acc, a, b) asm("fma.rn.f32x2 %0, %1, %2, %0;" : "+l"(acc) : "l"(a), "l"(b))

__device__ __forceinline__ float sigf(float x) { return 1.f / (1.f + __expf(-x)); }

// ---------------- prep: weight transposes + slots init ----------------
__global__ void prep(const float* __restrict__ Wq, const float* __restrict__ wih,
                     const float* __restrict__ whh, const float* __restrict__ w1,
                     const float* __restrict__ w2, const float* __restrict__ noise,
                     const float* __restrict__ mu, const float* __restrict__ lsig) {
    int t = blockIdx.x * 256 + threadIdx.x;   // grid 128 -> 32768 threads
    { int d = t & 63; g_slots[t] = __ldg(mu + d) + __expf(__ldg(lsig + d)) * noise[t]; }
    if (t < 4096)  { int e = t >> 6, d = t & 63;  g_WqT[d*64 + e]  = Wq[t]; }
    if (t < 12288) { int j = t >> 6, d = t & 63;  g_wihT[d*192 + j] = wih[t];
                                                   g_whhT[d*192 + j] = whh[t]; }
    if (t < 8192)  { int j = t >> 6, d = t & 63;  g_w1T[d*128 + j] = w1[t]; }
    if (t < 8192)  { int o = t >> 7, j = t & 127; g_w2T[j*64 + o]  = w2[t]; }
}

// ---------------- fused input LN + K^T/V projection (proven 357us form) ----------------
__global__ void __launch_bounds__(256) ln_kv(const float* __restrict__ inp,
        const float* __restrict__ Wk, const float* __restrict__ Wv,
        const float* __restrict__ lng, const float* __restrict__ lnb) {
    __shared__ __align__(16) float xs[32 * 66];
    __shared__ __align__(16) float ws[128 * 64];
    int t = threadIdx.x;
    int r0 = blockIdx.x * 32;
    const float* ip = inp + (size_t)r0 * 64;
    #pragma unroll
    for (int i = 0; i < 8; i++) { int id = t + 256*i; xs[(id>>6)*66 + (id&63)] = ip[id]; }
    #pragma unroll
    for (int i = 0; i < 16; i++) { int id = t + 256*i; ws[id] = Wk[id]; ws[4096+id] = Wv[id]; }
    __syncthreads();
    {   // LayerNorm: 8 threads/row
        int row = t >> 3, sub = t & 7;
        float s = 0.f, ss = 0.f;
        #pragma unroll
        for (int i = 0; i < 8; i++) { float x = xs[row*66 + sub*8 + i]; s += x; ss += x*x; }
        s += __shfl_xor_sync(~0u, s, 1); ss += __shfl_xor_sync(~0u, ss, 1);
        s += __shfl_xor_sync(~0u, s, 2); ss += __shfl_xor_sync(~0u, ss, 2);
        s += __shfl_xor_sync(~0u, s, 4); ss += __shfl_xor_sync(~0u, ss, 4);
        float mu = s * 0.015625f;
        float rstd = rsqrtf(ss * 0.015625f - mu*mu + 1e-5f);
        #pragma unroll
        for (int i = 0; i < 8; i++) {
            int f = sub*8 + i;
            xs[row*66 + f] = (xs[row*66 + f] - mu) * rstd * __ldg(lng+f) + __ldg(lnb+f);
        }
    }
    __syncthreads();
    int tx = t & 15, ty = t >> 4;
    ull acc[8][2];
    #pragma unroll
    for (int j = 0; j < 8; j++) { acc[j][0] = 0ull; acc[j][1] = 0ull; }
    const ull* ws2 = (const ull*)ws;
    #pragma unroll 8
    for (int f2 = 0; f2 < 32; f2++) {
        ull a0 = *(const ull*)&xs[tx*66 + 2*f2];
        ull a1 = *(const ull*)&xs[(tx+16)*66 + 2*f2];
        #pragma unroll
        for (int j = 0; j < 8; j++) {
            ull bb = ws2[(ty*8 + j)*32 + f2];
            FMA2(acc[j][0], bb, a0);
            FMA2(acc[j][1], bb, a1);
        }
    }
    float cs[8][2];
    #pragma unroll
    for (int j = 0; j < 8; j++)
        #pragma unroll
        for (int i = 0; i < 2; i++) { float2 f = *reinterpret_cast<float2*>(&acc[j][i]); cs[j][i] = f.x + f.y; }

    int b = r0 >> 12, nn0 = r0 & 4095;
    float* os = ws;
    __syncthreads();
    if (ty < 8) {
        #pragma unroll
        for (int j = 0; j < 8; j++) {
            int od = ty*8 + j;
            os[tx*66 + od] = cs[j][0];
            os[(tx+16)*66 + od] = cs[j][1];
        }
    }
    __syncthreads();
    #pragma unroll
    for (int i = 0; i < 8; i++) {
        int id = t + 256*i; int d = id >> 5, row = id & 31;
        g_kT[((size_t)b*64 + d)*4096 + nn0 + row] = os[row*66 + d];
    }
    __syncthreads();
    if (ty >= 8) {
        #pragma unroll
        for (int j = 0; j < 8; j++) {
            int od = ty*8 + j - 64;
            os[tx*66 + od] = cs[j][0];
            os[(tx+16)*66 + od] = cs[j][1];
        }
    }
    __syncthreads();
    #pragma unroll
    for (int i = 0; i < 8; i++) {
        int id = t + 256*i; int d = id & 63, row = id >> 6;
        g_v[((size_t)r0 + row)*64 + d] = os[row*66 + d];
    }
}

// ---------------- slots LN + Q projection (proven form) ----------------
__global__ void __launch_bounds__(256) q_kernel(const float* __restrict__ lng,
                                                const float* __restrict__ lnb) {
    __shared__ float sn_s[512];
    int b = blockIdx.x, t = threadIdx.x;
    int w = t >> 5, lane = t & 31;
    float s0 = g_slots[b*512 + w*64 + lane];
    float s1 = g_slots[b*512 + w*64 + 32 + lane];
    float s = s0 + s1, ss = s0*s0 + s1*s1;
    #pragma unroll
    for (int o = 16; o > 0; o >>= 1) { s += __shfl_xor_sync(~0u, s, o); ss += __shfl_xor_sync(~0u, ss, o); }
    float mu = s * 0.015625f;
    float rstd = rsqrtf(ss * 0.015625f - mu*mu + 1e-5f);
    sn_s[w*64 + lane]      = (s0 - mu)*rstd*__ldg(lng+lane)    + __ldg(lnb+lane);
    sn_s[w*64 + 32 + lane] = (s1 - mu)*rstd*__ldg(lng+32+lane) + __ldg(lnb+32+lane);
    __syncthreads();
    int e = t & 63, k2 = t >> 6;
    #pragma unroll
    for (int kk = k2; kk < 8; kk += 4) {
        float a = 0.f;
        #pragma unroll 16
        for (int d = 0; d < 64; d++) a += sn_s[kk*64 + d] * __ldg(&g_WqT[d*64 + e]);
        g_q[b*512 + kk*64 + e] = a;
    }
}

// ---------------- attention (proven 357us form) ----------------
__global__ void __launch_bounds__(256) attn_kernel() {
    __shared__ float qs[512];
    __shared__ float attn_s[512 * 9];
    __shared__ float red[4 * 512];
    __shared__ float sred[64];
    int t = threadIdx.x, b = blockIdx.y, n0 = blockIdx.x * 512;
    qs[t] = g_q[b*512 + t]; qs[t+256] = g_q[b*512 + 256 + t];
    __syncthreads();

    float sacc[8];
    #pragma unroll
    for (int j = 0; j < 8; j++) sacc[j] = 0.f;
    #pragma unroll
    for (int rep = 0; rep < 2; rep++) {
        int nl = rep*256 + t;
        const float* kp = g_kT + (size_t)b*262144 + n0 + nl;
        float l[8];
        #pragma unroll
        for (int j = 0; j < 8; j++) l[j] = 0.f;
        #pragma unroll 16
        for (int d = 0; d < 64; d++) {
            float kd = __ldg(kp + d*4096);
            #pragma unroll
            for (int j = 0; j < 8; j++) l[j] += kd * qs[j*64 + d];
        }
        float m = l[0];
        #pragma unroll
        for (int j = 1; j < 8; j++) m = fmaxf(m, l[j]);
        float s = 0.f, e[8];
        #pragma unroll
        for (int j = 0; j < 8; j++) { e[j] = __expf((l[j] - m) * 0.125f); s += e[j]; }
        float inv = 1.0f / s;
        #pragma unroll
        for (int j = 0; j < 8; j++) {
            float a = e[j]*inv + 1e-8f;
            sacc[j] += a;
            attn_s[nl*9 + j] = a;
        }
    }
    #pragma unroll
    for (int j = 0; j < 8; j++) {
        float v = sacc[j];
        #pragma unroll
        for (int o = 16; o > 0; o >>= 1) v += __shfl_xor_sync(~0u, v, o);
        if ((t & 31) == 0) sred[(t>>5)*8 + j] = v;
    }
    __syncthreads();
    if (t < 8) {
        float v = 0.f;
        #pragma unroll
        for (int w = 0; w < 8; w++) v += sred[w*8 + t];
        g_Sp[blockIdx.x*512 + b*8 + t] = v;
    }
    int d = t & 63, grp = t >> 6;
    float acc[8];
    #pragma unroll
    for (int j = 0; j < 8; j++) acc[j] = 0.f;
    const float* vp = g_v + ((size_t)b*4096 + n0)*64 + d;
    int nb = grp * 128;
    #pragma unroll 4
    for (int n = nb; n < nb + 128; n++) {
        float vv = __ldg(vp + n*64);
        #pragma unroll
        for (int j = 0; j < 8; j++) acc[j] += attn_s[n*9 + j] * vv;
    }
    #pragma unroll
    for (int j = 0; j < 8; j++) red[grp*512 + j*64 + d] = acc[j];
    __syncthreads();
    #pragma unroll
    for (int rep = 0; rep < 2; rep++) {
        int e = rep*256 + t;
        float v = red[e] + red[512 + e] + red[1024 + e] + red[1536 + e];
        g_Up[((size_t)blockIdx.x*64 + b)*512 + e] = v;
    }
}

// ---------------- batched GRU + LN + MLP + residual: 4 rows/block ----------------
__global__ void __launch_bounds__(384) gru_mlp(const float* __restrict__ bih, const float* __restrict__ bhh,
        const float* __restrict__ b1, const float* __restrict__ b2,
        const float* __restrict__ lng, const float* __restrict__ lnb,
        float* __restrict__ out, int last) {
    __shared__ float u_s[256], h_s[256];       // 4 rows x 64
    __shared__ float gi_s[768], gh_s[768];     // 4 rows x 192
    __shared__ float hn_s[256], ln_s[256], h1_s[512];
    int t = threadIdx.x;
    int grow0 = blockIdx.x * 4;                // global rows grow0..grow0+3

    // Phase A: u = U/S, h = slots
    if (t < 256) {
        int r = t >> 6, d = t & 63;
        int grow = grow0 + r;
        float S = 0.f, U = 0.f;
        #pragma unroll
        for (int c = 0; c < 8; c++) {
            S += g_Sp[c*512 + grow];
            U += g_Up[c*32768 + grow*64 + d];
        }
        u_s[t] = U / S;
        h_s[t] = g_slots[grow*64 + d];
    }
    __syncthreads();

    // Phase B: gates. t<192: gi (input side), t>=192: gh (hidden side). 4 rows each.
    {
        int j = (t < 192) ? t : (t - 192);
        const float* W  = (t < 192) ? g_wihT : g_whhT;
        const float* xb = (t < 192) ? u_s : h_s;
        float acc0 = 0.f, acc1 = 0.f, acc2 = 0.f, acc3 = 0.f;
        #pragma unroll 8
        for (int d = 0; d < 64; d++) {
            float w = __ldg(&W[d*192 + j]);
            acc0 += xb[d]       * w;
            acc1 += xb[64 + d]  * w;
            acc2 += xb[128 + d] * w;
            acc3 += xb[192 + d] * w;
        }
        float bias = (t < 192) ? __ldg(bih + j) : __ldg(bhh + j);
        float* G = (t < 192) ? gi_s : gh_s;
        G[j]       = acc0 + bias;
        G[192 + j] = acc1 + bias;
        G[384 + j] = acc2 + bias;
        G[576 + j] = acc3 + bias;
    }
    __syncthreads();

    // Phase C: GRU combine
    if (t < 256) {
        int r = t >> 6, d = t & 63;
        float rr = sigf(gi_s[r*192 + d]       + gh_s[r*192 + d]);
        float z  = sigf(gi_s[r*192 + 64 + d]  + gh_s[r*192 + 64 + d]);
        float n  = tanhf(gi_s[r*192 + 128 + d] + rr * gh_s[r*192 + 128 + d]);
        hn_s[t] = (1.f - z)*n + z*h_s[t];
    }
    __syncthreads();

    // Phase D: LayerNorm, warp per row (warps 0..3)
    if (t < 128) {
        int r = t >> 5, lane = t & 31;
        float x0 = hn_s[r*64 + lane], x1 = hn_s[r*64 + 32 + lane];
        float s = x0 + x1, ss = x0*x0 + x1*x1;
        #pragma unroll
        for (int o = 16; o > 0; o >>= 1) { s += __shfl_xor_sync(~0u, s, o); ss += __shfl_xor_sync(~0u, ss, o); }
        float mu = s * 0.015625f;
        float rstd = rsqrtf(ss * 0.015625f - mu*mu + 1e-5f);
        ln_s[r*64 + lane]      = (x0 - mu)*rstd*__ldg(lng+lane)    + __ldg(lnb+lane);
        ln_s[r*64 + 32 + lane] = (x1 - mu)*rstd*__ldg(lng+32+lane) + __ldg(lnb+32+lane);
    }
    __syncthreads();

    // Phase E: MLP layer 1 + relu. t<128: output j for 4 rows.
    if (t < 128) {
        int j = t;
        float a0 = 0.f, a1 = 0.f, a2 = 0.f, a3 = 0.f;
        #pragma unroll 8
        for (int d = 0; d < 64; d++) {
            float w = __ldg(&g_w1T[d*128 + j]);
            a0 += ln_s[d]       * w;
            a1 += ln_s[64 + d]  * w;
            a2 += ln_s[128 + d] * w;
            a3 += ln_s[192 + d] * w;
        }
        float bias = __ldg(b1 + j);
        h1_s[j]       = fmaxf(a0 + bias, 0.f);
        h1_s[128 + j] = fmaxf(a1 + bias, 0.f);
        h1_s[256 + j] = fmaxf(a2 + bias, 0.f);
        h1_s[384 + j] = fmaxf(a3 + bias, 0.f);
    }
    __syncthreads();

    // Phase F: MLP layer 2 + residual. t<256: (row r, output o)
    if (t < 256) {
        int r = t >> 6, o = t & 63;
        float a = __ldg(b2 + o);
        #pragma unroll 8
        for (int j = 0; j < 128; j++) a += h1_s[r*128 + j] * __ldg(&g_w2T[j*64 + o]);
        float res = hn_s[r*64 + o] + a;
        int grow = grow0 + r;
        g_slots[grow*64 + o] = res;
        if (last) out[grow*64 + o] = res;
    }
}

extern "C" void kernel_launch(void* const* d_in, const int* in_sizes, int n_in,
                              void* d_out, int out_size) {
    const float* inputs = (const float*)d_in[0];
    const float* noise  = (const float*)d_in[1];
    const float* mu     = (const float*)d_in[2];
    const float* lsig   = (const float*)d_in[3];
    const float* Wq     = (const float*)d_in[4];
    const float* Wk     = (const float*)d_in[5];
    const float* Wv     = (const float*)d_in[6];
    const float* wih    = (const float*)d_in[7];
    const float* whh    = (const float*)d_in[8];
    const float* bih    = (const float*)d_in[9];
    const float* bhh    = (const float*)d_in[10];
    const float* w1     = (const float*)d_in[11];
    const float* b1     = (const float*)d_in[12];
    const float* w2     = (const float*)d_in[13];
    const float* b2     = (const float*)d_in[14];
    const float* ln_in_g   = (const float*)d_in[15];
    const float* ln_in_b   = (const float*)d_in[16];
    const float* ln_sl_g   = (const float*)d_in[17];
    const float* ln_sl_b   = (const float*)d_in[18];
    const float* ln_mlp_g  = (const float*)d_in[19];
    const float* ln_mlp_b  = (const float*)d_in[20];
    float* out = (float*)d_out;

    prep<<<128, 256>>>(Wq, wih, whh, w1, w2, noise, mu, lsig);
    ln_kv<<<8192, 256>>>(inputs, Wk, Wv, ln_in_g, ln_in_b);
    for (int it = 0; it < 3; it++) {
        q_kernel<<<64, 256>>>(ln_sl_g, ln_sl_b);
        attn_kernel<<<dim3(8, 64), 256>>>();
        gru_mlp<<<128, 384>>>(bih, bhh, b1, b2, ln_mlp_g, ln_mlp_b, out, it == 2);
    }
}

// round 6
// speedup vs baseline: 1.7802x; 1.2889x over previous
#include <cuda_runtime.h>
#include <cuda_bf16.h>

typedef unsigned long long ull;

// ---------------- device scratch ----------------
__device__ __nv_bfloat16 g_kT[16777216];  // [b][d][n] transposed K (bf16)
__device__ __nv_bfloat16 g_v [16777216];  // [b][n][d] (bf16)
__device__ float g_slots[32768];   // [b][k][d]
__device__ float g_q[65536];       // [b][e][j*2] duplicated-transposed q
__device__ float g_Up[262144];     // [chunk(8)][b][k][d]
__device__ float g_Sp[4096];       // [chunk(8)][b*8+k]
__device__ float g_WqT [4096];     // [d][e]
__device__ float g_wihT[12288];    // [d][j<192]
__device__ float g_whhT[12288];
__device__ float g_w1T [8192];     // [d][j<128]
__device__ float g_w2T [8192];     // [j<128][o<64]

#define FMA2(acc, a, b) asm("fma.rn.f32x2 %0, %1, %2, %0;" : "+l"(acc) : "l"(a), "l"(b))
#define PACK2(dst, x, y) asm("mov.b64 %0, {%1, %2};" : "=l"(dst) : "f"(x), "f"(y))

__device__ __forceinline__ float sigf(float x) { return 1.f / (1.f + __expf(-x)); }

// ---------------- prep: weight transposes + slots init ----------------
__global__ void prep(const float* __restrict__ Wq, const float* __restrict__ wih,
                     const float* __restrict__ whh, const float* __restrict__ w1,
                     const float* __restrict__ w2, const float* __restrict__ noise,
                     const float* __restrict__ mu, const float* __restrict__ lsig) {
    int t = blockIdx.x * 256 + threadIdx.x;   // grid 128 -> 32768 threads
    { int d = t & 63; g_slots[t] = __ldg(mu + d) + __expf(__ldg(lsig + d)) * noise[t]; }
    if (t < 4096)  { int e = t >> 6, d = t & 63;  g_WqT[d*64 + e]  = Wq[t]; }
    if (t < 12288) { int j = t >> 6, d = t & 63;  g_wihT[d*192 + j] = wih[t];
                                                   g_whhT[d*192 + j] = whh[t]; }
    if (t < 8192)  { int j = t >> 6, d = t & 63;  g_w1T[d*128 + j] = w1[t]; }
    if (t < 8192)  { int o = t >> 7, j = t & 127; g_w2T[j*64 + o]  = w2[t]; }
}

// ---------------- fused input LN + K^T/V projection (GEMM identical; bf16 stores) ----------------
__global__ void __launch_bounds__(256) ln_kv(const float* __restrict__ inp,
        const float* __restrict__ Wk, const float* __restrict__ Wv,
        const float* __restrict__ lng, const float* __restrict__ lnb) {
    __shared__ __align__(16) float xs[32 * 66];
    __shared__ __align__(16) float ws[128 * 64];
    int t = threadIdx.x;
    int r0 = blockIdx.x * 32;
    const float* ip = inp + (size_t)r0 * 64;
    #pragma unroll
    for (int i = 0; i < 8; i++) { int id = t + 256*i; xs[(id>>6)*66 + (id&63)] = ip[id]; }
    #pragma unroll
    for (int i = 0; i < 16; i++) { int id = t + 256*i; ws[id] = Wk[id]; ws[4096+id] = Wv[id]; }
    __syncthreads();
    {   // LayerNorm: 8 threads/row
        int row = t >> 3, sub = t & 7;
        float s = 0.f, ss = 0.f;
        #pragma unroll
        for (int i = 0; i < 8; i++) { float x = xs[row*66 + sub*8 + i]; s += x; ss += x*x; }
        s += __shfl_xor_sync(~0u, s, 1); ss += __shfl_xor_sync(~0u, ss, 1);
        s += __shfl_xor_sync(~0u, s, 2); ss += __shfl_xor_sync(~0u, ss, 2);
        s += __shfl_xor_sync(~0u, s, 4); ss += __shfl_xor_sync(~0u, ss, 4);
        float mu = s * 0.015625f;
        float rstd = rsqrtf(ss * 0.015625f - mu*mu + 1e-5f);
        #pragma unroll
        for (int i = 0; i < 8; i++) {
            int f = sub*8 + i;
            xs[row*66 + f] = (xs[row*66 + f] - mu) * rstd * __ldg(lng+f) + __ldg(lnb+f);
        }
    }
    __syncthreads();
    int tx = t & 15, ty = t >> 4;
    ull acc[8][2];
    #pragma unroll
    for (int j = 0; j < 8; j++) { acc[j][0] = 0ull; acc[j][1] = 0ull; }
    const ull* ws2 = (const ull*)ws;
    #pragma unroll 8
    for (int f2 = 0; f2 < 32; f2++) {
        ull a0 = *(const ull*)&xs[tx*66 + 2*f2];
        ull a1 = *(const ull*)&xs[(tx+16)*66 + 2*f2];
        #pragma unroll
        for (int j = 0; j < 8; j++) {
            ull bb = ws2[(ty*8 + j)*32 + f2];
            FMA2(acc[j][0], bb, a0);
            FMA2(acc[j][1], bb, a1);
        }
    }
    float cs[8][2];
    #pragma unroll
    for (int j = 0; j < 8; j++)
        #pragma unroll
        for (int i = 0; i < 2; i++) { float2 f = *reinterpret_cast<float2*>(&acc[j][i]); cs[j][i] = f.x + f.y; }

    int b = r0 >> 12, nn0 = r0 & 4095;
    float* os = ws;
    __syncthreads();
    if (ty < 8) {   // K wave -> transposed bf16 store
        #pragma unroll
        for (int j = 0; j < 8; j++) {
            int od = ty*8 + j;
            os[tx*66 + od] = cs[j][0];
            os[(tx+16)*66 + od] = cs[j][1];
        }
    }
    __syncthreads();
    #pragma unroll
    for (int i = 0; i < 4; i++) {
        int id = t + 256*i;                 // 0..1023
        int d = id >> 4, rp = id & 15;      // d, row-pair
        __nv_bfloat162 val = __floats2bfloat162_rn(os[(2*rp)*66 + d], os[(2*rp+1)*66 + d]);
        ((__nv_bfloat162*)g_kT)[((size_t)b*64 + d)*2048 + (nn0>>1) + rp] = val;
    }
    __syncthreads();
    if (ty >= 8) {  // V wave -> natural bf16 store
        #pragma unroll
        for (int j = 0; j < 8; j++) {
            int od = ty*8 + j - 64;
            os[tx*66 + od] = cs[j][0];
            os[(tx+16)*66 + od] = cs[j][1];
        }
    }
    __syncthreads();
    #pragma unroll
    for (int i = 0; i < 4; i++) {
        int id = t + 256*i;                 // 0..1023
        int row = id >> 5, dp = id & 31;    // row, d-pair
        __nv_bfloat162 val = __floats2bfloat162_rn(os[row*66 + 2*dp], os[row*66 + 2*dp + 1]);
        ((__nv_bfloat162*)g_v)[((size_t)(r0 + row))*32 + dp] = val;
    }
}

// ---------------- slots LN + Q projection -> duplicated-transposed layout ----------------
__global__ void __launch_bounds__(256) q_kernel(const float* __restrict__ lng,
                                                const float* __restrict__ lnb) {
    __shared__ float sn_s[512];
    int b = blockIdx.x, t = threadIdx.x;
    int w = t >> 5, lane = t & 31;
    float s0 = g_slots[b*512 + w*64 + lane];
    float s1 = g_slots[b*512 + w*64 + 32 + lane];
    float s = s0 + s1, ss = s0*s0 + s1*s1;
    #pragma unroll
    for (int o = 16; o > 0; o >>= 1) { s += __shfl_xor_sync(~0u, s, o); ss += __shfl_xor_sync(~0u, ss, o); }
    float mu = s * 0.015625f;
    float rstd = rsqrtf(ss * 0.015625f - mu*mu + 1e-5f);
    sn_s[w*64 + lane]      = (s0 - mu)*rstd*__ldg(lng+lane)    + __ldg(lnb+lane);
    sn_s[w*64 + 32 + lane] = (s1 - mu)*rstd*__ldg(lng+32+lane) + __ldg(lnb+32+lane);
    __syncthreads();
    int e = t & 63, k2 = t >> 6;
    #pragma unroll
    for (int kk = k2; kk < 8; kk += 4) {
        float a = 0.f;
        #pragma unroll 16
        for (int d = 0; d < 64; d++) a += sn_s[kk*64 + d] * __ldg(&g_WqT[d*64 + e]);
        g_q[b*1024 + e*16 + kk*2]     = a;   // duplicated pair (a,a)
        g_q[b*1024 + e*16 + kk*2 + 1] = a;
    }
}

// ---------------- attention: bf16 k/v, FMA2 everywhere ----------------
__global__ void __launch_bounds__(256) attn_kernel() {
    __shared__ __align__(16) float qst[1024];     // [e][16]: duplicated q pairs
    __shared__ __align__(16) float attn2[8192];   // [j][n][2] duplicated attn; later red[8][512]
    __shared__ float sred[64];
    int t = threadIdx.x, b = blockIdx.y, n0 = blockIdx.x * 512;

    ((float4*)qst)[t] = ((const float4*)(g_q + b*1024))[t];
    __syncthreads();

    // logits + softmax: thread handles token pair (2*t, 2*t+1)
    float sacc[8];
    {
        const __nv_bfloat162* kp = (const __nv_bfloat162*)g_kT + (size_t)b*131072 + (n0>>1) + t;
        ull l2[8];
        #pragma unroll
        for (int j = 0; j < 8; j++) l2[j] = 0ull;
        #pragma unroll 8
        for (int d = 0; d < 64; d++) {
            float2 kf = __bfloat1622float2(kp[d*2048]);
            ull kv; PACK2(kv, kf.x, kf.y);
            const ulonglong2* qp = (const ulonglong2*)&qst[d*16];
            ulonglong2 q01 = qp[0], q23 = qp[1];
            FMA2(l2[0], q01.x, kv); FMA2(l2[1], q01.y, kv);
            FMA2(l2[2], q23.x, kv); FMA2(l2[3], q23.y, kv);
            ulonglong2 q45 = qp[2], q67 = qp[3];
            FMA2(l2[4], q45.x, kv); FMA2(l2[5], q45.y, kv);
            FMA2(l2[6], q67.x, kv); FMA2(l2[7], q67.y, kv);
        }
        float l0[8], l1[8];
        #pragma unroll
        for (int j = 0; j < 8; j++) {
            float2 f = *reinterpret_cast<float2*>(&l2[j]);
            l0[j] = f.x; l1[j] = f.y;
        }
        float m0 = l0[0], m1 = l1[0];
        #pragma unroll
        for (int j = 1; j < 8; j++) { m0 = fmaxf(m0, l0[j]); m1 = fmaxf(m1, l1[j]); }
        float s0 = 0.f, s1 = 0.f, e0[8], e1[8];
        #pragma unroll
        for (int j = 0; j < 8; j++) {
            e0[j] = __expf((l0[j] - m0) * 0.125f); s0 += e0[j];
            e1[j] = __expf((l1[j] - m1) * 0.125f); s1 += e1[j];
        }
        float i0 = 1.0f / s0, i1 = 1.0f / s1;
        #pragma unroll
        for (int j = 0; j < 8; j++) {
            float a0 = e0[j]*i0 + 1e-8f;
            float a1 = e1[j]*i1 + 1e-8f;
            sacc[j] = a0 + a1;
            // [j][n] duplicated: consecutive 16B per lane -> dense STS.128
            *(float4*)&attn2[(j*512 + 2*t)*2] = make_float4(a0, a0, a1, a1);
        }
    }
    // deterministic S reduce
    #pragma unroll
    for (int j = 0; j < 8; j++) {
        float v = sacc[j];
        #pragma unroll
        for (int o = 16; o > 0; o >>= 1) v += __shfl_xor_sync(~0u, v, o);
        if ((t & 31) == 0) sred[(t>>5)*8 + j] = v;
    }
    __syncthreads();
    if (t < 8) {
        float v = 0.f;
        #pragma unroll
        for (int w = 0; w < 8; w++) v += sred[w*8 + t];
        g_Sp[blockIdx.x*512 + b*8 + t] = v;
    }

    // update: warp = 64-token group, lane = d-pair; bf16 v, FMA2
    int d2 = t & 31, grp = t >> 5;
    ull acc2[8];
    #pragma unroll
    for (int j = 0; j < 8; j++) acc2[j] = 0ull;
    const __nv_bfloat162* vp = (const __nv_bfloat162*)g_v + ((size_t)b*4096 + n0)*32 + d2;
    int nbeg = grp * 64;
    #pragma unroll 4
    for (int n = nbeg; n < nbeg + 64; n++) {
        float2 vf = __bfloat1622float2(vp[(size_t)n*32]);
        ull vv; PACK2(vv, vf.x, vf.y);
        #pragma unroll
        for (int j = 0; j < 8; j++) {
            ull aj = *(const ull*)&attn2[(j*512 + n)*2];   // broadcast LDS.64
            FMA2(acc2[j], aj, vv);
        }
    }
    __syncthreads();                 // all attn2 reads done
    float* red = attn2;              // [grp][j*64 + d]
    #pragma unroll
    for (int j = 0; j < 8; j++) {
        float2 r = *reinterpret_cast<float2*>(&acc2[j]);
        *(float2*)&red[grp*512 + j*64 + d2*2] = r;
    }
    __syncthreads();
    #pragma unroll
    for (int rep = 0; rep < 2; rep++) {
        int idx = rep*256 + t;
        float v = 0.f;
        #pragma unroll
        for (int g = 0; g < 8; g++) v += red[g*512 + idx];
        g_Up[((size_t)blockIdx.x*64 + b)*512 + idx] = v;
    }
}

// ---------------- batched GRU + LN + MLP + residual: 4 rows/block ----------------
__global__ void __launch_bounds__(384) gru_mlp(const float* __restrict__ bih, const float* __restrict__ bhh,
        const float* __restrict__ b1, const float* __restrict__ b2,
        const float* __restrict__ lng, const float* __restrict__ lnb,
        float* __restrict__ out, int last) {
    __shared__ float u_s[256], h_s[256];
    __shared__ float gi_s[768], gh_s[768];
    __shared__ float hn_s[256], ln_s[256], h1_s[512];
    int t = threadIdx.x;
    int grow0 = blockIdx.x * 4;

    if (t < 256) {
        int r = t >> 6, d = t & 63;
        int grow = grow0 + r;
        float S = 0.f, U = 0.f;
        #pragma unroll
        for (int c = 0; c < 8; c++) {
            S += g_Sp[c*512 + grow];
            U += g_Up[c*32768 + grow*64 + d];
        }
        u_s[t] = U / S;
        h_s[t] = g_slots[grow*64 + d];
    }
    __syncthreads();
    {
        int j = (t < 192) ? t : (t - 192);
        const float* W  = (t < 192) ? g_wihT : g_whhT;
        const float* xb = (t < 192) ? u_s : h_s;
        float acc0 = 0.f, acc1 = 0.f, acc2 = 0.f, acc3 = 0.f;
        #pragma unroll 8
        for (int d = 0; d < 64; d++) {
            float w = __ldg(&W[d*192 + j]);
            acc0 += xb[d]       * w;
            acc1 += xb[64 + d]  * w;
            acc2 += xb[128 + d] * w;
            acc3 += xb[192 + d] * w;
        }
        float bias = (t < 192) ? __ldg(bih + j) : __ldg(bhh + j);
        float* G = (t < 192) ? gi_s : gh_s;
        G[j]       = acc0 + bias;
        G[192 + j] = acc1 + bias;
        G[384 + j] = acc2 + bias;
        G[576 + j] = acc3 + bias;
    }
    __syncthreads();
    if (t < 256) {
        int r = t >> 6, d = t & 63;
        float rr = sigf(gi_s[r*192 + d]       + gh_s[r*192 + d]);
        float z  = sigf(gi_s[r*192 + 64 + d]  + gh_s[r*192 + 64 + d]);
        float n  = tanhf(gi_s[r*192 + 128 + d] + rr * gh_s[r*192 + 128 + d]);
        hn_s[t] = (1.f - z)*n + z*h_s[t];
    }
    __syncthreads();
    if (t < 128) {
        int r = t >> 5, lane = t & 31;
        float x0 = hn_s[r*64 + lane], x1 = hn_s[r*64 + 32 + lane];
        float s = x0 + x1, ss = x0*x0 + x1*x1;
        #pragma unroll
        for (int o = 16; o > 0; o >>= 1) { s += __shfl_xor_sync(~0u, s, o); ss += __shfl_xor_sync(~0u, ss, o); }
        float mu = s * 0.015625f;
        float rstd = rsqrtf(ss * 0.015625f - mu*mu + 1e-5f);
        ln_s[r*64 + lane]      = (x0 - mu)*rstd*__ldg(lng+lane)    + __ldg(lnb+lane);
        ln_s[r*64 + 32 + lane] = (x1 - mu)*rstd*__ldg(lng+32+lane) + __ldg(lnb+32+lane);
    }
    __syncthreads();
    if (t < 128) {
        int j = t;
        float a0 = 0.f, a1 = 0.f, a2 = 0.f, a3 = 0.f;
        #pragma unroll 8
        for (int d = 0; d < 64; d++) {
            float w = __ldg(&g_w1T[d*128 + j]);
            a0 += ln_s[d]       * w;
            a1 += ln_s[64 + d]  * w;
            a2 += ln_s[128 + d] * w;
            a3 += ln_s[192 + d] * w;
        }
        float bias = __ldg(b1 + j);
        h1_s[j]       = fmaxf(a0 + bias, 0.f);
        h1_s[128 + j] = fmaxf(a1 + bias, 0.f);
        h1_s[256 + j] = fmaxf(a2 + bias, 0.f);
        h1_s[384 + j] = fmaxf(a3 + bias, 0.f);
    }
    __syncthreads();
    if (t < 256) {
        int r = t >> 6, o = t & 63;
        float a = __ldg(b2 + o);
        #pragma unroll 8
        for (int j = 0; j < 128; j++) a += h1_s[r*128 + j] * __ldg(&g_w2T[j*64 + o]);
        float res = hn_s[r*64 + o] + a;
        int grow = grow0 + r;
        g_slots[grow*64 + o] = res;
        if (last) out[grow*64 + o] = res;
    }
}

extern "C" void kernel_launch(void* const* d_in, const int* in_sizes, int n_in,
                              void* d_out, int out_size) {
    const float* inputs = (const float*)d_in[0];
    const float* noise  = (const float*)d_in[1];
    const float* mu     = (const float*)d_in[2];
    const float* lsig   = (const float*)d_in[3];
    const float* Wq     = (const float*)d_in[4];
    const float* Wk     = (const float*)d_in[5];
    const float* Wv     = (const float*)d_in[6];
    const float* wih    = (const float*)d_in[7];
    const float* whh    = (const float*)d_in[8];
    const float* bih    = (const float*)d_in[9];
    const float* bhh    = (const float*)d_in[10];
    const float* w1     = (const float*)d_in[11];
    const float* b1     = (const float*)d_in[12];
    const float* w2     = (const float*)d_in[13];
    const float* b2     = (const float*)d_in[14];
    const float* ln_in_g   = (const float*)d_in[15];
    const float* ln_in_b   = (const float*)d_in[16];
    const float* ln_sl_g   = (const float*)d_in[17];
    const float* ln_sl_b   = (const float*)d_in[18];
    const float* ln_mlp_g  = (const float*)d_in[19];
    const float* ln_mlp_b  = (const float*)d_in[20];
    float* out = (float*)d_out;

    prep<<<128, 256>>>(Wq, wih, whh, w1, w2, noise, mu, lsig);
    ln_kv<<<8192, 256>>>(inputs, Wk, Wv, ln_in_g, ln_in_b);
    for (int it = 0; it < 3; it++) {
        q_kernel<<<64, 256>>>(ln_sl_g, ln_sl_b);
        attn_kernel<<<dim3(8, 64), 256>>>();
        gru_mlp<<<128, 384>>>(bih, bhh, b1, b2, ln_mlp_g, ln_mlp_b, out, it == 2);
    }
}

// round 7
// speedup vs baseline: 1.7961x; 1.0089x over previous
#include <cuda_runtime.h>
#include <cuda_bf16.h>

typedef unsigned long long ull;

// ---------------- device scratch ----------------
__device__ __nv_bfloat16 g_kT[16777216];  // [b][d][n] transposed K (bf16)
__device__ __nv_bfloat16 g_v [16777216];  // [b][n][d] (bf16)
__device__ float g_slots[32768];   // [b][k][d]
__device__ float g_q[65536];       // [b][e][j*2] duplicated-transposed q
__device__ float g_Up[262144];     // [chunk(8)][b][k][d]
__device__ float g_Sp[4096];       // [chunk(8)][b*8+k]
__device__ float g_WqT [4096];     // [d][e]
__device__ float g_wihT[12288];    // [d][j<192]
__device__ float g_whhT[12288];
__device__ float g_w1T [8192];     // [d][j<128]
__device__ float g_w2T [8192];     // [j<128][o<64]

#define FMA2(acc, a, b) asm("fma.rn.f32x2 %0, %1, %2, %0;" : "+l"(acc) : "l"(a), "l"(b))
#define PACK2(dst, x, y) asm("mov.b64 %0, {%1, %2};" : "=l"(dst) : "f"(x), "f"(y))

__device__ __forceinline__ float sigf(float x) { return 1.f / (1.f + __expf(-x)); }

// ---------------- prep: weight transposes + slots init ----------------
__global__ void prep(const float* __restrict__ Wq, const float* __restrict__ wih,
                     const float* __restrict__ whh, const float* __restrict__ w1,
                     const float* __restrict__ w2, const float* __restrict__ noise,
                     const float* __restrict__ mu, const float* __restrict__ lsig) {
    int t = blockIdx.x * 256 + threadIdx.x;   // grid 128 -> 32768 threads
    { int d = t & 63; g_slots[t] = __ldg(mu + d) + __expf(__ldg(lsig + d)) * noise[t]; }
    if (t < 4096)  { int e = t >> 6, d = t & 63;  g_WqT[d*64 + e]  = Wq[t]; }
    if (t < 12288) { int j = t >> 6, d = t & 63;  g_wihT[d*192 + j] = wih[t];
                                                   g_whhT[d*192 + j] = whh[t]; }
    if (t < 8192)  { int j = t >> 6, d = t & 63;  g_w1T[d*128 + j] = w1[t]; }
    if (t < 8192)  { int o = t >> 7, j = t & 127; g_w2T[j*64 + o]  = w2[t]; }
}

// ---------------- fused input LN + K^T/V projection (LDS.128 weights) ----------------
__global__ void __launch_bounds__(256) ln_kv(const float* __restrict__ inp,
        const float* __restrict__ Wk, const float* __restrict__ Wv,
        const float* __restrict__ lng, const float* __restrict__ lnb) {
    __shared__ __align__(16) float xs[32 * 66];
    __shared__ __align__(16) float ws[128 * 64];
    int t = threadIdx.x;
    int r0 = blockIdx.x * 32;
    const float* ip = inp + (size_t)r0 * 64;
    #pragma unroll
    for (int i = 0; i < 8; i++) { int id = t + 256*i; xs[(id>>6)*66 + (id&63)] = ip[id]; }
    #pragma unroll
    for (int i = 0; i < 16; i++) { int id = t + 256*i; ws[id] = Wk[id]; ws[4096+id] = Wv[id]; }
    __syncthreads();
    {   // LayerNorm: 8 threads/row
        int row = t >> 3, sub = t & 7;
        float s = 0.f, ss = 0.f;
        #pragma unroll
        for (int i = 0; i < 8; i++) { float x = xs[row*66 + sub*8 + i]; s += x; ss += x*x; }
        s += __shfl_xor_sync(~0u, s, 1); ss += __shfl_xor_sync(~0u, ss, 1);
        s += __shfl_xor_sync(~0u, s, 2); ss += __shfl_xor_sync(~0u, ss, 2);
        s += __shfl_xor_sync(~0u, s, 4); ss += __shfl_xor_sync(~0u, ss, 4);
        float mu = s * 0.015625f;
        float rstd = rsqrtf(ss * 0.015625f - mu*mu + 1e-5f);
        #pragma unroll
        for (int i = 0; i < 8; i++) {
            int f = sub*8 + i;
            xs[row*66 + f] = (xs[row*66 + f] - mu) * rstd * __ldg(lng+f) + __ldg(lnb+f);
        }
    }
    __syncthreads();
    int tx = t & 15, ty = t >> 4;
    ull acc[8][2];
    #pragma unroll
    for (int j = 0; j < 8; j++) { acc[j][0] = 0ull; acc[j][1] = 0ull; }
    #pragma unroll 4
    for (int f4 = 0; f4 < 16; f4++) {            // 4 f-dims per step
        ull a0l = *(const ull*)&xs[tx*66 + 4*f4];
        ull a0h = *(const ull*)&xs[tx*66 + 4*f4 + 2];
        ull a1l = *(const ull*)&xs[(tx+16)*66 + 4*f4];
        ull a1h = *(const ull*)&xs[(tx+16)*66 + 4*f4 + 2];
        #pragma unroll
        for (int j = 0; j < 8; j++) {
            ulonglong2 bq = *(const ulonglong2*)&ws[(ty*8 + j)*64 + 4*f4];   // one LDS.128
            FMA2(acc[j][0], bq.x, a0l); FMA2(acc[j][0], bq.y, a0h);
            FMA2(acc[j][1], bq.x, a1l); FMA2(acc[j][1], bq.y, a1h);
        }
    }
    float cs[8][2];
    #pragma unroll
    for (int j = 0; j < 8; j++)
        #pragma unroll
        for (int i = 0; i < 2; i++) { float2 f = *reinterpret_cast<float2*>(&acc[j][i]); cs[j][i] = f.x + f.y; }

    int b = r0 >> 12, nn0 = r0 & 4095;
    float* os = ws;
    __syncthreads();
    if (ty < 8) {   // K wave -> transposed bf16 store
        #pragma unroll
        for (int j = 0; j < 8; j++) {
            int od = ty*8 + j;
            os[tx*66 + od] = cs[j][0];
            os[(tx+16)*66 + od] = cs[j][1];
        }
    }
    __syncthreads();
    #pragma unroll
    for (int i = 0; i < 4; i++) {
        int id = t + 256*i;                 // 0..1023
        int d = id >> 4, rp = id & 15;      // d, row-pair
        __nv_bfloat162 val = __floats2bfloat162_rn(os[(2*rp)*66 + d], os[(2*rp+1)*66 + d]);
        ((__nv_bfloat162*)g_kT)[((size_t)b*64 + d)*2048 + (nn0>>1) + rp] = val;
    }
    __syncthreads();
    if (ty >= 8) {  // V wave -> natural bf16 store
        #pragma unroll
        for (int j = 0; j < 8; j++) {
            int od = ty*8 + j - 64;
            os[tx*66 + od] = cs[j][0];
            os[(tx+16)*66 + od] = cs[j][1];
        }
    }
    __syncthreads();
    #pragma unroll
    for (int i = 0; i < 4; i++) {
        int id = t + 256*i;                 // 0..1023
        int row = id >> 5, dp = id & 31;    // row, d-pair
        __nv_bfloat162 val = __floats2bfloat162_rn(os[row*66 + 2*dp], os[row*66 + 2*dp + 1]);
        ((__nv_bfloat162*)g_v)[((size_t)(r0 + row))*32 + dp] = val;
    }
}

// ---------------- slots LN + Q projection -> duplicated-transposed layout ----------------
__global__ void __launch_bounds__(256) q_kernel(const float* __restrict__ lng,
                                                const float* __restrict__ lnb) {
    __shared__ float sn_s[512];
    int b = blockIdx.x, t = threadIdx.x;
    int w = t >> 5, lane = t & 31;
    float s0 = g_slots[b*512 + w*64 + lane];
    float s1 = g_slots[b*512 + w*64 + 32 + lane];
    float s = s0 + s1, ss = s0*s0 + s1*s1;
    #pragma unroll
    for (int o = 16; o > 0; o >>= 1) { s += __shfl_xor_sync(~0u, s, o); ss += __shfl_xor_sync(~0u, ss, o); }
    float mu = s * 0.015625f;
    float rstd = rsqrtf(ss * 0.015625f - mu*mu + 1e-5f);
    sn_s[w*64 + lane]      = (s0 - mu)*rstd*__ldg(lng+lane)    + __ldg(lnb+lane);
    sn_s[w*64 + 32 + lane] = (s1 - mu)*rstd*__ldg(lng+32+lane) + __ldg(lnb+32+lane);
    __syncthreads();
    int e = t & 63, k2 = t >> 6;
    #pragma unroll
    for (int kk = k2; kk < 8; kk += 4) {
        float a = 0.f;
        #pragma unroll 16
        for (int d = 0; d < 64; d++) a += sn_s[kk*64 + d] * __ldg(&g_WqT[d*64 + e]);
        g_q[b*1024 + e*16 + kk*2]     = a;   // duplicated pair (a,a)
        g_q[b*1024 + e*16 + kk*2 + 1] = a;
    }
}

// ---------------- attention: bf16 k/v, FMA2, LDS.128 update reads ----------------
__global__ void __launch_bounds__(256) attn_kernel() {
    __shared__ __align__(16) float qst[1024];     // [e][16]: duplicated q pairs
    __shared__ __align__(16) float attn2[8192];   // [j][n][2] duplicated attn; later red[8][512]
    __shared__ float sred[64];
    int t = threadIdx.x, b = blockIdx.y, n0 = blockIdx.x * 512;

    ((float4*)qst)[t] = ((const float4*)(g_q + b*1024))[t];
    __syncthreads();

    // logits + softmax: thread handles token pair (2*t, 2*t+1)
    float sacc[8];
    {
        const __nv_bfloat162* kp = (const __nv_bfloat162*)g_kT + (size_t)b*131072 + (n0>>1) + t;
        ull l2[8];
        #pragma unroll
        for (int j = 0; j < 8; j++) l2[j] = 0ull;
        #pragma unroll 8
        for (int d = 0; d < 64; d++) {
            float2 kf = __bfloat1622float2(kp[d*2048]);
            ull kv; PACK2(kv, kf.x, kf.y);
            const ulonglong2* qp = (const ulonglong2*)&qst[d*16];
            ulonglong2 q01 = qp[0], q23 = qp[1];
            FMA2(l2[0], q01.x, kv); FMA2(l2[1], q01.y, kv);
            FMA2(l2[2], q23.x, kv); FMA2(l2[3], q23.y, kv);
            ulonglong2 q45 = qp[2], q67 = qp[3];
            FMA2(l2[4], q45.x, kv); FMA2(l2[5], q45.y, kv);
            FMA2(l2[6], q67.x, kv); FMA2(l2[7], q67.y, kv);
        }
        float l0[8], l1[8];
        #pragma unroll
        for (int j = 0; j < 8; j++) {
            float2 f = *reinterpret_cast<float2*>(&l2[j]);
            l0[j] = f.x; l1[j] = f.y;
        }
        float m0 = l0[0], m1 = l1[0];
        #pragma unroll
        for (int j = 1; j < 8; j++) { m0 = fmaxf(m0, l0[j]); m1 = fmaxf(m1, l1[j]); }
        float s0 = 0.f, s1 = 0.f, e0[8], e1[8];
        #pragma unroll
        for (int j = 0; j < 8; j++) {
            e0[j] = __expf((l0[j] - m0) * 0.125f); s0 += e0[j];
            e1[j] = __expf((l1[j] - m1) * 0.125f); s1 += e1[j];
        }
        float i0 = 1.0f / s0, i1 = 1.0f / s1;
        #pragma unroll
        for (int j = 0; j < 8; j++) {
            float a0 = e0[j]*i0 + 1e-8f;
            float a1 = e1[j]*i1 + 1e-8f;
            sacc[j] = a0 + a1;
            // [j][n] duplicated: consecutive 16B per lane -> dense STS.128
            *(float4*)&attn2[(j*512 + 2*t)*2] = make_float4(a0, a0, a1, a1);
        }
    }
    // deterministic S reduce
    #pragma unroll
    for (int j = 0; j < 8; j++) {
        float v = sacc[j];
        #pragma unroll
        for (int o = 16; o > 0; o >>= 1) v += __shfl_xor_sync(~0u, v, o);
        if ((t & 31) == 0) sred[(t>>5)*8 + j] = v;
    }
    __syncthreads();
    if (t < 8) {
        float v = 0.f;
        #pragma unroll
        for (int w = 0; w < 8; w++) v += sred[w*8 + t];
        g_Sp[blockIdx.x*512 + b*8 + t] = v;
    }

    // update: warp = 64-token group, lane = d-pair; 2 tokens/iter, LDS.128 attn reads
    int d2 = t & 31, grp = t >> 5;
    ull acc2[8];
    #pragma unroll
    for (int j = 0; j < 8; j++) acc2[j] = 0ull;
    const __nv_bfloat162* vp = (const __nv_bfloat162*)g_v + ((size_t)b*4096 + n0)*32 + d2;
    int nbeg = grp * 64;
    #pragma unroll 2
    for (int n = nbeg; n < nbeg + 64; n += 2) {
        float2 vf0 = __bfloat1622float2(vp[(size_t)n*32]);
        float2 vf1 = __bfloat1622float2(vp[(size_t)(n+1)*32]);
        ull v0; PACK2(v0, vf0.x, vf0.y);
        ull v1; PACK2(v1, vf1.x, vf1.y);
        #pragma unroll
        for (int j = 0; j < 8; j++) {
            ulonglong2 ap = *(const ulonglong2*)&attn2[(j*512 + n)*2];  // broadcast LDS.128
            FMA2(acc2[j], ap.x, v0);
            FMA2(acc2[j], ap.y, v1);
        }
    }
    __syncthreads();                 // all attn2 reads done
    float* red = attn2;              // [grp][j*64 + d]
    #pragma unroll
    for (int j = 0; j < 8; j++) {
        float2 r = *reinterpret_cast<float2*>(&acc2[j]);
        *(float2*)&red[grp*512 + j*64 + d2*2] = r;
    }
    __syncthreads();
    #pragma unroll
    for (int rep = 0; rep < 2; rep++) {
        int idx = rep*256 + t;
        float v = 0.f;
        #pragma unroll
        for (int g = 0; g < 8; g++) v += red[g*512 + idx];
        g_Up[((size_t)blockIdx.x*64 + b)*512 + idx] = v;
    }
}

// ---------------- batched GRU + LN + MLP + residual: 4 rows/block ----------------
__global__ void __launch_bounds__(384) gru_mlp(const float* __restrict__ bih, const float* __restrict__ bhh,
        const float* __restrict__ b1, const float* __restrict__ b2,
        const float* __restrict__ lng, const float* __restrict__ lnb,
        float* __restrict__ out, int last) {
    __shared__ float u_s[256], h_s[256];
    __shared__ float gi_s[768], gh_s[768];
    __shared__ float hn_s[256], ln_s[256], h1_s[512];
    int t = threadIdx.x;
    int grow0 = blockIdx.x * 4;

    if (t < 256) {
        int r = t >> 6, d = t & 63;
        int grow = grow0 + r;
        float S = 0.f, U = 0.f;
        #pragma unroll
        for (int c = 0; c < 8; c++) {
            S += g_Sp[c*512 + grow];
            U += g_Up[c*32768 + grow*64 + d];
        }
        u_s[t] = U / S;
        h_s[t] = g_slots[grow*64 + d];
    }
    __syncthreads();
    {
        int j = (t < 192) ? t : (t - 192);
        const float* W  = (t < 192) ? g_wihT : g_whhT;
        const float* xb = (t < 192) ? u_s : h_s;
        float acc0 = 0.f, acc1 = 0.f, acc2 = 0.f, acc3 = 0.f;
        #pragma unroll 8
        for (int d = 0; d < 64; d++) {
            float w = __ldg(&W[d*192 + j]);
            acc0 += xb[d]       * w;
            acc1 += xb[64 + d]  * w;
            acc2 += xb[128 + d] * w;
            acc3 += xb[192 + d] * w;
        }
        float bias = (t < 192) ? __ldg(bih + j) : __ldg(bhh + j);
        float* G = (t < 192) ? gi_s : gh_s;
        G[j]       = acc0 + bias;
        G[192 + j] = acc1 + bias;
        G[384 + j] = acc2 + bias;
        G[576 + j] = acc3 + bias;
    }
    __syncthreads();
    if (t < 256) {
        int r = t >> 6, d = t & 63;
        float rr = sigf(gi_s[r*192 + d]       + gh_s[r*192 + d]);
        float z  = sigf(gi_s[r*192 + 64 + d]  + gh_s[r*192 + 64 + d]);
        float n  = tanhf(gi_s[r*192 + 128 + d] + rr * gh_s[r*192 + 128 + d]);
        hn_s[t] = (1.f - z)*n + z*h_s[t];
    }
    __syncthreads();
    if (t < 128) {
        int r = t >> 5, lane = t & 31;
        float x0 = hn_s[r*64 + lane], x1 = hn_s[r*64 + 32 + lane];
        float s = x0 + x1, ss = x0*x0 + x1*x1;
        #pragma unroll
        for (int o = 16; o > 0; o >>= 1) { s += __shfl_xor_sync(~0u, s, o); ss += __shfl_xor_sync(~0u, ss, o); }
        float mu = s * 0.015625f;
        float rstd = rsqrtf(ss * 0.015625f - mu*mu + 1e-5f);
        ln_s[r*64 + lane]      = (x0 - mu)*rstd*__ldg(lng+lane)    + __ldg(lnb+lane);
        ln_s[r*64 + 32 + lane] = (x1 - mu)*rstd*__ldg(lng+32+lane) + __ldg(lnb+32+lane);
    }
    __syncthreads();
    if (t < 128) {
        int j = t;
        float a0 = 0.f, a1 = 0.f, a2 = 0.f, a3 = 0.f;
        #pragma unroll 8
        for (int d = 0; d < 64; d++) {
            float w = __ldg(&g_w1T[d*128 + j]);
            a0 += ln_s[d]       * w;
            a1 += ln_s[64 + d]  * w;
            a2 += ln_s[128 + d] * w;
            a3 += ln_s[192 + d] * w;
        }
        float bias = __ldg(b1 + j);
        h1_s[j]       = fmaxf(a0 + bias, 0.f);
        h1_s[128 + j] = fmaxf(a1 + bias, 0.f);
        h1_s[256 + j] = fmaxf(a2 + bias, 0.f);
        h1_s[384 + j] = fmaxf(a3 + bias, 0.f);
    }
    __syncthreads();
    if (t < 256) {
        int r = t >> 6, o = t & 63;
        float a = __ldg(b2 + o);
        #pragma unroll 8
        for (int j = 0; j < 128; j++) a += h1_s[r*128 + j] * __ldg(&g_w2T[j*64 + o]);
        float res = hn_s[r*64 + o] + a;
        int grow = grow0 + r;
        g_slots[grow*64 + o] = res;
        if (last) out[grow*64 + o] = res;
    }
}

extern "C" void kernel_launch(void* const* d_in, const int* in_sizes, int n_in,
                              void* d_out, int out_size) {
    const float* inputs = (const float*)d_in[0];
    const float* noise  = (const float*)d_in[1];
    const float* mu     = (const float*)d_in[2];
    const float* lsig   = (const float*)d_in[3];
    const float* Wq     = (const float*)d_in[4];
    const float* Wk     = (const float*)d_in[5];
    const float* Wv     = (const float*)d_in[6];
    const float* wih    = (const float*)d_in[7];
    const float* whh    = (const float*)d_in[8];
    const float* bih    = (const float*)d_in[9];
    const float* bhh    = (const float*)d_in[10];
    const float* w1     = (const float*)d_in[11];
    const float* b1     = (const float*)d_in[12];
    const float* w2     = (const float*)d_in[13];
    const float* b2     = (const float*)d_in[14];
    const float* ln_in_g   = (const float*)d_in[15];
    const float* ln_in_b   = (const float*)d_in[16];
    const float* ln_sl_g   = (const float*)d_in[17];
    const float* ln_sl_b   = (const float*)d_in[18];
    const float* ln_mlp_g  = (const float*)d_in[19];
    const float* ln_mlp_b  = (const float*)d_in[20];
    float* out = (float*)d_out;

    prep<<<128, 256>>>(Wq, wih, whh, w1, w2, noise, mu, lsig);
    ln_kv<<<8192, 256>>>(inputs, Wk, Wv, ln_in_g, ln_in_b);
    for (int it = 0; it < 3; it++) {
        q_kernel<<<64, 256>>>(ln_sl_g, ln_sl_b);
        attn_kernel<<<dim3(8, 64), 256>>>();
        gru_mlp<<<128, 384>>>(bih, bhh, b1, b2, ln_mlp_g, ln_mlp_b, out, it == 2);
    }
}

// round 8
// speedup vs baseline: 1.8217x; 1.0143x over previous
#include <cuda_runtime.h>
#include <cuda_bf16.h>

typedef unsigned long long ull;

// ---------------- device scratch ----------------
__device__ __nv_bfloat16 g_kT[16777216];  // [b][d][n] transposed K (bf16)
__device__ __nv_bfloat16 g_v [16777216];  // [b][n][d] (bf16)
__device__ float g_slots[32768];   // [b][k][d]
__device__ float g_q[65536];       // [b][e][j*2] duplicated-transposed q
__device__ float g_Up[262144];     // [chunk(8)][b][k][d]
__device__ float g_Sp[4096];       // [chunk(8)][b*8+k]
__device__ float g_WqT [4096];     // [d][e]
__device__ float g_wihT[12288];    // [d][j<192]
__device__ float g_whhT[12288];
__device__ float g_w1T [8192];     // [d][j<128]
__device__ float g_w2T [8192];     // [j<128][o<64]

#define FMA2(acc, a, b) asm("fma.rn.f32x2 %0, %1, %2, %0;" : "+l"(acc) : "l"(a), "l"(b))
#define PACK2(dst, x, y) asm("mov.b64 %0, {%1, %2};" : "=l"(dst) : "f"(x), "f"(y))

__device__ __forceinline__ float sigf(float x) { return 1.f / (1.f + __expf(-x)); }

// ---------------- prep: transposes + slots init + iter-1 q ----------------
__global__ void __launch_bounds__(256) prep(const float* __restrict__ Wq, const float* __restrict__ wih,
                     const float* __restrict__ whh, const float* __restrict__ w1,
                     const float* __restrict__ w2, const float* __restrict__ noise,
                     const float* __restrict__ mu, const float* __restrict__ lsig,
                     const float* __restrict__ lng, const float* __restrict__ lnb) {
    __shared__ float sWqT[65 * 64];   // padded transpose of Wq: [d][e] stride 65
    __shared__ float slot_s[256];     // this block's 4 rows
    int tid = threadIdx.x;
    int t = blockIdx.x * 256 + tid;   // global over 32768

    // weight transposes (global, for later kernels)
    if (t < 4096)  { int e = t >> 6, d = t & 63;  g_WqT[d*64 + e]  = Wq[t]; }
    if (t < 12288) { int j = t >> 6, d = t & 63;  g_wihT[d*192 + j] = wih[t];
                                                   g_whhT[d*192 + j] = whh[t]; }
    if (t < 8192)  { int j = t >> 6, d = t & 63;  g_w1T[d*128 + j] = w1[t]; }
    if (t < 8192)  { int o = t >> 7, j = t & 127; g_w2T[j*64 + o]  = w2[t]; }

    // slots init (this block covers rows 4B..4B+3)
    {
        int d = t & 63;
        float val = __ldg(mu + d) + __expf(__ldg(lsig + d)) * noise[t];
        g_slots[t] = val;
        slot_s[tid] = val;
    }
    // stage Wq transposed into smem for the local q projection
    #pragma unroll
    for (int i = tid; i < 4096; i += 256) { int e = i >> 6, d = i & 63; sWqT[d*65 + e] = Wq[i]; }
    __syncthreads();

    // slots LN: warps 0..3, warp w -> local row w
    if (tid < 128) {
        int w = tid >> 5, lane = tid & 31;
        float s0 = slot_s[w*64 + lane], s1 = slot_s[w*64 + 32 + lane];
        float s = s0 + s1, ss = s0*s0 + s1*s1;
        #pragma unroll
        for (int o = 16; o > 0; o >>= 1) { s += __shfl_xor_sync(~0u, s, o); ss += __shfl_xor_sync(~0u, ss, o); }
        float m = s * 0.015625f;
        float rstd = rsqrtf(ss * 0.015625f - m*m + 1e-5f);
        slot_s[w*64 + lane]      = (s0 - m)*rstd*__ldg(lng+lane)    + __ldg(lnb+lane);
        slot_s[w*64 + 32 + lane] = (s1 - m)*rstd*__ldg(lng+32+lane) + __ldg(lnb+32+lane);
    }
    __syncthreads();

    // q projection for the 4 rows: thread (r, e)
    {
        int r = tid >> 6, e = tid & 63;
        float a = 0.f;
        #pragma unroll 16
        for (int d = 0; d < 64; d++) a += slot_s[r*64 + d] * sWqT[d*65 + e];
        int grow = blockIdx.x*4 + r;
        int b = grow >> 3, k = grow & 7;
        g_q[b*1024 + e*16 + k*2]     = a;
        g_q[b*1024 + e*16 + k*2 + 1] = a;
    }
}

// ---------------- fused input LN + K^T/V projection (LDS.128 weights) ----------------
__global__ void __launch_bounds__(256) ln_kv(const float* __restrict__ inp,
        const float* __restrict__ Wk, const float* __restrict__ Wv,
        const float* __restrict__ lng, const float* __restrict__ lnb) {
    __shared__ __align__(16) float xs[32 * 66];
    __shared__ __align__(16) float ws[128 * 64];
    int t = threadIdx.x;
    int r0 = blockIdx.x * 32;
    const float* ip = inp + (size_t)r0 * 64;
    #pragma unroll
    for (int i = 0; i < 8; i++) { int id = t + 256*i; xs[(id>>6)*66 + (id&63)] = ip[id]; }
    #pragma unroll
    for (int i = 0; i < 16; i++) { int id = t + 256*i; ws[id] = Wk[id]; ws[4096+id] = Wv[id]; }
    __syncthreads();
    {   // LayerNorm: 8 threads/row
        int row = t >> 3, sub = t & 7;
        float s = 0.f, ss = 0.f;
        #pragma unroll
        for (int i = 0; i < 8; i++) { float x = xs[row*66 + sub*8 + i]; s += x; ss += x*x; }
        s += __shfl_xor_sync(~0u, s, 1); ss += __shfl_xor_sync(~0u, ss, 1);
        s += __shfl_xor_sync(~0u, s, 2); ss += __shfl_xor_sync(~0u, ss, 2);
        s += __shfl_xor_sync(~0u, s, 4); ss += __shfl_xor_sync(~0u, ss, 4);
        float mu = s * 0.015625f;
        float rstd = rsqrtf(ss * 0.015625f - mu*mu + 1e-5f);
        #pragma unroll
        for (int i = 0; i < 8; i++) {
            int f = sub*8 + i;
            xs[row*66 + f] = (xs[row*66 + f] - mu) * rstd * __ldg(lng+f) + __ldg(lnb+f);
        }
    }
    __syncthreads();
    int tx = t & 15, ty = t >> 4;
    ull acc[8][2];
    #pragma unroll
    for (int j = 0; j < 8; j++) { acc[j][0] = 0ull; acc[j][1] = 0ull; }
    #pragma unroll 4
    for (int f4 = 0; f4 < 16; f4++) {            // 4 f-dims per step
        ull a0l = *(const ull*)&xs[tx*66 + 4*f4];
        ull a0h = *(const ull*)&xs[tx*66 + 4*f4 + 2];
        ull a1l = *(const ull*)&xs[(tx+16)*66 + 4*f4];
        ull a1h = *(const ull*)&xs[(tx+16)*66 + 4*f4 + 2];
        #pragma unroll
        for (int j = 0; j < 8; j++) {
            ulonglong2 bq = *(const ulonglong2*)&ws[(ty*8 + j)*64 + 4*f4];   // one LDS.128
            FMA2(acc[j][0], bq.x, a0l); FMA2(acc[j][0], bq.y, a0h);
            FMA2(acc[j][1], bq.x, a1l); FMA2(acc[j][1], bq.y, a1h);
        }
    }
    float cs[8][2];
    #pragma unroll
    for (int j = 0; j < 8; j++)
        #pragma unroll
        for (int i = 0; i < 2; i++) { float2 f = *reinterpret_cast<float2*>(&acc[j][i]); cs[j][i] = f.x + f.y; }

    int b = r0 >> 12, nn0 = r0 & 4095;
    float* os = ws;
    __syncthreads();
    if (ty < 8) {   // K wave -> transposed bf16 store
        #pragma unroll
        for (int j = 0; j < 8; j++) {
            int od = ty*8 + j;
            os[tx*66 + od] = cs[j][0];
            os[(tx+16)*66 + od] = cs[j][1];
        }
    }
    __syncthreads();
    #pragma unroll
    for (int i = 0; i < 4; i++) {
        int id = t + 256*i;                 // 0..1023
        int d = id >> 4, rp = id & 15;      // d, row-pair
        __nv_bfloat162 val = __floats2bfloat162_rn(os[(2*rp)*66 + d], os[(2*rp+1)*66 + d]);
        ((__nv_bfloat162*)g_kT)[((size_t)b*64 + d)*2048 + (nn0>>1) + rp] = val;
    }
    __syncthreads();
    if (ty >= 8) {  // V wave -> natural bf16 store
        #pragma unroll
        for (int j = 0; j < 8; j++) {
            int od = ty*8 + j - 64;
            os[tx*66 + od] = cs[j][0];
            os[(tx+16)*66 + od] = cs[j][1];
        }
    }
    __syncthreads();
    #pragma unroll
    for (int i = 0; i < 4; i++) {
        int id = t + 256*i;                 // 0..1023
        int row = id >> 5, dp = id & 31;    // row, d-pair
        __nv_bfloat162 val = __floats2bfloat162_rn(os[row*66 + 2*dp], os[row*66 + 2*dp + 1]);
        ((__nv_bfloat162*)g_v)[((size_t)(r0 + row))*32 + dp] = val;
    }
}

// ---------------- attention: bf16 k/v, FMA2, LDS.128 update reads ----------------
__global__ void __launch_bounds__(256) attn_kernel() {
    __shared__ __align__(16) float qst[1024];     // [e][16]: duplicated q pairs
    __shared__ __align__(16) float attn2[8192];   // [j][n][2] duplicated attn; later red[8][512]
    __shared__ float sred[64];
    int t = threadIdx.x, b = blockIdx.y, n0 = blockIdx.x * 512;

    ((float4*)qst)[t] = ((const float4*)(g_q + b*1024))[t];
    __syncthreads();

    // logits + softmax: thread handles token pair (2*t, 2*t+1)
    float sacc[8];
    {
        const __nv_bfloat162* kp = (const __nv_bfloat162*)g_kT + (size_t)b*131072 + (n0>>1) + t;
        ull l2[8];
        #pragma unroll
        for (int j = 0; j < 8; j++) l2[j] = 0ull;
        #pragma unroll 8
        for (int d = 0; d < 64; d++) {
            float2 kf = __bfloat1622float2(kp[d*2048]);
            ull kv; PACK2(kv, kf.x, kf.y);
            const ulonglong2* qp = (const ulonglong2*)&qst[d*16];
            ulonglong2 q01 = qp[0], q23 = qp[1];
            FMA2(l2[0], q01.x, kv); FMA2(l2[1], q01.y, kv);
            FMA2(l2[2], q23.x, kv); FMA2(l2[3], q23.y, kv);
            ulonglong2 q45 = qp[2], q67 = qp[3];
            FMA2(l2[4], q45.x, kv); FMA2(l2[5], q45.y, kv);
            FMA2(l2[6], q67.x, kv); FMA2(l2[7], q67.y, kv);
        }
        float l0[8], l1[8];
        #pragma unroll
        for (int j = 0; j < 8; j++) {
            float2 f = *reinterpret_cast<float2*>(&l2[j]);
            l0[j] = f.x; l1[j] = f.y;
        }
        float m0 = l0[0], m1 = l1[0];
        #pragma unroll
        for (int j = 1; j < 8; j++) { m0 = fmaxf(m0, l0[j]); m1 = fmaxf(m1, l1[j]); }
        float s0 = 0.f, s1 = 0.f, e0[8], e1[8];
        #pragma unroll
        for (int j = 0; j < 8; j++) {
            e0[j] = __expf((l0[j] - m0) * 0.125f); s0 += e0[j];
            e1[j] = __expf((l1[j] - m1) * 0.125f); s1 += e1[j];
        }
        float i0 = 1.0f / s0, i1 = 1.0f / s1;
        #pragma unroll
        for (int j = 0; j < 8; j++) {
            float a0 = e0[j]*i0 + 1e-8f;
            float a1 = e1[j]*i1 + 1e-8f;
            sacc[j] = a0 + a1;
            *(float4*)&attn2[(j*512 + 2*t)*2] = make_float4(a0, a0, a1, a1);
        }
    }
    // deterministic S reduce
    #pragma unroll
    for (int j = 0; j < 8; j++) {
        float v = sacc[j];
        #pragma unroll
        for (int o = 16; o > 0; o >>= 1) v += __shfl_xor_sync(~0u, v, o);
        if ((t & 31) == 0) sred[(t>>5)*8 + j] = v;
    }
    __syncthreads();
    if (t < 8) {
        float v = 0.f;
        #pragma unroll
        for (int w = 0; w < 8; w++) v += sred[w*8 + t];
        g_Sp[blockIdx.x*512 + b*8 + t] = v;
    }

    // update: warp = 64-token group, lane = d-pair; 2 tokens/iter, LDS.128 attn reads
    int d2 = t & 31, grp = t >> 5;
    ull acc2[8];
    #pragma unroll
    for (int j = 0; j < 8; j++) acc2[j] = 0ull;
    const __nv_bfloat162* vp = (const __nv_bfloat162*)g_v + ((size_t)b*4096 + n0)*32 + d2;
    int nbeg = grp * 64;
    #pragma unroll 2
    for (int n = nbeg; n < nbeg + 64; n += 2) {
        float2 vf0 = __bfloat1622float2(vp[(size_t)n*32]);
        float2 vf1 = __bfloat1622float2(vp[(size_t)(n+1)*32]);
        ull v0; PACK2(v0, vf0.x, vf0.y);
        ull v1; PACK2(v1, vf1.x, vf1.y);
        #pragma unroll
        for (int j = 0; j < 8; j++) {
            ulonglong2 ap = *(const ulonglong2*)&attn2[(j*512 + n)*2];  // broadcast LDS.128
            FMA2(acc2[j], ap.x, v0);
            FMA2(acc2[j], ap.y, v1);
        }
    }
    __syncthreads();                 // all attn2 reads done
    float* red = attn2;              // [grp][j*64 + d]
    #pragma unroll
    for (int j = 0; j < 8; j++) {
        float2 r = *reinterpret_cast<float2*>(&acc2[j]);
        *(float2*)&red[grp*512 + j*64 + d2*2] = r;
    }
    __syncthreads();
    #pragma unroll
    for (int rep = 0; rep < 2; rep++) {
        int idx = rep*256 + t;
        float v = 0.f;
        #pragma unroll
        for (int g = 0; g < 8; g++) v += red[g*512 + idx];
        g_Up[((size_t)blockIdx.x*64 + b)*512 + idx] = v;
    }
}

// ---------------- batched GRU + LN + MLP + residual + next-iter q ----------------
__global__ void __launch_bounds__(384) gru_mlp(const float* __restrict__ bih, const float* __restrict__ bhh,
        const float* __restrict__ b1, const float* __restrict__ b2,
        const float* __restrict__ lng, const float* __restrict__ lnb,
        const float* __restrict__ lng2, const float* __restrict__ lnb2,
        float* __restrict__ out, int last) {
    __shared__ float u_s[256], h_s[256];
    __shared__ float gi_s[768], gh_s[768];
    __shared__ float hn_s[256], ln_s[256], h1_s[512];
    int t = threadIdx.x;
    int grow0 = blockIdx.x * 4;

    if (t < 256) {
        int r = t >> 6, d = t & 63;
        int grow = grow0 + r;
        float S = 0.f, U = 0.f;
        #pragma unroll
        for (int c = 0; c < 8; c++) {
            S += g_Sp[c*512 + grow];
            U += g_Up[c*32768 + grow*64 + d];
        }
        u_s[t] = U / S;
        h_s[t] = g_slots[grow*64 + d];
    }
    __syncthreads();
    {
        int j = (t < 192) ? t : (t - 192);
        const float* W  = (t < 192) ? g_wihT : g_whhT;
        const float* xb = (t < 192) ? u_s : h_s;
        float acc0 = 0.f, acc1 = 0.f, acc2 = 0.f, acc3 = 0.f;
        #pragma unroll 8
        for (int d = 0; d < 64; d++) {
            float w = __ldg(&W[d*192 + j]);
            acc0 += xb[d]       * w;
            acc1 += xb[64 + d]  * w;
            acc2 += xb[128 + d] * w;
            acc3 += xb[192 + d] * w;
        }
        float bias = (t < 192) ? __ldg(bih + j) : __ldg(bhh + j);
        float* G = (t < 192) ? gi_s : gh_s;
        G[j]       = acc0 + bias;
        G[192 + j] = acc1 + bias;
        G[384 + j] = acc2 + bias;
        G[576 + j] = acc3 + bias;
    }
    __syncthreads();
    if (t < 256) {
        int r = t >> 6, d = t & 63;
        float rr = sigf(gi_s[r*192 + d]       + gh_s[r*192 + d]);
        float z  = sigf(gi_s[r*192 + 64 + d]  + gh_s[r*192 + 64 + d]);
        float n  = tanhf(gi_s[r*192 + 128 + d] + rr * gh_s[r*192 + 128 + d]);
        hn_s[t] = (1.f - z)*n + z*h_s[t];
    }
    __syncthreads();
    if (t < 128) {
        int r = t >> 5, lane = t & 31;
        float x0 = hn_s[r*64 + lane], x1 = hn_s[r*64 + 32 + lane];
        float s = x0 + x1, ss = x0*x0 + x1*x1;
        #pragma unroll
        for (int o = 16; o > 0; o >>= 1) { s += __shfl_xor_sync(~0u, s, o); ss += __shfl_xor_sync(~0u, ss, o); }
        float mu = s * 0.015625f;
        float rstd = rsqrtf(ss * 0.015625f - mu*mu + 1e-5f);
        ln_s[r*64 + lane]      = (x0 - mu)*rstd*__ldg(lng+lane)    + __ldg(lnb+lane);
        ln_s[r*64 + 32 + lane] = (x1 - mu)*rstd*__ldg(lng+32+lane) + __ldg(lnb+32+lane);
    }
    __syncthreads();
    if (t < 128) {
        int j = t;
        float a0 = 0.f, a1 = 0.f, a2 = 0.f, a3 = 0.f;
        #pragma unroll 8
        for (int d = 0; d < 64; d++) {
            float w = __ldg(&g_w1T[d*128 + j]);
            a0 += ln_s[d]       * w;
            a1 += ln_s[64 + d]  * w;
            a2 += ln_s[128 + d] * w;
            a3 += ln_s[192 + d] * w;
        }
        float bias = __ldg(b1 + j);
        h1_s[j]       = fmaxf(a0 + bias, 0.f);
        h1_s[128 + j] = fmaxf(a1 + bias, 0.f);
        h1_s[256 + j] = fmaxf(a2 + bias, 0.f);
        h1_s[384 + j] = fmaxf(a3 + bias, 0.f);
    }
    __syncthreads();
    if (t < 256) {
        int r = t >> 6, o = t & 63;
        float a = __ldg(b2 + o);
        #pragma unroll 8
        for (int j = 0; j < 128; j++) a += h1_s[r*128 + j] * __ldg(&g_w2T[j*64 + o]);
        float res = hn_s[r*64 + o] + a;
        int grow = grow0 + r;
        g_slots[grow*64 + o] = res;
        if (last) out[grow*64 + o] = res;
        u_s[t] = res;                    // stage for q phase (u_s free)
    }
    if (last) return;
    __syncthreads();

    // ---- next-iter q: slots-LN + Wq projection ----
    if (t < 128) {
        int r = t >> 5, lane = t & 31;
        float x0 = u_s[r*64 + lane], x1 = u_s[r*64 + 32 + lane];
        float s = x0 + x1, ss = x0*x0 + x1*x1;
        #pragma unroll
        for (int o = 16; o > 0; o >>= 1) { s += __shfl_xor_sync(~0u, s, o); ss += __shfl_xor_sync(~0u, ss, o); }
        float mu = s * 0.015625f;
        float rstd = rsqrtf(ss * 0.015625f - mu*mu + 1e-5f);
        ln_s[r*64 + lane]      = (x0 - mu)*rstd*__ldg(lng2+lane)    + __ldg(lnb2+lane);
        ln_s[r*64 + 32 + lane] = (x1 - mu)*rstd*__ldg(lng2+32+lane) + __ldg(lnb2+32+lane);
    }
    __syncthreads();
    if (t < 256) {
        int r = t >> 6, e = t & 63;
        float a = 0.f;
        #pragma unroll 16
        for (int d = 0; d < 64; d++) a += ln_s[r*64 + d] * __ldg(&g_WqT[d*64 + e]);
        int grow = grow0 + r;
        int b = grow >> 3, k = grow & 7;
        g_q[b*1024 + e*16 + k*2]     = a;
        g_q[b*1024 + e*16 + k*2 + 1] = a;
    }
}

extern "C" void kernel_launch(void* const* d_in, const int* in_sizes, int n_in,
                              void* d_out, int out_size) {
    const float* inputs = (const float*)d_in[0];
    const float* noise  = (const float*)d_in[1];
    const float* mu     = (const float*)d_in[2];
    const float* lsig   = (const float*)d_in[3];
    const float* Wq     = (const float*)d_in[4];
    const float* Wk     = (const float*)d_in[5];
    const float* Wv     = (const float*)d_in[6];
    const float* wih    = (const float*)d_in[7];
    const float* whh    = (const float*)d_in[8];
    const float* bih    = (const float*)d_in[9];
    const float* bhh    = (const float*)d_in[10];
    const float* w1     = (const float*)d_in[11];
    const float* b1     = (const float*)d_in[12];
    const float* w2     = (const float*)d_in[13];
    const float* b2     = (const float*)d_in[14];
    const float* ln_in_g   = (const float*)d_in[15];
    const float* ln_in_b   = (const float*)d_in[16];
    const float* ln_sl_g   = (const float*)d_in[17];
    const float* ln_sl_b   = (const float*)d_in[18];
    const float* ln_mlp_g  = (const float*)d_in[19];
    const float* ln_mlp_b  = (const float*)d_in[20];
    float* out = (float*)d_out;

    prep<<<128, 256>>>(Wq, wih, whh, w1, w2, noise, mu, lsig, ln_sl_g, ln_sl_b);
    ln_kv<<<8192, 256>>>(inputs, Wk, Wv, ln_in_g, ln_in_b);
    for (int it = 0; it < 3; it++) {
        attn_kernel<<<dim3(8, 64), 256>>>();
        gru_mlp<<<128, 384>>>(bih, bhh, b1, b2, ln_mlp_g, ln_mlp_b,
                              ln_sl_g, ln_sl_b, out, it == 2);
    }
}

// round 9
// speedup vs baseline: 1.8664x; 1.0245x over previous
#include <cuda_runtime.h>
#include <cuda_bf16.h>

typedef unsigned long long ull;

// ---------------- device scratch ----------------
__device__ __nv_bfloat16 g_kT[16777216];  // [b][d][n] transposed K (bf16)
__device__ __nv_bfloat16 g_v [16777216];  // [b][n][d] (bf16)
__device__ float g_slots[32768];   // [b][k][d]
__device__ float g_q[65536];       // [b][e][j*2] duplicated-transposed q
__device__ float g_Up[262144];     // [chunk(8)][b][k][d]
__device__ float g_Sp[4096];       // [chunk(8)][b*8+k]

#define FMA2(acc, a, b) asm("fma.rn.f32x2 %0, %1, %2, %0;" : "+l"(acc) : "l"(a), "l"(b))
#define PACK2(dst, x, y) asm("mov.b64 %0, {%1, %2};" : "=l"(dst) : "f"(x), "f"(y))

__device__ __forceinline__ float sigf(float x) { return 1.f / (1.f + __expf(-x)); }
__device__ __forceinline__ float dot4(float4 a, float4 b) {
    return a.x*b.x + a.y*b.y + a.z*b.z + a.w*b.w;
}

// ---------------- prep: slots init + iter-1 q ----------------
__global__ void __launch_bounds__(256) prep(const float* __restrict__ Wq,
                     const float* __restrict__ noise,
                     const float* __restrict__ mu, const float* __restrict__ lsig,
                     const float* __restrict__ lng, const float* __restrict__ lnb) {
    __shared__ float sWqT[65 * 64];   // padded transpose of Wq: [d][e] stride 65
    __shared__ float slot_s[256];     // this block's 4 rows
    int tid = threadIdx.x;
    int t = blockIdx.x * 256 + tid;   // global over 32768

    // slots init (this block covers rows 4B..4B+3)
    {
        int d = t & 63;
        float val = __ldg(mu + d) + __expf(__ldg(lsig + d)) * noise[t];
        g_slots[t] = val;
        slot_s[tid] = val;
    }
    #pragma unroll
    for (int i = tid; i < 4096; i += 256) { int e = i >> 6, d = i & 63; sWqT[d*65 + e] = Wq[i]; }
    __syncthreads();

    // slots LN: warps 0..3, warp w -> local row w
    if (tid < 128) {
        int w = tid >> 5, lane = tid & 31;
        float s0 = slot_s[w*64 + lane], s1 = slot_s[w*64 + 32 + lane];
        float s = s0 + s1, ss = s0*s0 + s1*s1;
        #pragma unroll
        for (int o = 16; o > 0; o >>= 1) { s += __shfl_xor_sync(~0u, s, o); ss += __shfl_xor_sync(~0u, ss, o); }
        float m = s * 0.015625f;
        float rstd = rsqrtf(ss * 0.015625f - m*m + 1e-5f);
        slot_s[w*64 + lane]      = (s0 - m)*rstd*__ldg(lng+lane)    + __ldg(lnb+lane);
        slot_s[w*64 + 32 + lane] = (s1 - m)*rstd*__ldg(lng+32+lane) + __ldg(lnb+32+lane);
    }
    __syncthreads();

    // q projection for the 4 rows: thread (r, e)
    {
        int r = tid >> 6, e = tid & 63;
        float a = 0.f;
        #pragma unroll 16
        for (int d = 0; d < 64; d++) a += slot_s[r*64 + d] * sWqT[d*65 + e];
        int grow = blockIdx.x*4 + r;
        int b = grow >> 3, k = grow & 7;
        g_q[b*1024 + e*16 + k*2]     = a;
        g_q[b*1024 + e*16 + k*2 + 1] = a;
    }
}

// ---------------- fused input LN + K^T/V projection (LDS.128 weights) ----------------
__global__ void __launch_bounds__(256) ln_kv(const float* __restrict__ inp,
        const float* __restrict__ Wk, const float* __restrict__ Wv,
        const float* __restrict__ lng, const float* __restrict__ lnb) {
    __shared__ __align__(16) float xs[32 * 66];
    __shared__ __align__(16) float ws[128 * 64];
    int t = threadIdx.x;
    int r0 = blockIdx.x * 32;
    const float* ip = inp + (size_t)r0 * 64;
    #pragma unroll
    for (int i = 0; i < 8; i++) { int id = t + 256*i; xs[(id>>6)*66 + (id&63)] = ip[id]; }
    #pragma unroll
    for (int i = 0; i < 16; i++) { int id = t + 256*i; ws[id] = Wk[id]; ws[4096+id] = Wv[id]; }
    __syncthreads();
    {   // LayerNorm: 8 threads/row
        int row = t >> 3, sub = t & 7;
        float s = 0.f, ss = 0.f;
        #pragma unroll
        for (int i = 0; i < 8; i++) { float x = xs[row*66 + sub*8 + i]; s += x; ss += x*x; }
        s += __shfl_xor_sync(~0u, s, 1); ss += __shfl_xor_sync(~0u, ss, 1);
        s += __shfl_xor_sync(~0u, s, 2); ss += __shfl_xor_sync(~0u, ss, 2);
        s += __shfl_xor_sync(~0u, s, 4); ss += __shfl_xor_sync(~0u, ss, 4);
        float mu = s * 0.015625f;
        float rstd = rsqrtf(ss * 0.015625f - mu*mu + 1e-5f);
        #pragma unroll
        for (int i = 0; i < 8; i++) {
            int f = sub*8 + i;
            xs[row*66 + f] = (xs[row*66 + f] - mu) * rstd * __ldg(lng+f) + __ldg(lnb+f);
        }
    }
    __syncthreads();
    int tx = t & 15, ty = t >> 4;
    ull acc[8][2];
    #pragma unroll
    for (int j = 0; j < 8; j++) { acc[j][0] = 0ull; acc[j][1] = 0ull; }
    #pragma unroll 4
    for (int f4 = 0; f4 < 16; f4++) {            // 4 f-dims per step
        ull a0l = *(const ull*)&xs[tx*66 + 4*f4];
        ull a0h = *(const ull*)&xs[tx*66 + 4*f4 + 2];
        ull a1l = *(const ull*)&xs[(tx+16)*66 + 4*f4];
        ull a1h = *(const ull*)&xs[(tx+16)*66 + 4*f4 + 2];
        #pragma unroll
        for (int j = 0; j < 8; j++) {
            ulonglong2 bq = *(const ulonglong2*)&ws[(ty*8 + j)*64 + 4*f4];   // one LDS.128
            FMA2(acc[j][0], bq.x, a0l); FMA2(acc[j][0], bq.y, a0h);
            FMA2(acc[j][1], bq.x, a1l); FMA2(acc[j][1], bq.y, a1h);
        }
    }
    float cs[8][2];
    #pragma unroll
    for (int j = 0; j < 8; j++)
        #pragma unroll
        for (int i = 0; i < 2; i++) { float2 f = *reinterpret_cast<float2*>(&acc[j][i]); cs[j][i] = f.x + f.y; }

    int b = r0 >> 12, nn0 = r0 & 4095;
    float* os = ws;
    __syncthreads();
    if (ty < 8) {   // K wave -> transposed bf16 store
        #pragma unroll
        for (int j = 0; j < 8; j++) {
            int od = ty*8 + j;
            os[tx*66 + od] = cs[j][0];
            os[(tx+16)*66 + od] = cs[j][1];
        }
    }
    __syncthreads();
    #pragma unroll
    for (int i = 0; i < 4; i++) {
        int id = t + 256*i;                 // 0..1023
        int d = id >> 4, rp = id & 15;      // d, row-pair
        __nv_bfloat162 val = __floats2bfloat162_rn(os[(2*rp)*66 + d], os[(2*rp+1)*66 + d]);
        ((__nv_bfloat162*)g_kT)[((size_t)b*64 + d)*2048 + (nn0>>1) + rp] = val;
    }
    __syncthreads();
    if (ty >= 8) {  // V wave -> natural bf16 store
        #pragma unroll
        for (int j = 0; j < 8; j++) {
            int od = ty*8 + j - 64;
            os[tx*66 + od] = cs[j][0];
            os[(tx+16)*66 + od] = cs[j][1];
        }
    }
    __syncthreads();
    #pragma unroll
    for (int i = 0; i < 4; i++) {
        int id = t + 256*i;                 // 0..1023
        int row = id >> 5, dp = id & 31;    // row, d-pair
        __nv_bfloat162 val = __floats2bfloat162_rn(os[row*66 + 2*dp], os[row*66 + 2*dp + 1]);
        ((__nv_bfloat162*)g_v)[((size_t)(r0 + row))*32 + dp] = val;
    }
}

// ---------------- attention: bf16 k/v, FMA2, LDS.128 update reads ----------------
__global__ void __launch_bounds__(256) attn_kernel() {
    __shared__ __align__(16) float qst[1024];     // [e][16]: duplicated q pairs
    __shared__ __align__(16) float attn2[8192];   // [j][n][2] duplicated attn; later red[8][512]
    __shared__ float sred[64];
    int t = threadIdx.x, b = blockIdx.y, n0 = blockIdx.x * 512;

    ((float4*)qst)[t] = ((const float4*)(g_q + b*1024))[t];
    __syncthreads();

    // logits + softmax: thread handles token pair (2*t, 2*t+1)
    float sacc[8];
    {
        const __nv_bfloat162* kp = (const __nv_bfloat162*)g_kT + (size_t)b*131072 + (n0>>1) + t;
        ull l2[8];
        #pragma unroll
        for (int j = 0; j < 8; j++) l2[j] = 0ull;
        #pragma unroll 8
        for (int d = 0; d < 64; d++) {
            float2 kf = __bfloat1622float2(kp[d*2048]);
            ull kv; PACK2(kv, kf.x, kf.y);
            const ulonglong2* qp = (const ulonglong2*)&qst[d*16];
            ulonglong2 q01 = qp[0], q23 = qp[1];
            FMA2(l2[0], q01.x, kv); FMA2(l2[1], q01.y, kv);
            FMA2(l2[2], q23.x, kv); FMA2(l2[3], q23.y, kv);
            ulonglong2 q45 = qp[2], q67 = qp[3];
            FMA2(l2[4], q45.x, kv); FMA2(l2[5], q45.y, kv);
            FMA2(l2[6], q67.x, kv); FMA2(l2[7], q67.y, kv);
        }
        float l0[8], l1[8];
        #pragma unroll
        for (int j = 0; j < 8; j++) {
            float2 f = *reinterpret_cast<float2*>(&l2[j]);
            l0[j] = f.x; l1[j] = f.y;
        }
        float m0 = l0[0], m1 = l1[0];
        #pragma unroll
        for (int j = 1; j < 8; j++) { m0 = fmaxf(m0, l0[j]); m1 = fmaxf(m1, l1[j]); }
        float s0 = 0.f, s1 = 0.f, e0[8], e1[8];
        #pragma unroll
        for (int j = 0; j < 8; j++) {
            e0[j] = __expf((l0[j] - m0) * 0.125f); s0 += e0[j];
            e1[j] = __expf((l1[j] - m1) * 0.125f); s1 += e1[j];
        }
        float i0 = 1.0f / s0, i1 = 1.0f / s1;
        #pragma unroll
        for (int j = 0; j < 8; j++) {
            float a0 = e0[j]*i0 + 1e-8f;
            float a1 = e1[j]*i1 + 1e-8f;
            sacc[j] = a0 + a1;
            *(float4*)&attn2[(j*512 + 2*t)*2] = make_float4(a0, a0, a1, a1);
        }
    }
    // deterministic S reduce
    #pragma unroll
    for (int j = 0; j < 8; j++) {
        float v = sacc[j];
        #pragma unroll
        for (int o = 16; o > 0; o >>= 1) v += __shfl_xor_sync(~0u, v, o);
        if ((t & 31) == 0) sred[(t>>5)*8 + j] = v;
    }
    __syncthreads();
    if (t < 8) {
        float v = 0.f;
        #pragma unroll
        for (int w = 0; w < 8; w++) v += sred[w*8 + t];
        g_Sp[blockIdx.x*512 + b*8 + t] = v;
    }

    // update: warp = 64-token group, lane = d-pair; 2 tokens/iter, LDS.128 attn reads
    int d2 = t & 31, grp = t >> 5;
    ull acc2[8];
    #pragma unroll
    for (int j = 0; j < 8; j++) acc2[j] = 0ull;
    const __nv_bfloat162* vp = (const __nv_bfloat162*)g_v + ((size_t)b*4096 + n0)*32 + d2;
    int nbeg = grp * 64;
    #pragma unroll 2
    for (int n = nbeg; n < nbeg + 64; n += 2) {
        float2 vf0 = __bfloat1622float2(vp[(size_t)n*32]);
        float2 vf1 = __bfloat1622float2(vp[(size_t)(n+1)*32]);
        ull v0; PACK2(v0, vf0.x, vf0.y);
        ull v1; PACK2(v1, vf1.x, vf1.y);
        #pragma unroll
        for (int j = 0; j < 8; j++) {
            ulonglong2 ap = *(const ulonglong2*)&attn2[(j*512 + n)*2];  // broadcast LDS.128
            FMA2(acc2[j], ap.x, v0);
            FMA2(acc2[j], ap.y, v1);
        }
    }
    __syncthreads();                 // all attn2 reads done
    float* red = attn2;              // [grp][j*64 + d]
    #pragma unroll
    for (int j = 0; j < 8; j++) {
        float2 r = *reinterpret_cast<float2*>(&acc2[j]);
        *(float2*)&red[grp*512 + j*64 + d2*2] = r;
    }
    __syncthreads();
    #pragma unroll
    for (int rep = 0; rep < 2; rep++) {
        int idx = rep*256 + t;
        float v = 0.f;
        #pragma unroll
        for (int g = 0; g < 8; g++) v += red[g*512 + idx];
        g_Up[((size_t)blockIdx.x*64 + b)*512 + idx] = v;
    }
}

// ---------------- batched GRU + LN + MLP + residual + next-iter q ----------------
// Row-major weights consumed directly via contiguous float4 row reads.
__global__ void __launch_bounds__(384) gru_mlp(
        const float* __restrict__ wih, const float* __restrict__ whh,
        const float* __restrict__ bih, const float* __restrict__ bhh,
        const float* __restrict__ w1, const float* __restrict__ b1,
        const float* __restrict__ w2, const float* __restrict__ b2,
        const float* __restrict__ Wq,
        const float* __restrict__ lng, const float* __restrict__ lnb,
        const float* __restrict__ lng2, const float* __restrict__ lnb2,
        float* __restrict__ out, int last) {
    __shared__ __align__(16) float u_s[256], h_s[256];
    __shared__ __align__(16) float gi_s[768], gh_s[768];
    __shared__ __align__(16) float hn_s[256], ln_s[256], h1_s[512];
    int t = threadIdx.x;
    int grow0 = blockIdx.x * 4;

    // Phase A: u = U/S, h = slots
    if (t < 256) {
        int r = t >> 6, d = t & 63;
        int grow = grow0 + r;
        float S = 0.f, U = 0.f;
        #pragma unroll
        for (int c = 0; c < 8; c++) {
            S += g_Sp[c*512 + grow];
            U += g_Up[c*32768 + grow*64 + d];
        }
        u_s[t] = U / S;
        h_s[t] = g_slots[grow*64 + d];
    }
    __syncthreads();

    // Phase B: gates. t<192: gi over wih rows; t>=192: gh over whh rows. 4 rows each.
    {
        int j = (t < 192) ? t : (t - 192);
        const float4* W = (const float4*)((t < 192) ? wih : whh) + j*16;  // row j, 64 floats
        const float* xb = (t < 192) ? u_s : h_s;
        float a0 = 0.f, a1 = 0.f, a2 = 0.f, a3 = 0.f;
        #pragma unroll
        for (int i = 0; i < 16; i++) {
            float4 w = __ldg(W + i);
            float4 x0 = *(const float4*)&xb[i*4];
            float4 x1 = *(const float4*)&xb[64 + i*4];
            float4 x2 = *(const float4*)&xb[128 + i*4];
            float4 x3 = *(const float4*)&xb[192 + i*4];
            a0 += dot4(x0, w); a1 += dot4(x1, w); a2 += dot4(x2, w); a3 += dot4(x3, w);
        }
        float bias = (t < 192) ? __ldg(bih + j) : __ldg(bhh + j);
        float* G = (t < 192) ? gi_s : gh_s;
        G[j]       = a0 + bias;
        G[192 + j] = a1 + bias;
        G[384 + j] = a2 + bias;
        G[576 + j] = a3 + bias;
    }
    __syncthreads();

    // Phase C: GRU combine
    if (t < 256) {
        int r = t >> 6, d = t & 63;
        float rr = sigf(gi_s[r*192 + d]       + gh_s[r*192 + d]);
        float z  = sigf(gi_s[r*192 + 64 + d]  + gh_s[r*192 + 64 + d]);
        float n  = tanhf(gi_s[r*192 + 128 + d] + rr * gh_s[r*192 + 128 + d]);
        hn_s[t] = (1.f - z)*n + z*h_s[t];
    }
    __syncthreads();

    // Phase D: LayerNorm (mlp), warp per row
    if (t < 128) {
        int r = t >> 5, lane = t & 31;
        float x0 = hn_s[r*64 + lane], x1 = hn_s[r*64 + 32 + lane];
        float s = x0 + x1, ss = x0*x0 + x1*x1;
        #pragma unroll
        for (int o = 16; o > 0; o >>= 1) { s += __shfl_xor_sync(~0u, s, o); ss += __shfl_xor_sync(~0u, ss, o); }
        float mu = s * 0.015625f;
        float rstd = rsqrtf(ss * 0.015625f - mu*mu + 1e-5f);
        ln_s[r*64 + lane]      = (x0 - mu)*rstd*__ldg(lng+lane)    + __ldg(lnb+lane);
        ln_s[r*64 + 32 + lane] = (x1 - mu)*rstd*__ldg(lng+32+lane) + __ldg(lnb+32+lane);
    }
    __syncthreads();

    // Phase E: MLP layer1 + relu. t<128: w1 row j (64 floats) x 4 rows.
    if (t < 128) {
        const float4* W = (const float4*)w1 + t*16;
        float a0 = 0.f, a1 = 0.f, a2 = 0.f, a3 = 0.f;
        #pragma unroll
        for (int i = 0; i < 16; i++) {
            float4 w = __ldg(W + i);
            float4 x0 = *(const float4*)&ln_s[i*4];
            float4 x1 = *(const float4*)&ln_s[64 + i*4];
            float4 x2 = *(const float4*)&ln_s[128 + i*4];
            float4 x3 = *(const float4*)&ln_s[192 + i*4];
            a0 += dot4(x0, w); a1 += dot4(x1, w); a2 += dot4(x2, w); a3 += dot4(x3, w);
        }
        float bias = __ldg(b1 + t);
        h1_s[t]       = fmaxf(a0 + bias, 0.f);
        h1_s[128 + t] = fmaxf(a1 + bias, 0.f);
        h1_s[256 + t] = fmaxf(a2 + bias, 0.f);
        h1_s[384 + t] = fmaxf(a3 + bias, 0.f);
    }
    __syncthreads();

    // Phase F: MLP layer2 + residual. t<256: (row r, output o); w2 row o (128 floats).
    if (t < 256) {
        int r = t >> 6, o = t & 63;
        const float4* W = (const float4*)w2 + o*32;
        const float4* H = (const float4*)&h1_s[r*128];
        float a = 0.f;
        #pragma unroll
        for (int i = 0; i < 32; i++) a += dot4(H[i], __ldg(W + i));
        a += __ldg(b2 + o);
        float res = hn_s[r*64 + o] + a;
        int grow = grow0 + r;
        g_slots[grow*64 + o] = res;
        if (last) out[grow*64 + o] = res;
        u_s[t] = res;                    // stage for q phase
    }
    if (last) return;
    __syncthreads();

    // ---- next-iter q: slots-LN + Wq row reads ----
    if (t < 128) {
        int r = t >> 5, lane = t & 31;
        float x0 = u_s[r*64 + lane], x1 = u_s[r*64 + 32 + lane];
        float s = x0 + x1, ss = x0*x0 + x1*x1;
        #pragma unroll
        for (int o = 16; o > 0; o >>= 1) { s += __shfl_xor_sync(~0u, s, o); ss += __shfl_xor_sync(~0u, ss, o); }
        float mu = s * 0.015625f;
        float rstd = rsqrtf(ss * 0.015625f - mu*mu + 1e-5f);
        ln_s[r*64 + lane]      = (x0 - mu)*rstd*__ldg(lng2+lane)    + __ldg(lnb2+lane);
        ln_s[r*64 + 32 + lane] = (x1 - mu)*rstd*__ldg(lng2+32+lane) + __ldg(lnb2+32+lane);
    }
    __syncthreads();
    if (t < 256) {
        int r = t >> 6, e = t & 63;
        const float4* W = (const float4*)Wq + e*16;   // Wq row e (64 floats)
        const float4* X = (const float4*)&ln_s[r*64];
        float a = 0.f;
        #pragma unroll
        for (int i = 0; i < 16; i++) a += dot4(X[i], __ldg(W + i));
        int grow = grow0 + r;
        int b = grow >> 3, k = grow & 7;
        g_q[b*1024 + e*16 + k*2]     = a;
        g_q[b*1024 + e*16 + k*2 + 1] = a;
    }
}

extern "C" void kernel_launch(void* const* d_in, const int* in_sizes, int n_in,
                              void* d_out, int out_size) {
    const float* inputs = (const float*)d_in[0];
    const float* noise  = (const float*)d_in[1];
    const float* mu     = (const float*)d_in[2];
    const float* lsig   = (const float*)d_in[3];
    const float* Wq     = (const float*)d_in[4];
    const float* Wk     = (const float*)d_in[5];
    const float* Wv     = (const float*)d_in[6];
    const float* wih    = (const float*)d_in[7];
    const float* whh    = (const float*)d_in[8];
    const float* bih    = (const float*)d_in[9];
    const float* bhh    = (const float*)d_in[10];
    const float* w1     = (const float*)d_in[11];
    const float* b1     = (const float*)d_in[12];
    const float* w2     = (const float*)d_in[13];
    const float* b2     = (const float*)d_in[14];
    const float* ln_in_g   = (const float*)d_in[15];
    const float* ln_in_b   = (const float*)d_in[16];
    const float* ln_sl_g   = (const float*)d_in[17];
    const float* ln_sl_b   = (const float*)d_in[18];
    const float* ln_mlp_g  = (const float*)d_in[19];
    const float* ln_mlp_b  = (const float*)d_in[20];
    float* out = (float*)d_out;

    prep<<<128, 256>>>(Wq, noise, mu, lsig, ln_sl_g, ln_sl_b);
    ln_kv<<<8192, 256>>>(inputs, Wk, Wv, ln_in_g, ln_in_b);
    for (int it = 0; it < 3; it++) {
        attn_kernel<<<dim3(8, 64), 256>>>();
        gru_mlp<<<128, 384>>>(wih, whh, bih, bhh, w1, b1, w2, b2, Wq,
                              ln_mlp_g, ln_mlp_b, ln_sl_g, ln_sl_b, out, it == 2);
    }
}

// round 10
// speedup vs baseline: 2.0563x; 1.1017x over previous
#include <cuda_runtime.h>
#include <cuda_bf16.h>

typedef unsigned long long ull;

// ---------------- device scratch ----------------
__device__ __nv_bfloat16 g_kT[16777216];  // [b][d][n] transposed K (bf16)
__device__ __nv_bfloat16 g_v [16777216];  // [b][n][d] (bf16)
__device__ float g_slots[32768];   // [b][k][d]
__device__ float g_q[65536];       // [b][e][j*2] duplicated-transposed q
__device__ float g_Up[262144];     // [chunk(8)][b][k][d]
__device__ float g_Sp[4096];       // [chunk(8)][b*8+k]

#define FMA2(acc, a, b) asm("fma.rn.f32x2 %0, %1, %2, %0;" : "+l"(acc) : "l"(a), "l"(b))
#define PACK2(dst, x, y) asm("mov.b64 %0, {%1, %2};" : "=l"(dst) : "f"(x), "f"(y))

__device__ __forceinline__ float sigf(float x) { return 1.f / (1.f + __expf(-x)); }
__device__ __forceinline__ float dot4(float4 a, float4 b) {
    return a.x*b.x + a.y*b.y + a.z*b.z + a.w*b.w;
}

// ---------------- prep: slots init + iter-1 q ----------------
__global__ void __launch_bounds__(256) prep(const float* __restrict__ Wq,
                     const float* __restrict__ noise,
                     const float* __restrict__ mu, const float* __restrict__ lsig,
                     const float* __restrict__ lng, const float* __restrict__ lnb) {
    __shared__ float sWqT[65 * 64];   // padded transpose of Wq: [d][e] stride 65
    __shared__ float slot_s[256];     // this block's 4 rows
    int tid = threadIdx.x;
    int t = blockIdx.x * 256 + tid;   // global over 32768

    {
        int d = t & 63;
        float val = __ldg(mu + d) + __expf(__ldg(lsig + d)) * noise[t];
        g_slots[t] = val;
        slot_s[tid] = val;
    }
    #pragma unroll
    for (int i = tid; i < 4096; i += 256) { int e = i >> 6, d = i & 63; sWqT[d*65 + e] = Wq[i]; }
    __syncthreads();

    if (tid < 128) {
        int w = tid >> 5, lane = tid & 31;
        float s0 = slot_s[w*64 + lane], s1 = slot_s[w*64 + 32 + lane];
        float s = s0 + s1, ss = s0*s0 + s1*s1;
        #pragma unroll
        for (int o = 16; o > 0; o >>= 1) { s += __shfl_xor_sync(~0u, s, o); ss += __shfl_xor_sync(~0u, ss, o); }
        float m = s * 0.015625f;
        float rstd = rsqrtf(ss * 0.015625f - m*m + 1e-5f);
        slot_s[w*64 + lane]      = (s0 - m)*rstd*__ldg(lng+lane)    + __ldg(lnb+lane);
        slot_s[w*64 + 32 + lane] = (s1 - m)*rstd*__ldg(lng+32+lane) + __ldg(lnb+32+lane);
    }
    __syncthreads();

    {
        int r = tid >> 6, e = tid & 63;
        float a = 0.f;
        #pragma unroll 16
        for (int d = 0; d < 64; d++) a += slot_s[r*64 + d] * sWqT[d*65 + e];
        int grow = blockIdx.x*4 + r;
        int b = grow >> 3, k = grow & 7;
        g_q[b*1024 + e*16 + k*2]     = a;
        g_q[b*1024 + e*16 + k*2 + 1] = a;
    }
}

// ---------------- fused input LN + K^T/V projection (LDS.128 weights) ----------------
__global__ void __launch_bounds__(256) ln_kv(const float* __restrict__ inp,
        const float* __restrict__ Wk, const float* __restrict__ Wv,
        const float* __restrict__ lng, const float* __restrict__ lnb) {
    __shared__ __align__(16) float xs[32 * 66];
    __shared__ __align__(16) float ws[128 * 64];
    int t = threadIdx.x;
    int r0 = blockIdx.x * 32;
    const float* ip = inp + (size_t)r0 * 64;
    #pragma unroll
    for (int i = 0; i < 8; i++) { int id = t + 256*i; xs[(id>>6)*66 + (id&63)] = ip[id]; }
    #pragma unroll
    for (int i = 0; i < 16; i++) { int id = t + 256*i; ws[id] = Wk[id]; ws[4096+id] = Wv[id]; }
    __syncthreads();
    {   // LayerNorm: 8 threads/row
        int row = t >> 3, sub = t & 7;
        float s = 0.f, ss = 0.f;
        #pragma unroll
        for (int i = 0; i < 8; i++) { float x = xs[row*66 + sub*8 + i]; s += x; ss += x*x; }
        s += __shfl_xor_sync(~0u, s, 1); ss += __shfl_xor_sync(~0u, ss, 1);
        s += __shfl_xor_sync(~0u, s, 2); ss += __shfl_xor_sync(~0u, ss, 2);
        s += __shfl_xor_sync(~0u, s, 4); ss += __shfl_xor_sync(~0u, ss, 4);
        float mu = s * 0.015625f;
        float rstd = rsqrtf(ss * 0.015625f - mu*mu + 1e-5f);
        #pragma unroll
        for (int i = 0; i < 8; i++) {
            int f = sub*8 + i;
            xs[row*66 + f] = (xs[row*66 + f] - mu) * rstd * __ldg(lng+f) + __ldg(lnb+f);
        }
    }
    __syncthreads();
    int tx = t & 15, ty = t >> 4;
    ull acc[8][2];
    #pragma unroll
    for (int j = 0; j < 8; j++) { acc[j][0] = 0ull; acc[j][1] = 0ull; }
    #pragma unroll 4
    for (int f4 = 0; f4 < 16; f4++) {            // 4 f-dims per step
        ull a0l = *(const ull*)&xs[tx*66 + 4*f4];
        ull a0h = *(const ull*)&xs[tx*66 + 4*f4 + 2];
        ull a1l = *(const ull*)&xs[(tx+16)*66 + 4*f4];
        ull a1h = *(const ull*)&xs[(tx+16)*66 + 4*f4 + 2];
        #pragma unroll
        for (int j = 0; j < 8; j++) {
            ulonglong2 bq = *(const ulonglong2*)&ws[(ty*8 + j)*64 + 4*f4];   // one LDS.128
            FMA2(acc[j][0], bq.x, a0l); FMA2(acc[j][0], bq.y, a0h);
            FMA2(acc[j][1], bq.x, a1l); FMA2(acc[j][1], bq.y, a1h);
        }
    }
    float cs[8][2];
    #pragma unroll
    for (int j = 0; j < 8; j++)
        #pragma unroll
        for (int i = 0; i < 2; i++) { float2 f = *reinterpret_cast<float2*>(&acc[j][i]); cs[j][i] = f.x + f.y; }

    int b = r0 >> 12, nn0 = r0 & 4095;
    float* os = ws;
    __syncthreads();
    if (ty < 8) {   // K wave -> transposed bf16 store
        #pragma unroll
        for (int j = 0; j < 8; j++) {
            int od = ty*8 + j;
            os[tx*66 + od] = cs[j][0];
            os[(tx+16)*66 + od] = cs[j][1];
        }
    }
    __syncthreads();
    #pragma unroll
    for (int i = 0; i < 4; i++) {
        int id = t + 256*i;                 // 0..1023
        int d = id >> 4, rp = id & 15;      // d, row-pair
        __nv_bfloat162 val = __floats2bfloat162_rn(os[(2*rp)*66 + d], os[(2*rp+1)*66 + d]);
        ((__nv_bfloat162*)g_kT)[((size_t)b*64 + d)*2048 + (nn0>>1) + rp] = val;
    }
    __syncthreads();
    if (ty >= 8) {  // V wave -> natural bf16 store
        #pragma unroll
        for (int j = 0; j < 8; j++) {
            int od = ty*8 + j - 64;
            os[tx*66 + od] = cs[j][0];
            os[(tx+16)*66 + od] = cs[j][1];
        }
    }
    __syncthreads();
    #pragma unroll
    for (int i = 0; i < 4; i++) {
        int id = t + 256*i;                 // 0..1023
        int row = id >> 5, dp = id & 31;    // row, d-pair
        __nv_bfloat162 val = __floats2bfloat162_rn(os[row*66 + 2*dp], os[row*66 + 2*dp + 1]);
        ((__nv_bfloat162*)g_v)[((size_t)(r0 + row))*32 + dp] = val;
    }
}

// ---------------- attention: bf16 k/v, FMA2, LDS.128 update reads ----------------
__global__ void __launch_bounds__(256) attn_kernel() {
    __shared__ __align__(16) float qst[1024];     // [e][16]: duplicated q pairs
    __shared__ __align__(16) float attn2[8192];   // [j][n][2] duplicated attn; later red[8][512]
    __shared__ float sred[64];
    int t = threadIdx.x, b = blockIdx.y, n0 = blockIdx.x * 512;

    ((float4*)qst)[t] = ((const float4*)(g_q + b*1024))[t];
    __syncthreads();

    // logits + softmax: thread handles token pair (2*t, 2*t+1)
    float sacc[8];
    {
        const __nv_bfloat162* kp = (const __nv_bfloat162*)g_kT + (size_t)b*131072 + (n0>>1) + t;
        ull l2[8];
        #pragma unroll
        for (int j = 0; j < 8; j++) l2[j] = 0ull;
        #pragma unroll 8
        for (int d = 0; d < 64; d++) {
            float2 kf = __bfloat1622float2(kp[d*2048]);
            ull kv; PACK2(kv, kf.x, kf.y);
            const ulonglong2* qp = (const ulonglong2*)&qst[d*16];
            ulonglong2 q01 = qp[0], q23 = qp[1];
            FMA2(l2[0], q01.x, kv); FMA2(l2[1], q01.y, kv);
            FMA2(l2[2], q23.x, kv); FMA2(l2[3], q23.y, kv);
            ulonglong2 q45 = qp[2], q67 = qp[3];
            FMA2(l2[4], q45.x, kv); FMA2(l2[5], q45.y, kv);
            FMA2(l2[6], q67.x, kv); FMA2(l2[7], q67.y, kv);
        }
        float l0[8], l1[8];
        #pragma unroll
        for (int j = 0; j < 8; j++) {
            float2 f = *reinterpret_cast<float2*>(&l2[j]);
            l0[j] = f.x; l1[j] = f.y;
        }
        float m0 = l0[0], m1 = l1[0];
        #pragma unroll
        for (int j = 1; j < 8; j++) { m0 = fmaxf(m0, l0[j]); m1 = fmaxf(m1, l1[j]); }
        float s0 = 0.f, s1 = 0.f, e0[8], e1[8];
        #pragma unroll
        for (int j = 0; j < 8; j++) {
            e0[j] = __expf((l0[j] - m0) * 0.125f); s0 += e0[j];
            e1[j] = __expf((l1[j] - m1) * 0.125f); s1 += e1[j];
        }
        float i0 = 1.0f / s0, i1 = 1.0f / s1;
        #pragma unroll
        for (int j = 0; j < 8; j++) {
            float a0 = e0[j]*i0 + 1e-8f;
            float a1 = e1[j]*i1 + 1e-8f;
            sacc[j] = a0 + a1;
            *(float4*)&attn2[(j*512 + 2*t)*2] = make_float4(a0, a0, a1, a1);
        }
    }
    // deterministic S reduce
    #pragma unroll
    for (int j = 0; j < 8; j++) {
        float v = sacc[j];
        #pragma unroll
        for (int o = 16; o > 0; o >>= 1) v += __shfl_xor_sync(~0u, v, o);
        if ((t & 31) == 0) sred[(t>>5)*8 + j] = v;
    }
    __syncthreads();
    if (t < 8) {
        float v = 0.f;
        #pragma unroll
        for (int w = 0; w < 8; w++) v += sred[w*8 + t];
        g_Sp[blockIdx.x*512 + b*8 + t] = v;
    }

    // update: warp = 64-token group, lane = d-pair; 2 tokens/iter, LDS.128 attn reads
    int d2 = t & 31, grp = t >> 5;
    ull acc2[8];
    #pragma unroll
    for (int j = 0; j < 8; j++) acc2[j] = 0ull;
    const __nv_bfloat162* vp = (const __nv_bfloat162*)g_v + ((size_t)b*4096 + n0)*32 + d2;
    int nbeg = grp * 64;
    #pragma unroll 2
    for (int n = nbeg; n < nbeg + 64; n += 2) {
        float2 vf0 = __bfloat1622float2(vp[(size_t)n*32]);
        float2 vf1 = __bfloat1622float2(vp[(size_t)(n+1)*32]);
        ull v0; PACK2(v0, vf0.x, vf0.y);
        ull v1; PACK2(v1, vf1.x, vf1.y);
        #pragma unroll
        for (int j = 0; j < 8; j++) {
            ulonglong2 ap = *(const ulonglong2*)&attn2[(j*512 + n)*2];  // broadcast LDS.128
            FMA2(acc2[j], ap.x, v0);
            FMA2(acc2[j], ap.y, v1);
        }
    }
    __syncthreads();                 // all attn2 reads done
    float* red = attn2;              // [grp][j*64 + d]
    #pragma unroll
    for (int j = 0; j < 8; j++) {
        float2 r = *reinterpret_cast<float2*>(&acc2[j]);
        *(float2*)&red[grp*512 + j*64 + d2*2] = r;
    }
    __syncthreads();
    #pragma unroll
    for (int rep = 0; rep < 2; rep++) {
        int idx = rep*256 + t;
        float v = 0.f;
        #pragma unroll
        for (int g = 0; g < 8; g++) v += red[g*512 + idx];
        g_Up[((size_t)blockIdx.x*64 + b)*512 + idx] = v;
    }
}

// ---------------- batched GRU + LN + MLP + residual + next-iter q ----------------
// Weights staged through smem: coalesced LDG in, conflict-free padded LDS out.
__global__ void __launch_bounds__(384) gru_mlp(
        const float* __restrict__ wih, const float* __restrict__ whh,
        const float* __restrict__ bih, const float* __restrict__ bhh,
        const float* __restrict__ w1, const float* __restrict__ b1,
        const float* __restrict__ w2, const float* __restrict__ b2,
        const float* __restrict__ Wq,
        const float* __restrict__ lng, const float* __restrict__ lnb,
        const float* __restrict__ lng2, const float* __restrict__ lnb2,
        float* __restrict__ out, int last) {
    __shared__ __align__(16) float u_s[256], h_s[256];
    __shared__ __align__(16) float gi_s[768], gh_s[768];
    __shared__ __align__(16) float hn_s[256], ln_s[256], h1_s[512];
    __shared__ __align__(16) float wbuf[6912];    // 27.6 KB staging buffer
    int t = threadIdx.x;
    int grow0 = blockIdx.x * 4;

    // Phase A: u = U/S, h = slots
    if (t < 256) {
        int r = t >> 6, d = t & 63;
        int grow = grow0 + r;
        float S = 0.f, U = 0.f;
        #pragma unroll
        for (int c = 0; c < 8; c++) {
            S += g_Sp[c*512 + grow];
            U += g_Up[c*32768 + grow*64 + d];
        }
        u_s[t] = U / S;
        h_s[t] = g_slots[grow*64 + d];
    }

    // Phase B: gates. thread t -> gate j = t%192, row-pair rp = t/192 (rows 2rp, 2rp+1).
    // Weights staged in column-halves: [192][32] -> wbuf stride 36 (conflict-free LDS.128).
    float accI0 = 0.f, accI1 = 0.f, accH0 = 0.f, accH1 = 0.f;
    int j = (t < 192) ? t : (t - 192);
    int rp = (t < 192) ? 0 : 1;
    #pragma unroll
    for (int half = 0; half < 2; half++) {
        __syncthreads();
        #pragma unroll
        for (int i = t; i < 6144; i += 384) { int jj = i >> 5, c = i & 31; wbuf[jj*36 + c] = __ldg(&wih[jj*64 + half*32 + c]); }
        __syncthreads();
        {
            const float4* W  = (const float4*)wbuf + j*9;
            const float4* X0 = (const float4*)(u_s + rp*128) + half*8;
            const float4* X1 = (const float4*)(u_s + rp*128 + 64) + half*8;
            #pragma unroll
            for (int i = 0; i < 8; i++) { float4 w = W[i]; accI0 += dot4(X0[i], w); accI1 += dot4(X1[i], w); }
        }
        __syncthreads();
        #pragma unroll
        for (int i = t; i < 6144; i += 384) { int jj = i >> 5, c = i & 31; wbuf[jj*36 + c] = __ldg(&whh[jj*64 + half*32 + c]); }
        __syncthreads();
        {
            const float4* W  = (const float4*)wbuf + j*9;
            const float4* X0 = (const float4*)(h_s + rp*128) + half*8;
            const float4* X1 = (const float4*)(h_s + rp*128 + 64) + half*8;
            #pragma unroll
            for (int i = 0; i < 8; i++) { float4 w = W[i]; accH0 += dot4(X0[i], w); accH1 += dot4(X1[i], w); }
        }
    }
    {
        float bi = __ldg(bih + j), bh = __ldg(bhh + j);
        int r0 = rp*2;
        gi_s[r0*192 + j]     = accI0 + bi;
        gi_s[(r0+1)*192 + j] = accI1 + bi;
        gh_s[r0*192 + j]     = accH0 + bh;
        gh_s[(r0+1)*192 + j] = accH1 + bh;
    }
    __syncthreads();

    // Phase C: GRU combine
    if (t < 256) {
        int r = t >> 6, d = t & 63;
        float rr = sigf(gi_s[r*192 + d]       + gh_s[r*192 + d]);
        float z  = sigf(gi_s[r*192 + 64 + d]  + gh_s[r*192 + 64 + d]);
        float n  = tanhf(gi_s[r*192 + 128 + d] + rr * gh_s[r*192 + 128 + d]);
        hn_s[t] = (1.f - z)*n + z*h_s[t];
    }
    __syncthreads();

    // Phase D: LayerNorm (mlp), warp per row
    if (t < 128) {
        int r = t >> 5, lane = t & 31;
        float x0 = hn_s[r*64 + lane], x1 = hn_s[r*64 + 32 + lane];
        float s = x0 + x1, ss = x0*x0 + x1*x1;
        #pragma unroll
        for (int o = 16; o > 0; o >>= 1) { s += __shfl_xor_sync(~0u, s, o); ss += __shfl_xor_sync(~0u, ss, o); }
        float mu = s * 0.015625f;
        float rstd = rsqrtf(ss * 0.015625f - mu*mu + 1e-5f);
        ln_s[r*64 + lane]      = (x0 - mu)*rstd*__ldg(lng+lane)    + __ldg(lnb+lane);
        ln_s[r*64 + 32 + lane] = (x1 - mu)*rstd*__ldg(lng+32+lane) + __ldg(lnb+32+lane);
    }

    // Phase E: MLP layer1 + relu. w1 [128][64] staged in halves [128][32] stride 36.
    float e0 = 0.f, e1 = 0.f, e2 = 0.f, e3 = 0.f;
    #pragma unroll
    for (int half = 0; half < 2; half++) {
        __syncthreads();
        #pragma unroll
        for (int i = t; i < 4096; i += 384) { int jj = i >> 5, c = i & 31; wbuf[jj*36 + c] = __ldg(&w1[jj*64 + half*32 + c]); }
        __syncthreads();
        if (t < 128) {
            const float4* W  = (const float4*)wbuf + t*9;
            const float4* X0 = (const float4*)(ln_s)       + half*8;
            const float4* X1 = (const float4*)(ln_s + 64)  + half*8;
            const float4* X2 = (const float4*)(ln_s + 128) + half*8;
            const float4* X3 = (const float4*)(ln_s + 192) + half*8;
            #pragma unroll
            for (int i = 0; i < 8; i++) {
                float4 w = W[i];
                e0 += dot4(X0[i], w); e1 += dot4(X1[i], w);
                e2 += dot4(X2[i], w); e3 += dot4(X3[i], w);
            }
        }
    }
    if (t < 128) {
        float bias = __ldg(b1 + t);
        h1_s[t]       = fmaxf(e0 + bias, 0.f);
        h1_s[128 + t] = fmaxf(e1 + bias, 0.f);
        h1_s[256 + t] = fmaxf(e2 + bias, 0.f);
        h1_s[384 + t] = fmaxf(e3 + bias, 0.f);
    }

    // Phase F: MLP layer2 + residual. w2 [64][128] staged in halves [64][64] stride 68.
    float facc = 0.f;
    int fr = (t >> 6) & 3, fo = t & 63;
    #pragma unroll
    for (int half = 0; half < 2; half++) {
        __syncthreads();
        #pragma unroll
        for (int i = t; i < 4096; i += 384) { int jj = i >> 6, c = i & 63; wbuf[jj*68 + c] = __ldg(&w2[jj*128 + half*64 + c]); }
        __syncthreads();
        if (t < 256) {
            const float4* W = (const float4*)wbuf + fo*17;
            const float4* H = (const float4*)(h1_s + fr*128 + half*64);
            #pragma unroll
            for (int i = 0; i < 16; i++) facc += dot4(H[i], W[i]);
        }
    }
    if (t < 256) {
        float a = facc + __ldg(b2 + fo);
        float res = hn_s[fr*64 + fo] + a;
        int grow = grow0 + fr;
        g_slots[grow*64 + fo] = res;
        if (last) out[grow*64 + fo] = res;
        u_s[t] = res;                    // stage new slots for q phase
    }
    if (last) return;
    __syncthreads();

    // ---- next-iter q: stage Wq [64][64] stride 68, slots-LN, project ----
    #pragma unroll
    for (int i = t; i < 4096; i += 384) { int jj = i >> 6, c = i & 63; wbuf[jj*68 + c] = __ldg(&Wq[jj*64 + c]); }
    if (t < 128) {
        int r = t >> 5, lane = t & 31;
        float x0 = u_s[r*64 + lane], x1 = u_s[r*64 + 32 + lane];
        float s = x0 + x1, ss = x0*x0 + x1*x1;
        #pragma unroll
        for (int o = 16; o > 0; o >>= 1) { s += __shfl_xor_sync(~0u, s, o); ss += __shfl_xor_sync(~0u, ss, o); }
        float mu = s * 0.015625f;
        float rstd = rsqrtf(ss * 0.015625f - mu*mu + 1e-5f);
        ln_s[r*64 + lane]      = (x0 - mu)*rstd*__ldg(lng2+lane)    + __ldg(lnb2+lane);
        ln_s[r*64 + 32 + lane] = (x1 - mu)*rstd*__ldg(lng2+32+lane) + __ldg(lnb2+32+lane);
    }
    __syncthreads();
    if (t < 256) {
        int r = t >> 6, e = t & 63;
        const float4* W = (const float4*)wbuf + e*17;
        const float4* X = (const float4*)(ln_s + r*64);
        float a = 0.f;
        #pragma unroll
        for (int i = 0; i < 16; i++) a += dot4(X[i], W[i]);
        int grow = grow0 + r;
        int b = grow >> 3, k = grow & 7;
        g_q[b*1024 + e*16 + k*2]     = a;
        g_q[b*1024 + e*16 + k*2 + 1] = a;
    }
}

extern "C" void kernel_launch(void* const* d_in, const int* in_sizes, int n_in,
                              void* d_out, int out_size) {
    const float* inputs = (const float*)d_in[0];
    const float* noise  = (const float*)d_in[1];
    const float* mu     = (const float*)d_in[2];
    const float* lsig   = (const float*)d_in[3];
    const float* Wq     = (const float*)d_in[4];
    const float* Wk     = (const float*)d_in[5];
    const float* Wv     = (const float*)d_in[6];
    const float* wih    = (const float*)d_in[7];
    const float* whh    = (const float*)d_in[8];
    const float* bih    = (const float*)d_in[9];
    const float* bhh    = (const float*)d_in[10];
    const float* w1     = (const float*)d_in[11];
    const float* b1     = (const float*)d_in[12];
    const float* w2     = (const float*)d_in[13];
    const float* b2     = (const float*)d_in[14];
    const float* ln_in_g   = (const float*)d_in[15];
    const float* ln_in_b   = (const float*)d_in[16];
    const float* ln_sl_g   = (const float*)d_in[17];
    const float* ln_sl_b   = (const float*)d_in[18];
    const float* ln_mlp_g  = (const float*)d_in[19];
    const float* ln_mlp_b  = (const float*)d_in[20];
    float* out = (float*)d_out;

    prep<<<128, 256>>>(Wq, noise, mu, lsig, ln_sl_g, ln_sl_b);
    ln_kv<<<8192, 256>>>(inputs, Wk, Wv, ln_in_g, ln_in_b);
    for (int it = 0; it < 3; it++) {
        attn_kernel<<<dim3(8, 64), 256>>>();
        gru_mlp<<<128, 384>>>(wih, whh, bih, bhh, w1, b1, w2, b2, Wq,
                              ln_mlp_g, ln_mlp_b, ln_sl_g, ln_sl_b, out, it == 2);
    }
}

// round 11
// speedup vs baseline: 3.1662x; 1.5397x over previous
#include <cuda_runtime.h>
#include <cuda_bf16.h>

typedef unsigned long long ull;
typedef unsigned int uint32;

// ---------------- device scratch ----------------
__device__ __nv_bfloat16 g_kT[16777216];  // [b][d][n] transposed K (bf16)
__device__ __nv_bfloat16 g_v [16777216];  // [b][n][d] (bf16)
__device__ float g_slots[32768];   // [b][k][d]
__device__ float g_q[65536];       // [b][e][j*2] duplicated-transposed q
__device__ float g_Up[262144];     // [chunk(8)][b][k][d]
__device__ float g_Sp[4096];       // [chunk(8)][b*8+k]

#define FMA2(acc, a, b) asm("fma.rn.f32x2 %0, %1, %2, %0;" : "+l"(acc) : "l"(a), "l"(b))
#define PACK2(dst, x, y) asm("mov.b64 %0, {%1, %2};" : "=l"(dst) : "f"(x), "f"(y))

#define MMA16816(d, a0, a1, a2, a3, b0, b1) \
    asm volatile("mma.sync.aligned.m16n8k16.row.col.f32.bf16.bf16.f32 " \
        "{%0,%1,%2,%3}, {%4,%5,%6,%7}, {%8,%9}, {%0,%1,%2,%3};" \
        : "+f"(d[0]), "+f"(d[1]), "+f"(d[2]), "+f"(d[3]) \
        : "r"(a0), "r"(a1), "r"(a2), "r"(a3), "r"(b0), "r"(b1))

__device__ __forceinline__ float sigf(float x) { return 1.f / (1.f + __expf(-x)); }
__device__ __forceinline__ float dot4(float4 a, float4 b) {
    return a.x*b.x + a.y*b.y + a.z*b.z + a.w*b.w;
}

// ---------------- prep: slots init + iter-1 q ----------------
__global__ void __launch_bounds__(256) prep(const float* __restrict__ Wq,
                     const float* __restrict__ noise,
                     const float* __restrict__ mu, const float* __restrict__ lsig,
                     const float* __restrict__ lng, const float* __restrict__ lnb) {
    __shared__ float sWqT[65 * 64];
    __shared__ float slot_s[256];
    int tid = threadIdx.x;
    int t = blockIdx.x * 256 + tid;

    {
        int d = t & 63;
        float val = __ldg(mu + d) + __expf(__ldg(lsig + d)) * noise[t];
        g_slots[t] = val;
        slot_s[tid] = val;
    }
    #pragma unroll
    for (int i = tid; i < 4096; i += 256) { int e = i >> 6, d = i & 63; sWqT[d*65 + e] = Wq[i]; }
    __syncthreads();

    if (tid < 128) {
        int w = tid >> 5, lane = tid & 31;
        float s0 = slot_s[w*64 + lane], s1 = slot_s[w*64 + 32 + lane];
        float s = s0 + s1, ss = s0*s0 + s1*s1;
        #pragma unroll
        for (int o = 16; o > 0; o >>= 1) { s += __shfl_xor_sync(~0u, s, o); ss += __shfl_xor_sync(~0u, ss, o); }
        float m = s * 0.015625f;
        float rstd = rsqrtf(ss * 0.015625f - m*m + 1e-5f);
        slot_s[w*64 + lane]      = (s0 - m)*rstd*__ldg(lng+lane)    + __ldg(lnb+lane);
        slot_s[w*64 + 32 + lane] = (s1 - m)*rstd*__ldg(lng+32+lane) + __ldg(lnb+32+lane);
    }
    __syncthreads();

    {
        int r = tid >> 6, e = tid & 63;
        float a = 0.f;
        #pragma unroll 16
        for (int d = 0; d < 64; d++) a += slot_s[r*64 + d] * sWqT[d*65 + e];
        int grow = blockIdx.x*4 + r;
        int b = grow >> 3, k = grow & 7;
        g_q[b*1024 + e*16 + k*2]     = a;
        g_q[b*1024 + e*16 + k*2 + 1] = a;
    }
}

// ---------------- fused input LN + K^T/V projection via bf16 tensor cores ----------------
// 64 rows/block, grid 4096. Warps 0-3: K, warps 4-7: V.
__global__ void __launch_bounds__(256) ln_kv(const float* __restrict__ inp,
        const float* __restrict__ Wk, const float* __restrict__ Wv,
        const float* __restrict__ lng, const float* __restrict__ lnb) {
    __shared__ __align__(16) __nv_bfloat16 xb[64 * 72];    // LN'd x, bf16
    __shared__ __align__(16) __nv_bfloat16 wb[128 * 72];   // Wk rows 0-63, Wv rows 64-127; reused as staging
    int t = threadIdx.x;
    int r0 = blockIdx.x * 64;

    // LN: 4 threads/row, 16 elems each
    {
        int row = t >> 2, j0 = (t & 3) * 16;
        const float4* xp = (const float4*)(inp + (size_t)(r0 + row)*64 + j0);
        float4 q0 = __ldg(xp), q1 = __ldg(xp+1), q2 = __ldg(xp+2), q3 = __ldg(xp+3);
        float s  = q0.x+q0.y+q0.z+q0.w + q1.x+q1.y+q1.z+q1.w
                 + q2.x+q2.y+q2.z+q2.w + q3.x+q3.y+q3.z+q3.w;
        float ss = dot4(q0,q0) + dot4(q1,q1) + dot4(q2,q2) + dot4(q3,q3);
        s  += __shfl_xor_sync(~0u, s, 1);  ss += __shfl_xor_sync(~0u, ss, 1);
        s  += __shfl_xor_sync(~0u, s, 2);  ss += __shfl_xor_sync(~0u, ss, 2);
        float mu = s * 0.015625f;
        float rstd = rsqrtf(ss * 0.015625f - mu*mu + 1e-5f);
        float vals[16] = {q0.x,q0.y,q0.z,q0.w, q1.x,q1.y,q1.z,q1.w,
                          q2.x,q2.y,q2.z,q2.w, q3.x,q3.y,q3.z,q3.w};
        #pragma unroll
        for (int i = 0; i < 16; i++) {
            int f = j0 + i;
            float o = (vals[i] - mu) * rstd * __ldg(lng+f) + __ldg(lnb+f);
            xb[row*72 + f] = __float2bfloat16(o);
        }
    }
    // weights -> bf16 smem (rows 0-63 Wk, 64-127 Wv)
    #pragma unroll
    for (int i = t; i < 8192; i += 256) {
        int rr = i >> 6, c = i & 63;
        float w = (i < 4096) ? __ldg(Wk + i) : __ldg(Wv + i - 4096);
        wb[rr*72 + c] = __float2bfloat16(w);
    }
    __syncthreads();

    // MMA: warp w -> m-tile (w&3), matrix (w>>2): 16 rows x 64 outs, 4 k-steps
    int lane = t & 31, w = t >> 5;
    int mt = w & 3, msel = w >> 2;
    int row_a = mt*16 + (lane >> 2);
    int colq = (lane & 3) * 2;
    float d[8][4];
    #pragma unroll
    for (int nt = 0; nt < 8; nt++)
        #pragma unroll
        for (int i = 0; i < 4; i++) d[nt][i] = 0.f;
    #pragma unroll
    for (int ks = 0; ks < 4; ks++) {
        int k0 = ks * 16;
        uint32 a0 = *(const uint32*)&xb[row_a*72     + k0 + colq];
        uint32 a1 = *(const uint32*)&xb[(row_a+8)*72 + k0 + colq];
        uint32 a2 = *(const uint32*)&xb[row_a*72     + k0 + colq + 8];
        uint32 a3 = *(const uint32*)&xb[(row_a+8)*72 + k0 + colq + 8];
        #pragma unroll
        for (int nt = 0; nt < 8; nt++) {
            int rowb = msel*64 + nt*8 + (lane >> 2);
            uint32 b0 = *(const uint32*)&wb[rowb*72 + k0 + colq];
            uint32 b1 = *(const uint32*)&wb[rowb*72 + k0 + colq + 8];
            MMA16816(d[nt], a0, a1, a2, a3, b0, b1);
        }
    }
    __syncthreads();   // weights no longer needed; reuse wb as staging

    // staging: stV [row 64][72] = wb; stK [d 64][72] = wb + 4608
    __nv_bfloat16* stV = wb;
    __nv_bfloat16* stK = wb + 4608;
    if (msel == 0) {   // K: store transposed [d][token]
        #pragma unroll
        for (int nt = 0; nt < 8; nt++) {
            int dd = nt*8 + colq;
            stK[dd*72 + row_a]         = __float2bfloat16(d[nt][0]);
            stK[(dd+1)*72 + row_a]     = __float2bfloat16(d[nt][1]);
            stK[dd*72 + row_a + 8]     = __float2bfloat16(d[nt][2]);
            stK[(dd+1)*72 + row_a + 8] = __float2bfloat16(d[nt][3]);
        }
    } else {           // V: natural [token][d]
        #pragma unroll
        for (int nt = 0; nt < 8; nt++) {
            int nn = nt*8 + colq;
            *(__nv_bfloat162*)&stV[row_a*72 + nn]     = __floats2bfloat162_rn(d[nt][0], d[nt][1]);
            *(__nv_bfloat162*)&stV[(row_a+8)*72 + nn] = __floats2bfloat162_rn(d[nt][2], d[nt][3]);
        }
    }
    __syncthreads();

    // global stores (coalesced bf162)
    int b = r0 >> 12, nn0 = r0 & 4095;
    #pragma unroll
    for (int i = t; i < 2048; i += 256) {
        int row = i >> 5, dp = i & 31;
        __nv_bfloat162 vv = *(const __nv_bfloat162*)&stV[row*72 + 2*dp];
        ((__nv_bfloat162*)g_v)[(size_t)(r0 + row)*32 + dp] = vv;
        __nv_bfloat162 kk = *(const __nv_bfloat162*)&stK[row*72 + 2*dp];   // row = d here
        ((__nv_bfloat162*)g_kT)[((size_t)b*64 + row)*2048 + (nn0 >> 1) + dp] = kk;
    }
}

// ---------------- attention: bf16 k/v, FMA2, LDS.128 update reads ----------------
__global__ void __launch_bounds__(256) attn_kernel() {
    __shared__ __align__(16) float qst[1024];     // [e][16]: duplicated q pairs
    __shared__ __align__(16) float attn2[8192];   // [j][n][2] duplicated attn; later red[8][512]
    __shared__ float sred[64];
    int t = threadIdx.x, b = blockIdx.y, n0 = blockIdx.x * 512;

    ((float4*)qst)[t] = ((const float4*)(g_q + b*1024))[t];
    __syncthreads();

    float sacc[8];
    {
        const __nv_bfloat162* kp = (const __nv_bfloat162*)g_kT + (size_t)b*131072 + (n0>>1) + t;
        ull l2[8];
        #pragma unroll
        for (int j = 0; j < 8; j++) l2[j] = 0ull;
        #pragma unroll 8
        for (int d = 0; d < 64; d++) {
            float2 kf = __bfloat1622float2(kp[d*2048]);
            ull kv; PACK2(kv, kf.x, kf.y);
            const ulonglong2* qp = (const ulonglong2*)&qst[d*16];
            ulonglong2 q01 = qp[0], q23 = qp[1];
            FMA2(l2[0], q01.x, kv); FMA2(l2[1], q01.y, kv);
            FMA2(l2[2], q23.x, kv); FMA2(l2[3], q23.y, kv);
            ulonglong2 q45 = qp[2], q67 = qp[3];
            FMA2(l2[4], q45.x, kv); FMA2(l2[5], q45.y, kv);
            FMA2(l2[6], q67.x, kv); FMA2(l2[7], q67.y, kv);
        }
        float l0[8], l1[8];
        #pragma unroll
        for (int j = 0; j < 8; j++) {
            float2 f = *reinterpret_cast<float2*>(&l2[j]);
            l0[j] = f.x; l1[j] = f.y;
        }
        float m0 = l0[0], m1 = l1[0];
        #pragma unroll
        for (int j = 1; j < 8; j++) { m0 = fmaxf(m0, l0[j]); m1 = fmaxf(m1, l1[j]); }
        float s0 = 0.f, s1 = 0.f, e0[8], e1[8];
        #pragma unroll
        for (int j = 0; j < 8; j++) {
            e0[j] = __expf((l0[j] - m0) * 0.125f); s0 += e0[j];
            e1[j] = __expf((l1[j] - m1) * 0.125f); s1 += e1[j];
        }
        float i0 = 1.0f / s0, i1 = 1.0f / s1;
        #pragma unroll
        for (int j = 0; j < 8; j++) {
            float a0 = e0[j]*i0 + 1e-8f;
            float a1 = e1[j]*i1 + 1e-8f;
            sacc[j] = a0 + a1;
            *(float4*)&attn2[(j*512 + 2*t)*2] = make_float4(a0, a0, a1, a1);
        }
    }
    #pragma unroll
    for (int j = 0; j < 8; j++) {
        float v = sacc[j];
        #pragma unroll
        for (int o = 16; o > 0; o >>= 1) v += __shfl_xor_sync(~0u, v, o);
        if ((t & 31) == 0) sred[(t>>5)*8 + j] = v;
    }
    __syncthreads();
    if (t < 8) {
        float v = 0.f;
        #pragma unroll
        for (int w = 0; w < 8; w++) v += sred[w*8 + t];
        g_Sp[blockIdx.x*512 + b*8 + t] = v;
    }

    int d2 = t & 31, grp = t >> 5;
    ull acc2[8];
    #pragma unroll
    for (int j = 0; j < 8; j++) acc2[j] = 0ull;
    const __nv_bfloat162* vp = (const __nv_bfloat162*)g_v + ((size_t)b*4096 + n0)*32 + d2;
    int nbeg = grp * 64;
    #pragma unroll 2
    for (int n = nbeg; n < nbeg + 64; n += 2) {
        float2 vf0 = __bfloat1622float2(vp[(size_t)n*32]);
        float2 vf1 = __bfloat1622float2(vp[(size_t)(n+1)*32]);
        ull v0; PACK2(v0, vf0.x, vf0.y);
        ull v1; PACK2(v1, vf1.x, vf1.y);
        #pragma unroll
        for (int j = 0; j < 8; j++) {
            ulonglong2 ap = *(const ulonglong2*)&attn2[(j*512 + n)*2];
            FMA2(acc2[j], ap.x, v0);
            FMA2(acc2[j], ap.y, v1);
        }
    }
    __syncthreads();
    float* red = attn2;
    #pragma unroll
    for (int j = 0; j < 8; j++) {
        float2 r = *reinterpret_cast<float2*>(&acc2[j]);
        *(float2*)&red[grp*512 + j*64 + d2*2] = r;
    }
    __syncthreads();
    #pragma unroll
    for (int rep = 0; rep < 2; rep++) {
        int idx = rep*256 + t;
        float v = 0.f;
        #pragma unroll
        for (int g = 0; g < 8; g++) v += red[g*512 + idx];
        g_Up[((size_t)blockIdx.x*64 + b)*512 + idx] = v;
    }
}

// ---------------- batched GRU + LN + MLP + residual + next-iter q ----------------
__global__ void __launch_bounds__(384) gru_mlp(
        const float* __restrict__ wih, const float* __restrict__ whh,
        const float* __restrict__ bih, const float* __restrict__ bhh,
        const float* __restrict__ w1, const float* __restrict__ b1,
        const float* __restrict__ w2, const float* __restrict__ b2,
        const float* __restrict__ Wq,
        const float* __restrict__ lng, const float* __restrict__ lnb,
        const float* __restrict__ lng2, const float* __restrict__ lnb2,
        float* __restrict__ out, int last) {
    __shared__ __align__(16) float u_s[256], h_s[256];
    __shared__ __align__(16) float gi_s[768], gh_s[768];
    __shared__ __align__(16) float hn_s[256], ln_s[256], h1_s[512];
    __shared__ __align__(16) float wbuf[6912];
    int t = threadIdx.x;
    int grow0 = blockIdx.x * 4;

    if (t < 256) {
        int r = t >> 6, d = t & 63;
        int grow = grow0 + r;
        float S = 0.f, U = 0.f;
        #pragma unroll
        for (int c = 0; c < 8; c++) {
            S += g_Sp[c*512 + grow];
            U += g_Up[c*32768 + grow*64 + d];
        }
        u_s[t] = U / S;
        h_s[t] = g_slots[grow*64 + d];
    }

    float accI0 = 0.f, accI1 = 0.f, accH0 = 0.f, accH1 = 0.f;
    int j = (t < 192) ? t : (t - 192);
    int rp = (t < 192) ? 0 : 1;
    #pragma unroll
    for (int half = 0; half < 2; half++) {
        __syncthreads();
        #pragma unroll
        for (int i = t; i < 6144; i += 384) { int jj = i >> 5, c = i & 31; wbuf[jj*36 + c] = __ldg(&wih[jj*64 + half*32 + c]); }
        __syncthreads();
        {
            const float4* W  = (const float4*)wbuf + j*9;
            const float4* X0 = (const float4*)(u_s + rp*128) + half*8;
            const float4* X1 = (const float4*)(u_s + rp*128 + 64) + half*8;
            #pragma unroll
            for (int i = 0; i < 8; i++) { float4 w = W[i]; accI0 += dot4(X0[i], w); accI1 += dot4(X1[i], w); }
        }
        __syncthreads();
        #pragma unroll
        for (int i = t; i < 6144; i += 384) { int jj = i >> 5, c = i & 31; wbuf[jj*36 + c] = __ldg(&whh[jj*64 + half*32 + c]); }
        __syncthreads();
        {
            const float4* W  = (const float4*)wbuf + j*9;
            const float4* X0 = (const float4*)(h_s + rp*128) + half*8;
            const float4* X1 = (const float4*)(h_s + rp*128 + 64) + half*8;
            #pragma unroll
            for (int i = 0; i < 8; i++) { float4 w = W[i]; accH0 += dot4(X0[i], w); accH1 += dot4(X1[i], w); }
        }
    }
    {
        float bi = __ldg(bih + j), bh = __ldg(bhh + j);
        int r0 = rp*2;
        gi_s[r0*192 + j]     = accI0 + bi;
        gi_s[(r0+1)*192 + j] = accI1 + bi;
        gh_s[r0*192 + j]     = accH0 + bh;
        gh_s[(r0+1)*192 + j] = accH1 + bh;
    }
    __syncthreads();

    if (t < 256) {
        int r = t >> 6, d = t & 63;
        float rr = sigf(gi_s[r*192 + d]       + gh_s[r*192 + d]);
        float z  = sigf(gi_s[r*192 + 64 + d]  + gh_s[r*192 + 64 + d]);
        float n  = tanhf(gi_s[r*192 + 128 + d] + rr * gh_s[r*192 + 128 + d]);
        hn_s[t] = (1.f - z)*n + z*h_s[t];
    }
    __syncthreads();

    if (t < 128) {
        int r = t >> 5, lane = t & 31;
        float x0 = hn_s[r*64 + lane], x1 = hn_s[r*64 + 32 + lane];
        float s = x0 + x1, ss = x0*x0 + x1*x1;
        #pragma unroll
        for (int o = 16; o > 0; o >>= 1) { s += __shfl_xor_sync(~0u, s, o); ss += __shfl_xor_sync(~0u, ss, o); }
        float mu = s * 0.015625f;
        float rstd = rsqrtf(ss * 0.015625f - mu*mu + 1e-5f);
        ln_s[r*64 + lane]      = (x0 - mu)*rstd*__ldg(lng+lane)    + __ldg(lnb+lane);
        ln_s[r*64 + 32 + lane] = (x1 - mu)*rstd*__ldg(lng+32+lane) + __ldg(lnb+32+lane);
    }

    float e0 = 0.f, e1 = 0.f, e2 = 0.f, e3 = 0.f;
    #pragma unroll
    for (int half = 0; half < 2; half++) {
        __syncthreads();
        #pragma unroll
        for (int i = t; i < 4096; i += 384) { int jj = i >> 5, c = i & 31; wbuf[jj*36 + c] = __ldg(&w1[jj*64 + half*32 + c]); }
        __syncthreads();
        if (t < 128) {
            const float4* W  = (const float4*)wbuf + t*9;
            const float4* X0 = (const float4*)(ln_s)       + half*8;
            const float4* X1 = (const float4*)(ln_s + 64)  + half*8;
            const float4* X2 = (const float4*)(ln_s + 128) + half*8;
            const float4* X3 = (const float4*)(ln_s + 192) + half*8;
            #pragma unroll
            for (int i = 0; i < 8; i++) {
                float4 w = W[i];
                e0 += dot4(X0[i], w); e1 += dot4(X1[i], w);
                e2 += dot4(X2[i], w); e3 += dot4(X3[i], w);
            }
        }
    }
    if (t < 128) {
        float bias = __ldg(b1 + t);
        h1_s[t]       = fmaxf(e0 + bias, 0.f);
        h1_s[128 + t] = fmaxf(e1 + bias, 0.f);
        h1_s[256 + t] = fmaxf(e2 + bias, 0.f);
        h1_s[384 + t] = fmaxf(e3 + bias, 0.f);
    }

    float facc = 0.f;
    int fr = (t >> 6) & 3, fo = t & 63;
    #pragma unroll
    for (int half = 0; half < 2; half++) {
        __syncthreads();
        #pragma unroll
        for (int i = t; i < 4096; i += 384) { int jj = i >> 6, c = i & 63; wbuf[jj*68 + c] = __ldg(&w2[jj*128 + half*64 + c]); }
        __syncthreads();
        if (t < 256) {
            const float4* W = (const float4*)wbuf + fo*17;
            const float4* H = (const float4*)(h1_s + fr*128 + half*64);
            #pragma unroll
            for (int i = 0; i < 16; i++) facc += dot4(H[i], W[i]);
        }
    }
    if (t < 256) {
        float a = facc + __ldg(b2 + fo);
        float res = hn_s[fr*64 + fo] + a;
        int grow = grow0 + fr;
        g_slots[grow*64 + fo] = res;
        if (last) out[grow*64 + fo] = res;
        u_s[t] = res;
    }
    if (last) return;
    __syncthreads();

    #pragma unroll
    for (int i = t; i < 4096; i += 384) { int jj = i >> 6, c = i & 63; wbuf[jj*68 + c] = __ldg(&Wq[jj*64 + c]); }
    if (t < 128) {
        int r = t >> 5, lane = t & 31;
        float x0 = u_s[r*64 + lane], x1 = u_s[r*64 + 32 + lane];
        float s = x0 + x1, ss = x0*x0 + x1*x1;
        #pragma unroll
        for (int o = 16; o > 0; o >>= 1) { s += __shfl_xor_sync(~0u, s, o); ss += __shfl_xor_sync(~0u, ss, o); }
        float mu = s * 0.015625f;
        float rstd = rsqrtf(ss * 0.015625f - mu*mu + 1e-5f);
        ln_s[r*64 + lane]      = (x0 - mu)*rstd*__ldg(lng2+lane)    + __ldg(lnb2+lane);
        ln_s[r*64 + 32 + lane] = (x1 - mu)*rstd*__ldg(lng2+32+lane) + __ldg(lnb2+32+lane);
    }
    __syncthreads();
    if (t < 256) {
        int r = t >> 6, e = t & 63;
        const float4* W = (const float4*)wbuf + e*17;
        const float4* X = (const float4*)(ln_s + r*64);
        float a = 0.f;
        #pragma unroll
        for (int i = 0; i < 16; i++) a += dot4(X[i], W[i]);
        int grow = grow0 + r;
        int b = grow >> 3, k = grow & 7;
        g_q[b*1024 + e*16 + k*2]     = a;
        g_q[b*1024 + e*16 + k*2 + 1] = a;
    }
}

extern "C" void kernel_launch(void* const* d_in, const int* in_sizes, int n_in,
                              void* d_out, int out_size) {
    const float* inputs = (const float*)d_in[0];
    const float* noise  = (const float*)d_in[1];
    const float* mu     = (const float*)d_in[2];
    const float* lsig   = (const float*)d_in[3];
    const float* Wq     = (const float*)d_in[4];
    const float* Wk     = (const float*)d_in[5];
    const float* Wv     = (const float*)d_in[6];
    const float* wih    = (const float*)d_in[7];
    const float* whh    = (const float*)d_in[8];
    const float* bih    = (const float*)d_in[9];
    const float* bhh    = (const float*)d_in[10];
    const float* w1     = (const float*)d_in[11];
    const float* b1     = (const float*)d_in[12];
    const float* w2     = (const float*)d_in[13];
    const float* b2     = (const float*)d_in[14];
    const float* ln_in_g   = (const float*)d_in[15];
    const float* ln_in_b   = (const float*)d_in[16];
    const float* ln_sl_g   = (const float*)d_in[17];
    const float* ln_sl_b   = (const float*)d_in[18];
    const float* ln_mlp_g  = (const float*)d_in[19];
    const float* ln_mlp_b  = (const float*)d_in[20];
    float* out = (float*)d_out;

    prep<<<128, 256>>>(Wq, noise, mu, lsig, ln_sl_g, ln_sl_b);
    ln_kv<<<4096, 256>>>(inputs, Wk, Wv, ln_in_g, ln_in_b);
    for (int it = 0; it < 3; it++) {
        attn_kernel<<<dim3(8, 64), 256>>>();
        gru_mlp<<<128, 384>>>(wih, whh, bih, bhh, w1, b1, w2, b2, Wq,
                              ln_mlp_g, ln_mlp_b, ln_sl_g, ln_sl_b, out, it == 2);
    }
}

// round 13
// speedup vs baseline: 3.3907x; 1.0709x over previous
#include <cuda_runtime.h>
#include <cuda_bf16.h>

typedef unsigned long long ull;
typedef unsigned int uint32;

// ---------------- device scratch ----------------
__device__ __nv_bfloat16 g_kT[16777216];  // [b][d][n] transposed K (bf16)
__device__ __nv_bfloat16 g_v [16777216];  // [b][n][d] (bf16)
__device__ float g_slots[32768];   // [b][k][d]
__device__ float g_q[32768];       // [b][e][8] natural transposed q
__device__ float g_Up[262144];     // [chunk(8)][b][k][d]
__device__ float g_Sp[4096];       // [chunk(8)][b*8+k]

#define FMA2(acc, a, b) asm("fma.rn.f32x2 %0, %1, %2, %0;" : "+l"(acc) : "l"(a), "l"(b))
#define PACK2(dst, x, y) asm("mov.b64 %0, {%1, %2};" : "=l"(dst) : "f"(x), "f"(y))

#define MMA16816(d, a0, a1, a2, a3, b0, b1) \
    asm volatile("mma.sync.aligned.m16n8k16.row.col.f32.bf16.bf16.f32 " \
        "{%0,%1,%2,%3}, {%4,%5,%6,%7}, {%8,%9}, {%0,%1,%2,%3};" \
        : "+f"(d[0]), "+f"(d[1]), "+f"(d[2]), "+f"(d[3]) \
        : "r"(a0), "r"(a1), "r"(a2), "r"(a3), "r"(b0), "r"(b1))

__device__ __forceinline__ float sigf(float x) { return 1.f / (1.f + __expf(-x)); }
__device__ __forceinline__ float dot4(float4 a, float4 b) {
    return a.x*b.x + a.y*b.y + a.z*b.z + a.w*b.w;
}

// ---------------- prep: slots init + iter-1 q ----------------
__global__ void __launch_bounds__(256) prep(const float* __restrict__ Wq,
                     const float* __restrict__ noise,
                     const float* __restrict__ mu, const float* __restrict__ lsig,
                     const float* __restrict__ lng, const float* __restrict__ lnb) {
    __shared__ float sWqT[65 * 64];
    __shared__ float slot_s[256];
    int tid = threadIdx.x;
    int t = blockIdx.x * 256 + tid;

    {
        int d = t & 63;
        float val = __ldg(mu + d) + __expf(__ldg(lsig + d)) * noise[t];
        g_slots[t] = val;
        slot_s[tid] = val;
    }
    #pragma unroll
    for (int i = tid; i < 4096; i += 256) { int e = i >> 6, d = i & 63; sWqT[d*65 + e] = Wq[i]; }
    __syncthreads();

    if (tid < 128) {
        int w = tid >> 5, lane = tid & 31;
        float s0 = slot_s[w*64 + lane], s1 = slot_s[w*64 + 32 + lane];
        float s = s0 + s1, ss = s0*s0 + s1*s1;
        #pragma unroll
        for (int o = 16; o > 0; o >>= 1) { s += __shfl_xor_sync(~0u, s, o); ss += __shfl_xor_sync(~0u, ss, o); }
        float m = s * 0.015625f;
        float rstd = rsqrtf(ss * 0.015625f - m*m + 1e-5f);
        slot_s[w*64 + lane]      = (s0 - m)*rstd*__ldg(lng+lane)    + __ldg(lnb+lane);
        slot_s[w*64 + 32 + lane] = (s1 - m)*rstd*__ldg(lng+32+lane) + __ldg(lnb+32+lane);
    }
    __syncthreads();

    {
        int r = tid >> 6, e = tid & 63;
        float a = 0.f;
        #pragma unroll 16
        for (int d = 0; d < 64; d++) a += slot_s[r*64 + d] * sWqT[d*65 + e];
        int grow = blockIdx.x*4 + r;
        int b = grow >> 3, k = grow & 7;
        g_q[b*512 + e*8 + k] = a;
    }
}

// ---------------- fused input LN + K^T/V projection via bf16 tensor cores ----------------
__global__ void __launch_bounds__(256) ln_kv(const float* __restrict__ inp,
        const float* __restrict__ Wk, const float* __restrict__ Wv,
        const float* __restrict__ lng, const float* __restrict__ lnb) {
    __shared__ __align__(16) __nv_bfloat16 xb[64 * 72];
    __shared__ __align__(16) __nv_bfloat16 wb[128 * 72];
    int t = threadIdx.x;
    int r0 = blockIdx.x * 64;

    {
        int row = t >> 2, j0 = (t & 3) * 16;
        const float4* xp = (const float4*)(inp + (size_t)(r0 + row)*64 + j0);
        float4 q0 = __ldg(xp), q1 = __ldg(xp+1), q2 = __ldg(xp+2), q3 = __ldg(xp+3);
        float s  = q0.x+q0.y+q0.z+q0.w + q1.x+q1.y+q1.z+q1.w
                 + q2.x+q2.y+q2.z+q2.w + q3.x+q3.y+q3.z+q3.w;
        float ss = dot4(q0,q0) + dot4(q1,q1) + dot4(q2,q2) + dot4(q3,q3);
        s  += __shfl_xor_sync(~0u, s, 1);  ss += __shfl_xor_sync(~0u, ss, 1);
        s  += __shfl_xor_sync(~0u, s, 2);  ss += __shfl_xor_sync(~0u, ss, 2);
        float mu = s * 0.015625f;
        float rstd = rsqrtf(ss * 0.015625f - mu*mu + 1e-5f);
        float vals[16] = {q0.x,q0.y,q0.z,q0.w, q1.x,q1.y,q1.z,q1.w,
                          q2.x,q2.y,q2.z,q2.w, q3.x,q3.y,q3.z,q3.w};
        #pragma unroll
        for (int i = 0; i < 16; i++) {
            int f = j0 + i;
            float o = (vals[i] - mu) * rstd * __ldg(lng+f) + __ldg(lnb+f);
            xb[row*72 + f] = __float2bfloat16(o);
        }
    }
    #pragma unroll
    for (int i = t; i < 8192; i += 256) {
        int rr = i >> 6, c = i & 63;
        float w = (i < 4096) ? __ldg(Wk + i) : __ldg(Wv + i - 4096);
        wb[rr*72 + c] = __float2bfloat16(w);
    }
    __syncthreads();

    int lane = t & 31, w = t >> 5;
    int mt = w & 3, msel = w >> 2;
    int row_a = mt*16 + (lane >> 2);
    int colq = (lane & 3) * 2;
    float d[8][4];
    #pragma unroll
    for (int nt = 0; nt < 8; nt++)
        #pragma unroll
        for (int i = 0; i < 4; i++) d[nt][i] = 0.f;
    #pragma unroll
    for (int ks = 0; ks < 4; ks++) {
        int k0 = ks * 16;
        uint32 a0 = *(const uint32*)&xb[row_a*72     + k0 + colq];
        uint32 a1 = *(const uint32*)&xb[(row_a+8)*72 + k0 + colq];
        uint32 a2 = *(const uint32*)&xb[row_a*72     + k0 + colq + 8];
        uint32 a3 = *(const uint32*)&xb[(row_a+8)*72 + k0 + colq + 8];
        #pragma unroll
        for (int nt = 0; nt < 8; nt++) {
            int rowb = msel*64 + nt*8 + (lane >> 2);
            uint32 b0 = *(const uint32*)&wb[rowb*72 + k0 + colq];
            uint32 b1 = *(const uint32*)&wb[rowb*72 + k0 + colq + 8];
            MMA16816(d[nt], a0, a1, a2, a3, b0, b1);
        }
    }
    __syncthreads();

    __nv_bfloat16* stV = wb;
    __nv_bfloat16* stK = wb + 4608;
    if (msel == 0) {
        #pragma unroll
        for (int nt = 0; nt < 8; nt++) {
            int dd = nt*8 + colq;
            stK[dd*72 + row_a]         = __float2bfloat16(d[nt][0]);
            stK[(dd+1)*72 + row_a]     = __float2bfloat16(d[nt][1]);
            stK[dd*72 + row_a + 8]     = __float2bfloat16(d[nt][2]);
            stK[(dd+1)*72 + row_a + 8] = __float2bfloat16(d[nt][3]);
        }
    } else {
        #pragma unroll
        for (int nt = 0; nt < 8; nt++) {
            int nn = nt*8 + colq;
            *(__nv_bfloat162*)&stV[row_a*72 + nn]     = __floats2bfloat162_rn(d[nt][0], d[nt][1]);
            *(__nv_bfloat162*)&stV[(row_a+8)*72 + nn] = __floats2bfloat162_rn(d[nt][2], d[nt][3]);
        }
    }
    __syncthreads();

    int b = r0 >> 12, nn0 = r0 & 4095;
    #pragma unroll
    for (int i = t; i < 2048; i += 256) {
        int row = i >> 5, dp = i & 31;
        __nv_bfloat162 vv = *(const __nv_bfloat162*)&stV[row*72 + 2*dp];
        ((__nv_bfloat162*)g_v)[(size_t)(r0 + row)*32 + dp] = vv;
        __nv_bfloat162 kk = *(const __nv_bfloat162*)&stK[row*72 + 2*dp];
        ((__nv_bfloat162*)g_kT)[((size_t)b*64 + row)*2048 + (nn0 >> 1) + dp] = kk;
    }
}

// ---------------- attention: k/v duplicated in regs, natural q/attn smem reads ----------------
__global__ void __launch_bounds__(256) attn_kernel() {
    __shared__ __align__(16) float qst[512];      // [e][8] natural q
    __shared__ __align__(16) float attn_s[6144];  // [n][12] stride-12; reused as red[8][512]
    __shared__ float sred[64];
    int t = threadIdx.x, b = blockIdx.y, n0 = blockIdx.x * 512;

    ((float2*)qst)[t] = ((const float2*)(g_q + b*512))[t];
    __syncthreads();

    // logits + softmax: thread handles tokens (2t, 2t+1)
    float sacc[8];
    {
        const __nv_bfloat162* kp = (const __nv_bfloat162*)g_kT + (size_t)b*131072 + (n0>>1) + t;
        ull lp0[4], lp1[4];
        #pragma unroll
        for (int i = 0; i < 4; i++) { lp0[i] = 0ull; lp1[i] = 0ull; }
        #pragma unroll 8
        for (int d = 0; d < 64; d++) {
            float2 kf = __bfloat1622float2(kp[d*2048]);
            ull kv0; PACK2(kv0, kf.x, kf.x);
            ull kv1; PACK2(kv1, kf.y, kf.y);
            ulonglong2 qa = *(const ulonglong2*)&qst[d*8];      // (q0,q1),(q2,q3)
            ulonglong2 qb = *(const ulonglong2*)&qst[d*8 + 4];  // (q4,q5),(q6,q7)
            FMA2(lp0[0], qa.x, kv0); FMA2(lp0[1], qa.y, kv0);
            FMA2(lp0[2], qb.x, kv0); FMA2(lp0[3], qb.y, kv0);
            FMA2(lp1[0], qa.x, kv1); FMA2(lp1[1], qa.y, kv1);
            FMA2(lp1[2], qb.x, kv1); FMA2(lp1[3], qb.y, kv1);
        }
        float l0[8], l1[8];
        #pragma unroll
        for (int i = 0; i < 4; i++) {
            float2 f0 = *reinterpret_cast<float2*>(&lp0[i]);
            float2 f1 = *reinterpret_cast<float2*>(&lp1[i]);
            l0[2*i] = f0.x; l0[2*i+1] = f0.y;
            l1[2*i] = f1.x; l1[2*i+1] = f1.y;
        }
        float m0 = l0[0], m1 = l1[0];
        #pragma unroll
        for (int j = 1; j < 8; j++) { m0 = fmaxf(m0, l0[j]); m1 = fmaxf(m1, l1[j]); }
        float s0 = 0.f, s1 = 0.f, e0[8], e1[8];
        #pragma unroll
        for (int j = 0; j < 8; j++) {
            e0[j] = __expf((l0[j] - m0) * 0.125f); s0 += e0[j];
            e1[j] = __expf((l1[j] - m1) * 0.125f); s1 += e1[j];
        }
        float i0 = 1.0f / s0, i1 = 1.0f / s1;
        float a0[8], a1[8];
        #pragma unroll
        for (int j = 0; j < 8; j++) {
            a0[j] = e0[j]*i0 + 1e-8f;
            a1[j] = e1[j]*i1 + 1e-8f;
            sacc[j] = a0[j] + a1[j];
        }
        *(float4*)&attn_s[(2*t)*12]     = make_float4(a0[0], a0[1], a0[2], a0[3]);
        *(float4*)&attn_s[(2*t)*12 + 4] = make_float4(a0[4], a0[5], a0[6], a0[7]);
        *(float4*)&attn_s[(2*t+1)*12]     = make_float4(a1[0], a1[1], a1[2], a1[3]);
        *(float4*)&attn_s[(2*t+1)*12 + 4] = make_float4(a1[4], a1[5], a1[6], a1[7]);
    }
    // deterministic S reduce
    #pragma unroll
    for (int j = 0; j < 8; j++) {
        float v = sacc[j];
        #pragma unroll
        for (int o = 16; o > 0; o >>= 1) v += __shfl_xor_sync(~0u, v, o);
        if ((t & 31) == 0) sred[(t>>5)*8 + j] = v;
    }
    __syncthreads();
    if (t < 8) {
        float v = 0.f;
        #pragma unroll
        for (int w = 0; w < 8; w++) v += sred[w*8 + t];
        g_Sp[blockIdx.x*512 + b*8 + t] = v;
    }

    // update: v duplicated in regs, natural attn pair reads
    int d2 = t & 31, grp = t >> 5;
    ull ap0[4], ap1[4];   // ap0[i] = (U[2i][d0], U[2i+1][d0]); ap1 for d1
    #pragma unroll
    for (int i = 0; i < 4; i++) { ap0[i] = 0ull; ap1[i] = 0ull; }
    const __nv_bfloat162* vp = (const __nv_bfloat162*)g_v + ((size_t)b*4096 + n0)*32 + d2;
    int nbeg = grp * 64;
    #pragma unroll 4
    for (int n = nbeg; n < nbeg + 64; n++) {
        float2 vf = __bfloat1622float2(vp[(size_t)n*32]);
        ull vv0; PACK2(vv0, vf.x, vf.x);
        ull vv1; PACK2(vv1, vf.y, vf.y);
        ulonglong2 aa = *(const ulonglong2*)&attn_s[n*12];
        ulonglong2 ab = *(const ulonglong2*)&attn_s[n*12 + 4];
        FMA2(ap0[0], aa.x, vv0); FMA2(ap0[1], aa.y, vv0);
        FMA2(ap0[2], ab.x, vv0); FMA2(ap0[3], ab.y, vv0);
        FMA2(ap1[0], aa.x, vv1); FMA2(ap1[1], aa.y, vv1);
        FMA2(ap1[2], ab.x, vv1); FMA2(ap1[3], ab.y, vv1);
    }
    __syncthreads();                 // all attn_s reads done
    float* red = attn_s;             // [grp][j*64 + d], 4096 floats
    #pragma unroll
    for (int i = 0; i < 4; i++) {
        float2 u0 = *reinterpret_cast<float2*>(&ap0[i]);   // (U[2i][d0], U[2i+1][d0])
        float2 u1 = *reinterpret_cast<float2*>(&ap1[i]);
        *(float2*)&red[grp*512 + (2*i)*64   + 2*d2] = make_float2(u0.x, u1.x);
        *(float2*)&red[grp*512 + (2*i+1)*64 + 2*d2] = make_float2(u0.y, u1.y);
    }
    __syncthreads();
    #pragma unroll
    for (int rep = 0; rep < 2; rep++) {
        int idx = rep*256 + t;
        float v = 0.f;
        #pragma unroll
        for (int g = 0; g < 8; g++) v += red[g*512 + idx];
        g_Up[((size_t)blockIdx.x*64 + b)*512 + idx] = v;
    }
}

// ---------------- batched GRU + LN + MLP + residual + next-iter q ----------------
__global__ void __launch_bounds__(384) gru_mlp(
        const float* __restrict__ wih, const float* __restrict__ whh,
        const float* __restrict__ bih, const float* __restrict__ bhh,
        const float* __restrict__ w1, const float* __restrict__ b1,
        const float* __restrict__ w2, const float* __restrict__ b2,
        const float* __restrict__ Wq,
        const float* __restrict__ lng, const float* __restrict__ lnb,
        const float* __restrict__ lng2, const float* __restrict__ lnb2,
        float* __restrict__ out, int last) {
    __shared__ __align__(16) float u_s[256], h_s[256];
    __shared__ __align__(16) float gi_s[768], gh_s[768];
    __shared__ __align__(16) float hn_s[256], ln_s[256], h1_s[512];
    __shared__ __align__(16) float wbuf[6912];
    int t = threadIdx.x;
    int grow0 = blockIdx.x * 4;

    if (t < 256) {
        int r = t >> 6, d = t & 63;
        int grow = grow0 + r;
        float S = 0.f, U = 0.f;
        #pragma unroll
        for (int c = 0; c < 8; c++) {
            S += g_Sp[c*512 + grow];
            U += g_Up[c*32768 + grow*64 + d];
        }
        u_s[t] = U / S;
        h_s[t] = g_slots[grow*64 + d];
    }

    float accI0 = 0.f, accI1 = 0.f, accH0 = 0.f, accH1 = 0.f;
    int j = (t < 192) ? t : (t - 192);
    int rp = (t < 192) ? 0 : 1;
    #pragma unroll
    for (int half = 0; half < 2; half++) {
        __syncthreads();
        #pragma unroll
        for (int i = t; i < 6144; i += 384) { int jj = i >> 5, c = i & 31; wbuf[jj*36 + c] = __ldg(&wih[jj*64 + half*32 + c]); }
        __syncthreads();
        {
            const float4* W  = (const float4*)wbuf + j*9;
            const float4* X0 = (const float4*)(u_s + rp*128) + half*8;
            const float4* X1 = (const float4*)(u_s + rp*128 + 64) + half*8;
            #pragma unroll
            for (int i = 0; i < 8; i++) { float4 w = W[i]; accI0 += dot4(X0[i], w); accI1 += dot4(X1[i], w); }
        }
        __syncthreads();
        #pragma unroll
        for (int i = t; i < 6144; i += 384) { int jj = i >> 5, c = i & 31; wbuf[jj*36 + c] = __ldg(&whh[jj*64 + half*32 + c]); }
        __syncthreads();
        {
            const float4* W  = (const float4*)wbuf + j*9;
            const float4* X0 = (const float4*)(h_s + rp*128) + half*8;
            const float4* X1 = (const float4*)(h_s + rp*128 + 64) + half*8;
            #pragma unroll
            for (int i = 0; i < 8; i++) { float4 w = W[i]; accH0 += dot4(X0[i], w); accH1 += dot4(X1[i], w); }
        }
    }
    {
        float bi = __ldg(bih + j), bh = __ldg(bhh + j);
        int r0 = rp*2;
        gi_s[r0*192 + j]     = accI0 + bi;
        gi_s[(r0+1)*192 + j] = accI1 + bi;
        gh_s[r0*192 + j]     = accH0 + bh;
        gh_s[(r0+1)*192 + j] = accH1 + bh;
    }
    __syncthreads();

    if (t < 256) {
        int r = t >> 6, d = t & 63;
        float rr = sigf(gi_s[r*192 + d]       + gh_s[r*192 + d]);
        float z  = sigf(gi_s[r*192 + 64 + d]  + gh_s[r*192 + 64 + d]);
        float n  = tanhf(gi_s[r*192 + 128 + d] + rr * gh_s[r*192 + 128 + d]);
        hn_s[t] = (1.f - z)*n + z*h_s[t];
    }
    __syncthreads();

    if (t < 128) {
        int r = t >> 5, lane = t & 31;
        float x0 = hn_s[r*64 + lane], x1 = hn_s[r*64 + 32 + lane];
        float s = x0 + x1, ss = x0*x0 + x1*x1;
        #pragma unroll
        for (int o = 16; o > 0; o >>= 1) { s += __shfl_xor_sync(~0u, s, o); ss += __shfl_xor_sync(~0u, ss, o); }
        float mu = s * 0.015625f;
        float rstd = rsqrtf(ss * 0.015625f - mu*mu + 1e-5f);
        ln_s[r*64 + lane]      = (x0 - mu)*rstd*__ldg(lng+lane)    + __ldg(lnb+lane);
        ln_s[r*64 + 32 + lane] = (x1 - mu)*rstd*__ldg(lng+32+lane) + __ldg(lnb+32+lane);
    }

    float e0 = 0.f, e1 = 0.f, e2 = 0.f, e3 = 0.f;
    #pragma unroll
    for (int half = 0; half < 2; half++) {
        __syncthreads();
        #pragma unroll
        for (int i = t; i < 4096; i += 384) { int jj = i >> 5, c = i & 31; wbuf[jj*36 + c] = __ldg(&w1[jj*64 + half*32 + c]); }
        __syncthreads();
        if (t < 128) {
            const float4* W  = (const float4*)wbuf + t*9;
            const float4* X0 = (const float4*)(ln_s)       + half*8;
            const float4* X1 = (const float4*)(ln_s + 64)  + half*8;
            const float4* X2 = (const float4*)(ln_s + 128) + half*8;
            const float4* X3 = (const float4*)(ln_s + 192) + half*8;
            #pragma unroll
            for (int i = 0; i < 8; i++) {
                float4 w = W[i];
                e0 += dot4(X0[i], w); e1 += dot4(X1[i], w);
                e2 += dot4(X2[i], w); e3 += dot4(X3[i], w);
            }
        }
    }
    if (t < 128) {
        float bias = __ldg(b1 + t);
        h1_s[t]       = fmaxf(e0 + bias, 0.f);
        h1_s[128 + t] = fmaxf(e1 + bias, 0.f);
        h1_s[256 + t] = fmaxf(e2 + bias, 0.f);
        h1_s[384 + t] = fmaxf(e3 + bias, 0.f);
    }

    float facc = 0.f;
    int fr = (t >> 6) & 3, fo = t & 63;
    #pragma unroll
    for (int half = 0; half < 2; half++) {
        __syncthreads();
        #pragma unroll
        for (int i = t; i < 4096; i += 384) { int jj = i >> 6, c = i & 63; wbuf[jj*68 + c] = __ldg(&w2[jj*128 + half*64 + c]); }
        __syncthreads();
        if (t < 256) {
            const float4* W = (const float4*)wbuf + fo*17;
            const float4* H = (const float4*)(h1_s + fr*128 + half*64);
            #pragma unroll
            for (int i = 0; i < 16; i++) facc += dot4(H[i], W[i]);
        }
    }
    if (t < 256) {
        float a = facc + __ldg(b2 + fo);
        float res = hn_s[fr*64 + fo] + a;
        int grow = grow0 + fr;
        g_slots[grow*64 + fo] = res;
        if (last) out[grow*64 + fo] = res;
        u_s[t] = res;
    }
    if (last) return;
    __syncthreads();

    #pragma unroll
    for (int i = t; i < 4096; i += 384) { int jj = i >> 6, c = i & 63; wbuf[jj*68 + c] = __ldg(&Wq[jj*64 + c]); }
    if (t < 128) {
        int r = t >> 5, lane = t & 31;
        float x0 = u_s[r*64 + lane], x1 = u_s[r*64 + 32 + lane];
        float s = x0 + x1, ss = x0*x0 + x1*x1;
        #pragma unroll
        for (int o = 16; o > 0; o >>= 1) { s += __shfl_xor_sync(~0u, s, o); ss += __shfl_xor_sync(~0u, ss, o); }
        float mu = s * 0.015625f;
        float rstd = rsqrtf(ss * 0.015625f - mu*mu + 1e-5f);
        ln_s[r*64 + lane]      = (x0 - mu)*rstd*__ldg(lng2+lane)    + __ldg(lnb2+lane);
        ln_s[r*64 + 32 + lane] = (x1 - mu)*rstd*__ldg(lng2+32+lane) + __ldg(lnb2+32+lane);
    }
    __syncthreads();
    if (t < 256) {
        int r = t >> 6, e = t & 63;
        const float4* W = (const float4*)wbuf + e*17;
        const float4* X = (const float4*)(ln_s + r*64);
        float a = 0.f;
        #pragma unroll
        for (int i = 0; i < 16; i++) a += dot4(X[i], W[i]);
        int grow = grow0 + r;
        int b = grow >> 3, k = grow & 7;
        g_q[b*512 + e*8 + k] = a;
    }
}

extern "C" void kernel_launch(void* const* d_in, const int* in_sizes, int n_in,
                              void* d_out, int out_size) {
    const float* inputs = (const float*)d_in[0];
    const float* noise  = (const float*)d_in[1];
    const float* mu     = (const float*)d_in[2];
    const float* lsig   = (const float*)d_in[3];
    const float* Wq     = (const float*)d_in[4];
    const float* Wk     = (const float*)d_in[5];
    const float* Wv     = (const float*)d_in[6];
    const float* wih    = (const float*)d_in[7];
    const float* whh    = (const float*)d_in[8];
    const float* bih    = (const float*)d_in[9];
    const float* bhh    = (const float*)d_in[10];
    const float* w1     = (const float*)d_in[11];
    const float* b1     = (const float*)d_in[12];
    const float* w2     = (const float*)d_in[13];
    const float* b2     = (const float*)d_in[14];
    const float* ln_in_g   = (const float*)d_in[15];
    const float* ln_in_b   = (const float*)d_in[16];
    const float* ln_sl_g   = (const float*)d_in[17];
    const float* ln_sl_b   = (const float*)d_in[18];
    const float* ln_mlp_g  = (const float*)d_in[19];
    const float* ln_mlp_b  = (const float*)d_in[20];
    float* out = (float*)d_out;

    prep<<<128, 256>>>(Wq, noise, mu, lsig, ln_sl_g, ln_sl_b);
    ln_kv<<<4096, 256>>>(inputs, Wk, Wv, ln_in_g, ln_in_b);
    for (int it = 0; it < 3; it++) {
        attn_kernel<<<dim3(8, 64), 256>>>();
        gru_mlp<<<128, 384>>>(wih, whh, bih, bhh, w1, b1, w2, b2, Wq,
                              ln_mlp_g, ln_mlp_b, ln_sl_g, ln_sl_b, out, it == 2);
    }
}

// round 14
// speedup vs baseline: 3.4036x; 1.0038x over previous
#include <cuda_runtime.h>
#include <cuda_bf16.h>

typedef unsigned long long ull;
typedef unsigned int uint32;

// ---------------- device scratch ----------------
__device__ __nv_bfloat16 g_kT[16777216];  // [b][d][n] transposed K (bf16)
__device__ __nv_bfloat16 g_v [16777216];  // [b][n][d] (bf16)
__device__ float g_slots[32768];   // [b][k][d]
__device__ float g_q[32768];       // [b][e][8] natural transposed q
__device__ float g_Up[262144];     // [chunk(8)][b][k][d]
__device__ float g_Sp[4096];       // [chunk(8)][b*8+k]

#define FMA2(acc, a, b) asm("fma.rn.f32x2 %0, %1, %2, %0;" : "+l"(acc) : "l"(a), "l"(b))
#define PACK2(dst, x, y) asm("mov.b64 %0, {%1, %2};" : "=l"(dst) : "f"(x), "f"(y))

#define MMA16816(d, a0, a1, a2, a3, b0, b1) \
    asm volatile("mma.sync.aligned.m16n8k16.row.col.f32.bf16.bf16.f32 " \
        "{%0,%1,%2,%3}, {%4,%5,%6,%7}, {%8,%9}, {%0,%1,%2,%3};" \
        : "+f"(d[0]), "+f"(d[1]), "+f"(d[2]), "+f"(d[3]) \
        : "r"(a0), "r"(a1), "r"(a2), "r"(a3), "r"(b0), "r"(b1))

__device__ __forceinline__ float sigf(float x) { return 1.f / (1.f + __expf(-x)); }
__device__ __forceinline__ float dot4(float4 a, float4 b) {
    return a.x*b.x + a.y*b.y + a.z*b.z + a.w*b.w;
}

// ---------------- prep: slots init + iter-1 q ----------------
__global__ void __launch_bounds__(256) prep(const float* __restrict__ Wq,
                     const float* __restrict__ noise,
                     const float* __restrict__ mu, const float* __restrict__ lsig,
                     const float* __restrict__ lng, const float* __restrict__ lnb) {
    __shared__ float sWqT[65 * 64];
    __shared__ float slot_s[256];
    int tid = threadIdx.x;
    int t = blockIdx.x * 256 + tid;

    {
        int d = t & 63;
        float val = __ldg(mu + d) + __expf(__ldg(lsig + d)) * noise[t];
        g_slots[t] = val;
        slot_s[tid] = val;
    }
    #pragma unroll
    for (int i = tid; i < 4096; i += 256) { int e = i >> 6, d = i & 63; sWqT[d*65 + e] = Wq[i]; }
    __syncthreads();

    if (tid < 128) {
        int w = tid >> 5, lane = tid & 31;
        float s0 = slot_s[w*64 + lane], s1 = slot_s[w*64 + 32 + lane];
        float s = s0 + s1, ss = s0*s0 + s1*s1;
        #pragma unroll
        for (int o = 16; o > 0; o >>= 1) { s += __shfl_xor_sync(~0u, s, o); ss += __shfl_xor_sync(~0u, ss, o); }
        float m = s * 0.015625f;
        float rstd = rsqrtf(ss * 0.015625f - m*m + 1e-5f);
        slot_s[w*64 + lane]      = (s0 - m)*rstd*__ldg(lng+lane)    + __ldg(lnb+lane);
        slot_s[w*64 + 32 + lane] = (s1 - m)*rstd*__ldg(lng+32+lane) + __ldg(lnb+32+lane);
    }
    __syncthreads();

    {
        int r = tid >> 6, e = tid & 63;
        float a = 0.f;
        #pragma unroll 16
        for (int d = 0; d < 64; d++) a += slot_s[r*64 + d] * sWqT[d*65 + e];
        int grow = blockIdx.x*4 + r;
        int b = grow >> 3, k = grow & 7;
        g_q[b*512 + e*8 + k] = a;
    }
}

// ---------------- fused input LN + K^T/V projection via bf16 tensor cores ----------------
__global__ void __launch_bounds__(256) ln_kv(const float* __restrict__ inp,
        const float* __restrict__ Wk, const float* __restrict__ Wv,
        const float* __restrict__ lng, const float* __restrict__ lnb) {
    __shared__ __align__(16) __nv_bfloat16 xb[64 * 72];
    __shared__ __align__(16) __nv_bfloat16 wb[128 * 72];
    int t = threadIdx.x;
    int r0 = blockIdx.x * 64;

    {
        int row = t >> 2, j0 = (t & 3) * 16;
        const float4* xp = (const float4*)(inp + (size_t)(r0 + row)*64 + j0);
        float4 q0 = __ldg(xp), q1 = __ldg(xp+1), q2 = __ldg(xp+2), q3 = __ldg(xp+3);
        float s  = q0.x+q0.y+q0.z+q0.w + q1.x+q1.y+q1.z+q1.w
                 + q2.x+q2.y+q2.z+q2.w + q3.x+q3.y+q3.z+q3.w;
        float ss = dot4(q0,q0) + dot4(q1,q1) + dot4(q2,q2) + dot4(q3,q3);
        s  += __shfl_xor_sync(~0u, s, 1);  ss += __shfl_xor_sync(~0u, ss, 1);
        s  += __shfl_xor_sync(~0u, s, 2);  ss += __shfl_xor_sync(~0u, ss, 2);
        float mu = s * 0.015625f;
        float rstd = rsqrtf(ss * 0.015625f - mu*mu + 1e-5f);
        float vals[16] = {q0.x,q0.y,q0.z,q0.w, q1.x,q1.y,q1.z,q1.w,
                          q2.x,q2.y,q2.z,q2.w, q3.x,q3.y,q3.z,q3.w};
        #pragma unroll
        for (int i = 0; i < 16; i++) {
            int f = j0 + i;
            float o = (vals[i] - mu) * rstd * __ldg(lng+f) + __ldg(lnb+f);
            xb[row*72 + f] = __float2bfloat16(o);
        }
    }
    #pragma unroll
    for (int i = t; i < 8192; i += 256) {
        int rr = i >> 6, c = i & 63;
        float w = (i < 4096) ? __ldg(Wk + i) : __ldg(Wv + i - 4096);
        wb[rr*72 + c] = __float2bfloat16(w);
    }
    __syncthreads();

    int lane = t & 31, w = t >> 5;
    int mt = w & 3, msel = w >> 2;
    int row_a = mt*16 + (lane >> 2);
    int colq = (lane & 3) * 2;
    float d[8][4];
    #pragma unroll
    for (int nt = 0; nt < 8; nt++)
        #pragma unroll
        for (int i = 0; i < 4; i++) d[nt][i] = 0.f;
    #pragma unroll
    for (int ks = 0; ks < 4; ks++) {
        int k0 = ks * 16;
        uint32 a0 = *(const uint32*)&xb[row_a*72     + k0 + colq];
        uint32 a1 = *(const uint32*)&xb[(row_a+8)*72 + k0 + colq];
        uint32 a2 = *(const uint32*)&xb[row_a*72     + k0 + colq + 8];
        uint32 a3 = *(const uint32*)&xb[(row_a+8)*72 + k0 + colq + 8];
        #pragma unroll
        for (int nt = 0; nt < 8; nt++) {
            int rowb = msel*64 + nt*8 + (lane >> 2);
            uint32 b0 = *(const uint32*)&wb[rowb*72 + k0 + colq];
            uint32 b1 = *(const uint32*)&wb[rowb*72 + k0 + colq + 8];
            MMA16816(d[nt], a0, a1, a2, a3, b0, b1);
        }
    }
    __syncthreads();

    __nv_bfloat16* stV = wb;
    __nv_bfloat16* stK = wb + 4608;
    if (msel == 0) {
        #pragma unroll
        for (int nt = 0; nt < 8; nt++) {
            int dd = nt*8 + colq;
            stK[dd*72 + row_a]         = __float2bfloat16(d[nt][0]);
            stK[(dd+1)*72 + row_a]     = __float2bfloat16(d[nt][1]);
            stK[dd*72 + row_a + 8]     = __float2bfloat16(d[nt][2]);
            stK[(dd+1)*72 + row_a + 8] = __float2bfloat16(d[nt][3]);
        }
    } else {
        #pragma unroll
        for (int nt = 0; nt < 8; nt++) {
            int nn = nt*8 + colq;
            *(__nv_bfloat162*)&stV[row_a*72 + nn]     = __floats2bfloat162_rn(d[nt][0], d[nt][1]);
            *(__nv_bfloat162*)&stV[(row_a+8)*72 + nn] = __floats2bfloat162_rn(d[nt][2], d[nt][3]);
        }
    }
    __syncthreads();

    int b = r0 >> 12, nn0 = r0 & 4095;
    #pragma unroll
    for (int i = t; i < 2048; i += 256) {
        int row = i >> 5, dp = i & 31;
        __nv_bfloat162 vv = *(const __nv_bfloat162*)&stV[row*72 + 2*dp];
        ((__nv_bfloat162*)g_v)[(size_t)(r0 + row)*32 + dp] = vv;
        __nv_bfloat162 kk = *(const __nv_bfloat162*)&stK[row*72 + 2*dp];
        ((__nv_bfloat162*)g_kT)[((size_t)b*64 + row)*2048 + (nn0 >> 1) + dp] = kk;
    }
}

// ---------------- attention: k/v duplicated in regs, natural q/attn smem reads ----------------
__global__ void __launch_bounds__(256) attn_kernel() {
    __shared__ __align__(16) float qst[512];      // [e][8] natural q
    __shared__ __align__(16) float attn_s[6144];  // [n][12] stride-12; reused as red[8][512]
    __shared__ float sred[64];
    int t = threadIdx.x, b = blockIdx.y, n0 = blockIdx.x * 512;

    ((float2*)qst)[t] = ((const float2*)(g_q + b*512))[t];
    __syncthreads();

    float sacc[8];
    {
        const __nv_bfloat162* kp = (const __nv_bfloat162*)g_kT + (size_t)b*131072 + (n0>>1) + t;
        ull lp0[4], lp1[4];
        #pragma unroll
        for (int i = 0; i < 4; i++) { lp0[i] = 0ull; lp1[i] = 0ull; }
        #pragma unroll 8
        for (int d = 0; d < 64; d++) {
            float2 kf = __bfloat1622float2(kp[d*2048]);
            ull kv0; PACK2(kv0, kf.x, kf.x);
            ull kv1; PACK2(kv1, kf.y, kf.y);
            ulonglong2 qa = *(const ulonglong2*)&qst[d*8];
            ulonglong2 qb = *(const ulonglong2*)&qst[d*8 + 4];
            FMA2(lp0[0], qa.x, kv0); FMA2(lp0[1], qa.y, kv0);
            FMA2(lp0[2], qb.x, kv0); FMA2(lp0[3], qb.y, kv0);
            FMA2(lp1[0], qa.x, kv1); FMA2(lp1[1], qa.y, kv1);
            FMA2(lp1[2], qb.x, kv1); FMA2(lp1[3], qb.y, kv1);
        }
        float l0[8], l1[8];
        #pragma unroll
        for (int i = 0; i < 4; i++) {
            float2 f0 = *reinterpret_cast<float2*>(&lp0[i]);
            float2 f1 = *reinterpret_cast<float2*>(&lp1[i]);
            l0[2*i] = f0.x; l0[2*i+1] = f0.y;
            l1[2*i] = f1.x; l1[2*i+1] = f1.y;
        }
        float m0 = l0[0], m1 = l1[0];
        #pragma unroll
        for (int j = 1; j < 8; j++) { m0 = fmaxf(m0, l0[j]); m1 = fmaxf(m1, l1[j]); }
        float s0 = 0.f, s1 = 0.f, e0[8], e1[8];
        #pragma unroll
        for (int j = 0; j < 8; j++) {
            e0[j] = __expf((l0[j] - m0) * 0.125f); s0 += e0[j];
            e1[j] = __expf((l1[j] - m1) * 0.125f); s1 += e1[j];
        }
        float i0 = 1.0f / s0, i1 = 1.0f / s1;
        float a0[8], a1[8];
        #pragma unroll
        for (int j = 0; j < 8; j++) {
            a0[j] = e0[j]*i0 + 1e-8f;
            a1[j] = e1[j]*i1 + 1e-8f;
            sacc[j] = a0[j] + a1[j];
        }
        *(float4*)&attn_s[(2*t)*12]     = make_float4(a0[0], a0[1], a0[2], a0[3]);
        *(float4*)&attn_s[(2*t)*12 + 4] = make_float4(a0[4], a0[5], a0[6], a0[7]);
        *(float4*)&attn_s[(2*t+1)*12]     = make_float4(a1[0], a1[1], a1[2], a1[3]);
        *(float4*)&attn_s[(2*t+1)*12 + 4] = make_float4(a1[4], a1[5], a1[6], a1[7]);
    }
    #pragma unroll
    for (int j = 0; j < 8; j++) {
        float v = sacc[j];
        #pragma unroll
        for (int o = 16; o > 0; o >>= 1) v += __shfl_xor_sync(~0u, v, o);
        if ((t & 31) == 0) sred[(t>>5)*8 + j] = v;
    }
    __syncthreads();
    if (t < 8) {
        float v = 0.f;
        #pragma unroll
        for (int w = 0; w < 8; w++) v += sred[w*8 + t];
        g_Sp[blockIdx.x*512 + b*8 + t] = v;
    }

    int d2 = t & 31, grp = t >> 5;
    ull ap0[4], ap1[4];
    #pragma unroll
    for (int i = 0; i < 4; i++) { ap0[i] = 0ull; ap1[i] = 0ull; }
    const __nv_bfloat162* vp = (const __nv_bfloat162*)g_v + ((size_t)b*4096 + n0)*32 + d2;
    int nbeg = grp * 64;
    #pragma unroll 4
    for (int n = nbeg; n < nbeg + 64; n++) {
        float2 vf = __bfloat1622float2(vp[(size_t)n*32]);
        ull vv0; PACK2(vv0, vf.x, vf.x);
        ull vv1; PACK2(vv1, vf.y, vf.y);
        ulonglong2 aa = *(const ulonglong2*)&attn_s[n*12];
        ulonglong2 ab = *(const ulonglong2*)&attn_s[n*12 + 4];
        FMA2(ap0[0], aa.x, vv0); FMA2(ap0[1], aa.y, vv0);
        FMA2(ap0[2], ab.x, vv0); FMA2(ap0[3], ab.y, vv0);
        FMA2(ap1[0], aa.x, vv1); FMA2(ap1[1], aa.y, vv1);
        FMA2(ap1[2], ab.x, vv1); FMA2(ap1[3], ab.y, vv1);
    }
    __syncthreads();
    float* red = attn_s;
    #pragma unroll
    for (int i = 0; i < 4; i++) {
        float2 u0 = *reinterpret_cast<float2*>(&ap0[i]);
        float2 u1 = *reinterpret_cast<float2*>(&ap1[i]);
        *(float2*)&red[grp*512 + (2*i)*64   + 2*d2] = make_float2(u0.x, u1.x);
        *(float2*)&red[grp*512 + (2*i+1)*64 + 2*d2] = make_float2(u0.y, u1.y);
    }
    __syncthreads();
    #pragma unroll
    for (int rep = 0; rep < 2; rep++) {
        int idx = rep*256 + t;
        float v = 0.f;
        #pragma unroll
        for (int g = 0; g < 8; g++) v += red[g*512 + idx];
        g_Up[((size_t)blockIdx.x*64 + b)*512 + idx] = v;
    }
}

// ---------------- pipelined GRU + LN + MLP + residual + next-iter q ----------------
// Dynamic-smem wbuf (52 KB): full-matrix stages, prefetch-ahead LDG pipelining.
__global__ void __launch_bounds__(384) gru_mlp(
        const float* __restrict__ wih, const float* __restrict__ whh,
        const float* __restrict__ bih, const float* __restrict__ bhh,
        const float* __restrict__ w1, const float* __restrict__ b1,
        const float* __restrict__ w2, const float* __restrict__ b2,
        const float* __restrict__ Wq,
        const float* __restrict__ lng, const float* __restrict__ lnb,
        const float* __restrict__ lng2, const float* __restrict__ lnb2,
        float* __restrict__ out, int last) {
    __shared__ __align__(16) float u_s[256], h_s[256];
    __shared__ __align__(16) float gi_s[768], gh_s[768];
    __shared__ __align__(16) float hn_s[256], ln_s[256], h1_s[512];
    extern __shared__ __align__(16) float wbuf[];   // 13056 floats
    int t = threadIdx.x;
    int grow0 = blockIdx.x * 4;
    float4 rbuf[8];

    // prefetch wih (3072 f4, 8/thread exact) -- overlaps Phase A's own LDGs
    #pragma unroll
    for (int k = 0; k < 8; k++) rbuf[k] = __ldg((const float4*)wih + t + 384*k);

    // Phase A: u = U/S, h = slots
    if (t < 256) {
        int r = t >> 6, d = t & 63;
        int grow = grow0 + r;
        float S = 0.f, U = 0.f;
        #pragma unroll
        for (int c = 0; c < 8; c++) {
            S += g_Sp[c*512 + grow];
            U += g_Up[c*32768 + grow*64 + d];
        }
        u_s[t] = U / S;
        h_s[t] = g_slots[grow*64 + d];
    }
    __syncthreads();                                   // (1)

    // STS wih (stride 68)
    #pragma unroll
    for (int k = 0; k < 8; k++) {
        int idx = t + 384*k; int r = idx >> 4, c = (idx & 15) * 4;
        *(float4*)&wbuf[r*68 + c] = rbuf[k];
    }
    __syncthreads();                                   // (2)
    // prefetch whh
    #pragma unroll
    for (int k = 0; k < 8; k++) rbuf[k] = __ldg((const float4*)whh + t + 384*k);

    // C_gi: gate j = t%192, row-pair rp: rows 2rp, 2rp+1
    int j = (t < 192) ? t : (t - 192);
    int rp = (t < 192) ? 0 : 1;
    {
        float a0 = 0.f, a1 = 0.f;
        const float4* W  = (const float4*)(wbuf + j*68);
        const float4* X0 = (const float4*)(u_s + rp*128);
        const float4* X1 = (const float4*)(u_s + rp*128 + 64);
        #pragma unroll
        for (int i = 0; i < 16; i++) { float4 w = W[i]; a0 += dot4(X0[i], w); a1 += dot4(X1[i], w); }
        float bi = __ldg(bih + j);
        gi_s[(rp*2)*192 + j]   = a0 + bi;
        gi_s[(rp*2+1)*192 + j] = a1 + bi;
    }
    __syncthreads();                                   // (3) done reading wih

    // STS whh
    #pragma unroll
    for (int k = 0; k < 8; k++) {
        int idx = t + 384*k; int r = idx >> 4, c = (idx & 15) * 4;
        *(float4*)&wbuf[r*68 + c] = rbuf[k];
    }
    __syncthreads();                                   // (4)
    // prefetch w1 (2048 f4, 6/thread guarded)
    #pragma unroll
    for (int k = 0; k < 6; k++) {
        int idx = t + 384*k;
        if (idx < 2048) rbuf[k] = __ldg((const float4*)w1 + idx);
    }

    // C_gh
    {
        float a0 = 0.f, a1 = 0.f;
        const float4* W  = (const float4*)(wbuf + j*68);
        const float4* X0 = (const float4*)(h_s + rp*128);
        const float4* X1 = (const float4*)(h_s + rp*128 + 64);
        #pragma unroll
        for (int i = 0; i < 16; i++) { float4 w = W[i]; a0 += dot4(X0[i], w); a1 += dot4(X1[i], w); }
        float bh = __ldg(bhh + j);
        gh_s[(rp*2)*192 + j]   = a0 + bh;
        gh_s[(rp*2+1)*192 + j] = a1 + bh;
    }
    __syncthreads();                                   // (5) gates done, wbuf free

    // STS w1 + Phase C combine (independent)
    #pragma unroll
    for (int k = 0; k < 6; k++) {
        int idx = t + 384*k;
        if (idx < 2048) { int r = idx >> 4, c = (idx & 15) * 4; *(float4*)&wbuf[r*68 + c] = rbuf[k]; }
    }
    if (t < 256) {
        int r = t >> 6, d = t & 63;
        float rr = sigf(gi_s[r*192 + d]       + gh_s[r*192 + d]);
        float z  = sigf(gi_s[r*192 + 64 + d]  + gh_s[r*192 + 64 + d]);
        float n  = tanhf(gi_s[r*192 + 128 + d] + rr * gh_s[r*192 + 128 + d]);
        hn_s[t] = (1.f - z)*n + z*h_s[t];
    }
    __syncthreads();                                   // (6) w1 staged + hn_s ready

    // Phase D: LayerNorm (mlp)
    if (t < 128) {
        int r = t >> 5, lane = t & 31;
        float x0 = hn_s[r*64 + lane], x1 = hn_s[r*64 + 32 + lane];
        float s = x0 + x1, ss = x0*x0 + x1*x1;
        #pragma unroll
        for (int o = 16; o > 0; o >>= 1) { s += __shfl_xor_sync(~0u, s, o); ss += __shfl_xor_sync(~0u, ss, o); }
        float mu = s * 0.015625f;
        float rstd = rsqrtf(ss * 0.015625f - mu*mu + 1e-5f);
        ln_s[r*64 + lane]      = (x0 - mu)*rstd*__ldg(lng+lane)    + __ldg(lnb+lane);
        ln_s[r*64 + 32 + lane] = (x1 - mu)*rstd*__ldg(lng+32+lane) + __ldg(lnb+32+lane);
    }
    // prefetch w2 (2048 f4 guarded)
    #pragma unroll
    for (int k = 0; k < 6; k++) {
        int idx = t + 384*k;
        if (idx < 2048) rbuf[k] = __ldg((const float4*)w2 + idx);
    }
    __syncthreads();                                   // (7) ln_s ready

    // C_w1: t<128, 4 rows
    float e0 = 0.f, e1 = 0.f, e2 = 0.f, e3 = 0.f;
    if (t < 128) {
        const float4* W  = (const float4*)(wbuf + t*68);
        const float4* X0 = (const float4*)(ln_s);
        const float4* X1 = (const float4*)(ln_s + 64);
        const float4* X2 = (const float4*)(ln_s + 128);
        const float4* X3 = (const float4*)(ln_s + 192);
        #pragma unroll
        for (int i = 0; i < 16; i++) {
            float4 w = W[i];
            e0 += dot4(X0[i], w); e1 += dot4(X1[i], w);
            e2 += dot4(X2[i], w); e3 += dot4(X3[i], w);
        }
        float bias = __ldg(b1 + t);
        h1_s[t]       = fmaxf(e0 + bias, 0.f);
        h1_s[128 + t] = fmaxf(e1 + bias, 0.f);
        h1_s[256 + t] = fmaxf(e2 + bias, 0.f);
        h1_s[384 + t] = fmaxf(e3 + bias, 0.f);
    }
    __syncthreads();                                   // (8) w1 reads done, h1_s ready

    // STS w2 (stride 132, 128 cols)
    #pragma unroll
    for (int k = 0; k < 6; k++) {
        int idx = t + 384*k;
        if (idx < 2048) { int r = idx >> 5, c = (idx & 31) * 4; *(float4*)&wbuf[r*132 + c] = rbuf[k]; }
    }
    __syncthreads();                                   // (9)
    // prefetch Wq (1024 f4 guarded)
    #pragma unroll
    for (int k = 0; k < 3; k++) {
        int idx = t + 384*k;
        if (idx < 1024) rbuf[k] = __ldg((const float4*)Wq + idx);
    }

    // C_w2: t<256 (row fr, output fo)
    int fr = (t >> 6) & 3, fo = t & 63;
    if (t < 256) {
        const float4* W = (const float4*)(wbuf + fo*132);
        const float4* H = (const float4*)(h1_s + fr*128);
        float a = 0.f;
        #pragma unroll
        for (int i = 0; i < 32; i++) a += dot4(H[i], W[i]);
        a += __ldg(b2 + fo);
        float res = hn_s[fr*64 + fo] + a;
        int grow = grow0 + fr;
        g_slots[grow*64 + fo] = res;
        if (last) out[grow*64 + fo] = res;
        u_s[t] = res;
    }
    __syncthreads();                                   // (10) w2 reads done, u_s ready
    if (last) return;

    // STS Wq (stride 68) + q-LN
    #pragma unroll
    for (int k = 0; k < 3; k++) {
        int idx = t + 384*k;
        if (idx < 1024) { int r = idx >> 4, c = (idx & 15) * 4; *(float4*)&wbuf[r*68 + c] = rbuf[k]; }
    }
    if (t < 128) {
        int r = t >> 5, lane = t & 31;
        float x0 = u_s[r*64 + lane], x1 = u_s[r*64 + 32 + lane];
        float s = x0 + x1, ss = x0*x0 + x1*x1;
        #pragma unroll
        for (int o = 16; o > 0; o >>= 1) { s += __shfl_xor_sync(~0u, s, o); ss += __shfl_xor_sync(~0u, ss, o); }
        float mu = s * 0.015625f;
        float rstd = rsqrtf(ss * 0.015625f - mu*mu + 1e-5f);
        ln_s[r*64 + lane]      = (x0 - mu)*rstd*__ldg(lng2+lane)    + __ldg(lnb2+lane);
        ln_s[r*64 + 32 + lane] = (x1 - mu)*rstd*__ldg(lng2+32+lane) + __ldg(lnb2+32+lane);
    }
    __syncthreads();                                   // (11) Wq staged + ln_s ready

    if (t < 256) {
        int r = t >> 6, e = t & 63;
        const float4* W = (const float4*)(wbuf + e*68);
        const float4* X = (const float4*)(ln_s + r*64);
        float a = 0.f;
        #pragma unroll
        for (int i = 0; i < 16; i++) a += dot4(X[i], W[i]);
        int grow = grow0 + r;
        int b = grow >> 3, k = grow & 7;
        g_q[b*512 + e*8 + k] = a;
    }
}

extern "C" void kernel_launch(void* const* d_in, const int* in_sizes, int n_in,
                              void* d_out, int out_size) {
    const float* inputs = (const float*)d_in[0];
    const float* noise  = (const float*)d_in[1];
    const float* mu     = (const float*)d_in[2];
    const float* lsig   = (const float*)d_in[3];
    const float* Wq     = (const float*)d_in[4];
    const float* Wk     = (const float*)d_in[5];
    const float* Wv     = (const float*)d_in[6];
    const float* wih    = (const float*)d_in[7];
    const float* whh    = (const float*)d_in[8];
    const float* bih    = (const float*)d_in[9];
    const float* bhh    = (const float*)d_in[10];
    const float* w1     = (const float*)d_in[11];
    const float* b1     = (const float*)d_in[12];
    const float* w2     = (const float*)d_in[13];
    const float* b2     = (const float*)d_in[14];
    const float* ln_in_g   = (const float*)d_in[15];
    const float* ln_in_b   = (const float*)d_in[16];
    const float* ln_sl_g   = (const float*)d_in[17];
    const float* ln_sl_b   = (const float*)d_in[18];
    const float* ln_mlp_g  = (const float*)d_in[19];
    const float* ln_mlp_b  = (const float*)d_in[20];
    float* out = (float*)d_out;

    const int GRU_SMEM = 13056 * 4;   // 52.2 KB dynamic
    cudaFuncSetAttribute(gru_mlp, cudaFuncAttributeMaxDynamicSharedMemorySize, GRU_SMEM);

    prep<<<128, 256>>>(Wq, noise, mu, lsig, ln_sl_g, ln_sl_b);
    ln_kv<<<4096, 256>>>(inputs, Wk, Wv, ln_in_g, ln_in_b);
    for (int it = 0; it < 3; it++) {
        attn_kernel<<<dim3(8, 64), 256>>>();
        gru_mlp<<<128, 384, GRU_SMEM>>>(wih, whh, bih, bhh, w1, b1, w2, b2, Wq,
                                        ln_mlp_g, ln_mlp_b, ln_sl_g, ln_sl_b, out, it == 2);
    }
}

// round 17
// speedup vs baseline: 3.5025x; 1.0291x over previous
#include <cuda_runtime.h>
#include <cuda_bf16.h>

typedef unsigned long long ull;
typedef unsigned int uint32;

// ---------------- device scratch ----------------
__device__ __nv_bfloat16 g_kT[16777216];  // [b][d][n] transposed K (bf16)
__device__ __nv_bfloat16 g_v [16777216];  // [b][n][d] (bf16)
__device__ float g_slots[32768];   // [b][k][d]
__device__ float g_q[32768];       // [b][e][8] natural transposed q
__device__ float g_Up[262144];     // [chunk(8)][b][k][d]
__device__ float g_Sp[4096];       // [chunk(8)][b*8+k]

#define FMA2(acc, a, b) asm("fma.rn.f32x2 %0, %1, %2, %0;" : "+l"(acc) : "l"(a), "l"(b))
#define PACK2(dst, x, y) asm("mov.b64 %0, {%1, %2};" : "=l"(dst) : "f"(x), "f"(y))

#define MMA16816(d, a0, a1, a2, a3, b0, b1) \
    asm volatile("mma.sync.aligned.m16n8k16.row.col.f32.bf16.bf16.f32 " \
        "{%0,%1,%2,%3}, {%4,%5,%6,%7}, {%8,%9}, {%0,%1,%2,%3};" \
        : "+f"(d[0]), "+f"(d[1]), "+f"(d[2]), "+f"(d[3]) \
        : "r"(a0), "r"(a1), "r"(a2), "r"(a3), "r"(b0), "r"(b1))

__device__ __forceinline__ float sigf(float x) { return 1.f / (1.f + __expf(-x)); }
__device__ __forceinline__ float dot4(float4 a, float4 b) {
    return a.x*b.x + a.y*b.y + a.z*b.z + a.w*b.w;
}
__device__ __forceinline__ void cp16(uint32 dst, const void* src) {
    asm volatile("cp.async.ca.shared.global [%0], [%1], 16;" :: "r"(dst), "l"(src));
}

// ---------------- prep: slots init + iter-1 q ----------------
__global__ void __launch_bounds__(256) prep(const float* __restrict__ Wq,
                     const float* __restrict__ noise,
                     const float* __restrict__ mu, const float* __restrict__ lsig,
                     const float* __restrict__ lng, const float* __restrict__ lnb) {
    __shared__ float sWqT[65 * 64];
    __shared__ float slot_s[256];
    int tid = threadIdx.x;
    int t = blockIdx.x * 256 + tid;

    {
        int d = t & 63;
        float val = __ldg(mu + d) + __expf(__ldg(lsig + d)) * noise[t];
        g_slots[t] = val;
        slot_s[tid] = val;
    }
    #pragma unroll
    for (int i = tid; i < 4096; i += 256) { int e = i >> 6, d = i & 63; sWqT[d*65 + e] = Wq[i]; }
    __syncthreads();

    if (tid < 128) {
        int w = tid >> 5, lane = tid & 31;
        float s0 = slot_s[w*64 + lane], s1 = slot_s[w*64 + 32 + lane];
        float s = s0 + s1, ss = s0*s0 + s1*s1;
        #pragma unroll
        for (int o = 16; o > 0; o >>= 1) { s += __shfl_xor_sync(~0u, s, o); ss += __shfl_xor_sync(~0u, ss, o); }
        float m = s * 0.015625f;
        float rstd = rsqrtf(ss * 0.015625f - m*m + 1e-5f);
        slot_s[w*64 + lane]      = (s0 - m)*rstd*__ldg(lng+lane)    + __ldg(lnb+lane);
        slot_s[w*64 + 32 + lane] = (s1 - m)*rstd*__ldg(lng+32+lane) + __ldg(lnb+32+lane);
    }
    __syncthreads();

    {
        int r = tid >> 6, e = tid & 63;
        float a = 0.f;
        #pragma unroll 16
        for (int d = 0; d < 64; d++) a += slot_s[r*64 + d] * sWqT[d*65 + e];
        int grow = blockIdx.x*4 + r;
        int b = grow >> 3, k = grow & 7;
        g_q[b*512 + e*8 + k] = a;
    }
}

// ---------------- fused input LN + K^T/V projection via bf16 tensor cores ----------------
__global__ void __launch_bounds__(256) ln_kv(const float* __restrict__ inp,
        const float* __restrict__ Wk, const float* __restrict__ Wv,
        const float* __restrict__ lng, const float* __restrict__ lnb) {
    __shared__ __align__(16) __nv_bfloat16 xb[64 * 72];
    __shared__ __align__(16) __nv_bfloat16 wb[128 * 72];
    int t = threadIdx.x;
    int r0 = blockIdx.x * 64;

    {
        int row = t >> 2, j0 = (t & 3) * 16;
        const float4* xp = (const float4*)(inp + (size_t)(r0 + row)*64 + j0);
        float4 q0 = __ldg(xp), q1 = __ldg(xp+1), q2 = __ldg(xp+2), q3 = __ldg(xp+3);
        float s  = q0.x+q0.y+q0.z+q0.w + q1.x+q1.y+q1.z+q1.w
                 + q2.x+q2.y+q2.z+q2.w + q3.x+q3.y+q3.z+q3.w;
        float ss = dot4(q0,q0) + dot4(q1,q1) + dot4(q2,q2) + dot4(q3,q3);
        s  += __shfl_xor_sync(~0u, s, 1);  ss += __shfl_xor_sync(~0u, ss, 1);
        s  += __shfl_xor_sync(~0u, s, 2);  ss += __shfl_xor_sync(~0u, ss, 2);
        float mu = s * 0.015625f;
        float rstd = rsqrtf(ss * 0.015625f - mu*mu + 1e-5f);
        float vals[16] = {q0.x,q0.y,q0.z,q0.w, q1.x,q1.y,q1.z,q1.w,
                          q2.x,q2.y,q2.z,q2.w, q3.x,q3.y,q3.z,q3.w};
        #pragma unroll
        for (int i = 0; i < 16; i++) {
            int f = j0 + i;
            float o = (vals[i] - mu) * rstd * __ldg(lng+f) + __ldg(lnb+f);
            xb[row*72 + f] = __float2bfloat16(o);
        }
    }
    #pragma unroll
    for (int i = t; i < 8192; i += 256) {
        int rr = i >> 6, c = i & 63;
        float w = (i < 4096) ? __ldg(Wk + i) : __ldg(Wv + i - 4096);
        wb[rr*72 + c] = __float2bfloat16(w);
    }
    __syncthreads();

    int lane = t & 31, w = t >> 5;
    int mt = w & 3, msel = w >> 2;
    int row_a = mt*16 + (lane >> 2);
    int colq = (lane & 3) * 2;
    float d[8][4];
    #pragma unroll
    for (int nt = 0; nt < 8; nt++)
        #pragma unroll
        for (int i = 0; i < 4; i++) d[nt][i] = 0.f;
    #pragma unroll
    for (int ks = 0; ks < 4; ks++) {
        int k0 = ks * 16;
        uint32 a0 = *(const uint32*)&xb[row_a*72     + k0 + colq];
        uint32 a1 = *(const uint32*)&xb[(row_a+8)*72 + k0 + colq];
        uint32 a2 = *(const uint32*)&xb[row_a*72     + k0 + colq + 8];
        uint32 a3 = *(const uint32*)&xb[(row_a+8)*72 + k0 + colq + 8];
        #pragma unroll
        for (int nt = 0; nt < 8; nt++) {
            int rowb = msel*64 + nt*8 + (lane >> 2);
            uint32 b0 = *(const uint32*)&wb[rowb*72 + k0 + colq];
            uint32 b1 = *(const uint32*)&wb[rowb*72 + k0 + colq + 8];
            MMA16816(d[nt], a0, a1, a2, a3, b0, b1);
        }
    }
    __syncthreads();

    __nv_bfloat16* stV = wb;
    __nv_bfloat16* stK = wb + 4608;
    if (msel == 0) {
        #pragma unroll
        for (int nt = 0; nt < 8; nt++) {
            int dd = nt*8 + colq;
            stK[dd*72 + row_a]         = __float2bfloat16(d[nt][0]);
            stK[(dd+1)*72 + row_a]     = __float2bfloat16(d[nt][1]);
            stK[dd*72 + row_a + 8]     = __float2bfloat16(d[nt][2]);
            stK[(dd+1)*72 + row_a + 8] = __float2bfloat16(d[nt][3]);
        }
    } else {
        #pragma unroll
        for (int nt = 0; nt < 8; nt++) {
            int nn = nt*8 + colq;
            *(__nv_bfloat162*)&stV[row_a*72 + nn]     = __floats2bfloat162_rn(d[nt][0], d[nt][1]);
            *(__nv_bfloat162*)&stV[(row_a+8)*72 + nn] = __floats2bfloat162_rn(d[nt][2], d[nt][3]);
        }
    }
    __syncthreads();

    int b = r0 >> 12, nn0 = r0 & 4095;
    #pragma unroll
    for (int i = t; i < 2048; i += 256) {
        int row = i >> 5, dp = i & 31;
        __nv_bfloat162 vv = *(const __nv_bfloat162*)&stV[row*72 + 2*dp];
        ((__nv_bfloat162*)g_v)[(size_t)(r0 + row)*32 + dp] = vv;
        __nv_bfloat162 kk = *(const __nv_bfloat162*)&stK[row*72 + 2*dp];
        ((__nv_bfloat162*)g_kT)[((size_t)b*64 + row)*2048 + (nn0 >> 1) + dp] = kk;
    }
}

// ---------------- attention: k/v duplicated in regs, natural q/attn smem reads ----------------
__global__ void __launch_bounds__(256) attn_kernel() {
    __shared__ __align__(16) float qst[512];      // [e][8] natural q
    __shared__ __align__(16) float attn_s[6144];  // [n][12] stride-12; reused as red[8][512]
    __shared__ float sred[64];
    int t = threadIdx.x, b = blockIdx.y, n0 = blockIdx.x * 512;

    ((float2*)qst)[t] = ((const float2*)(g_q + b*512))[t];
    __syncthreads();

    float sacc[8];
    {
        const __nv_bfloat162* kp = (const __nv_bfloat162*)g_kT + (size_t)b*131072 + (n0>>1) + t;
        ull lp0[4], lp1[4];
        #pragma unroll
        for (int i = 0; i < 4; i++) { lp0[i] = 0ull; lp1[i] = 0ull; }
        #pragma unroll 8
        for (int d = 0; d < 64; d++) {
            float2 kf = __bfloat1622float2(kp[d*2048]);
            ull kv0; PACK2(kv0, kf.x, kf.x);
            ull kv1; PACK2(kv1, kf.y, kf.y);
            ulonglong2 qa = *(const ulonglong2*)&qst[d*8];
            ulonglong2 qb = *(const ulonglong2*)&qst[d*8 + 4];
            FMA2(lp0[0], qa.x, kv0); FMA2(lp0[1], qa.y, kv0);
            FMA2(lp0[2], qb.x, kv0); FMA2(lp0[3], qb.y, kv0);
            FMA2(lp1[0], qa.x, kv1); FMA2(lp1[1], qa.y, kv1);
            FMA2(lp1[2], qb.x, kv1); FMA2(lp1[3], qb.y, kv1);
        }
        float l0[8], l1[8];
        #pragma unroll
        for (int i = 0; i < 4; i++) {
            float2 f0 = *reinterpret_cast<float2*>(&lp0[i]);
            float2 f1 = *reinterpret_cast<float2*>(&lp1[i]);
            l0[2*i] = f0.x; l0[2*i+1] = f0.y;
            l1[2*i] = f1.x; l1[2*i+1] = f1.y;
        }
        float m0 = l0[0], m1 = l1[0];
        #pragma unroll
        for (int j = 1; j < 8; j++) { m0 = fmaxf(m0, l0[j]); m1 = fmaxf(m1, l1[j]); }
        float s0 = 0.f, s1 = 0.f, e0[8], e1[8];
        #pragma unroll
        for (int j = 0; j < 8; j++) {
            e0[j] = __expf((l0[j] - m0) * 0.125f); s0 += e0[j];
            e1[j] = __expf((l1[j] - m1) * 0.125f); s1 += e1[j];
        }
        float i0 = 1.0f / s0, i1 = 1.0f / s1;
        float a0[8], a1[8];
        #pragma unroll
        for (int j = 0; j < 8; j++) {
            a0[j] = e0[j]*i0 + 1e-8f;
            a1[j] = e1[j]*i1 + 1e-8f;
            sacc[j] = a0[j] + a1[j];
        }
        *(float4*)&attn_s[(2*t)*12]     = make_float4(a0[0], a0[1], a0[2], a0[3]);
        *(float4*)&attn_s[(2*t)*12 + 4] = make_float4(a0[4], a0[5], a0[6], a0[7]);
        *(float4*)&attn_s[(2*t+1)*12]     = make_float4(a1[0], a1[1], a1[2], a1[3]);
        *(float4*)&attn_s[(2*t+1)*12 + 4] = make_float4(a1[4], a1[5], a1[6], a1[7]);
    }
    #pragma unroll
    for (int j = 0; j < 8; j++) {
        float v = sacc[j];
        #pragma unroll
        for (int o = 16; o > 0; o >>= 1) v += __shfl_xor_sync(~0u, v, o);
        if ((t & 31) == 0) sred[(t>>5)*8 + j] = v;
    }
    __syncthreads();
    if (t < 8) {
        float v = 0.f;
        #pragma unroll
        for (int w = 0; w < 8; w++) v += sred[w*8 + t];
        g_Sp[blockIdx.x*512 + b*8 + t] = v;
    }

    int d2 = t & 31, grp = t >> 5;
    ull ap0[4], ap1[4];
    #pragma unroll
    for (int i = 0; i < 4; i++) { ap0[i] = 0ull; ap1[i] = 0ull; }
    const __nv_bfloat162* vp = (const __nv_bfloat162*)g_v + ((size_t)b*4096 + n0)*32 + d2;
    int nbeg = grp * 64;
    #pragma unroll 4
    for (int n = nbeg; n < nbeg + 64; n++) {
        float2 vf = __bfloat1622float2(vp[(size_t)n*32]);
        ull vv0; PACK2(vv0, vf.x, vf.x);
        ull vv1; PACK2(vv1, vf.y, vf.y);
        ulonglong2 aa = *(const ulonglong2*)&attn_s[n*12];
        ulonglong2 ab = *(const ulonglong2*)&attn_s[n*12 + 4];
        FMA2(ap0[0], aa.x, vv0); FMA2(ap0[1], aa.y, vv0);
        FMA2(ap0[2], ab.x, vv0); FMA2(ap0[3], ab.y, vv0);
        FMA2(ap1[0], aa.x, vv1); FMA2(ap1[1], aa.y, vv1);
        FMA2(ap1[2], ab.x, vv1); FMA2(ap1[3], ab.y, vv1);
    }
    __syncthreads();
    float* red = attn_s;
    #pragma unroll
    for (int i = 0; i < 4; i++) {
        float2 u0 = *reinterpret_cast<float2*>(&ap0[i]);
        float2 u1 = *reinterpret_cast<float2*>(&ap1[i]);
        *(float2*)&red[grp*512 + (2*i)*64   + 2*d2] = make_float2(u0.x, u1.x);
        *(float2*)&red[grp*512 + (2*i+1)*64 + 2*d2] = make_float2(u0.y, u1.y);
    }
    __syncthreads();
    #pragma unroll
    for (int rep = 0; rep < 2; rep++) {
        int idx = rep*256 + t;
        float v = 0.f;
        #pragma unroll
        for (int g = 0; g < 8; g++) v += red[g*512 + idx];
        g_Up[((size_t)blockIdx.x*64 + b)*512 + idx] = v;
    }
}

// ---------------- gru_mlp v3: cp.async double-width staging, collapsed chain ----------------
// wbuf layout (floats): stage1: WIH @0 (192x68), WHH @13056 (192x68)
//                       stage2: W1 @0 (128x68), W2 @8704 (64x132), WQ @17152 (64x68)
__global__ void __launch_bounds__(384) gru_mlp(
        const float* __restrict__ wih, const float* __restrict__ whh,
        const float* __restrict__ bih, const float* __restrict__ bhh,
        const float* __restrict__ w1, const float* __restrict__ b1,
        const float* __restrict__ w2, const float* __restrict__ b2,
        const float* __restrict__ Wq,
        const float* __restrict__ lng, const float* __restrict__ lnb,
        const float* __restrict__ lng2, const float* __restrict__ lnb2,
        float* __restrict__ out, int last) {
    __shared__ __align__(16) float u_s[256], h_s[256];
    __shared__ __align__(16) float gi_s[768], gh_s[768];
    __shared__ __align__(16) float hn_s[256], ln_s[256], h1_s[512];
    extern __shared__ __align__(16) float wbuf[];   // 26112 floats (104.4 KB)
    int t = threadIdx.x;
    int grow0 = blockIdx.x * 4;
    uint32 sb = (uint32)__cvta_generic_to_shared(wbuf);

    // ---- stage 1: wih + whh via cp.async (overlaps Phase A) ----
    #pragma unroll
    for (int k = 0; k < 16; k++) {
        int idx = t + 384*k;                         // 0..6143
        if (idx < 3072) {
            int r = idx >> 4, c = (idx & 15) * 4;
            cp16(sb + (r*68 + c)*4, (const float4*)wih + idx);
        } else {
            int i2 = idx - 3072;
            int r = i2 >> 4, c = (i2 & 15) * 4;
            cp16(sb + (13056 + r*68 + c)*4, (const float4*)whh + i2);
        }
    }
    asm volatile("cp.async.commit_group;");

    // Phase A: u = U/S, h = slots
    if (t < 256) {
        int r = t >> 6, d = t & 63;
        int grow = grow0 + r;
        float S = 0.f, U = 0.f;
        #pragma unroll
        for (int c = 0; c < 8; c++) {
            S += g_Sp[c*512 + grow];
            U += g_Up[c*32768 + grow*64 + d];
        }
        u_s[t] = U / S;
        h_s[t] = g_slots[grow*64 + d];
    }
    asm volatile("cp.async.wait_group 0;" ::: "memory");
    __syncthreads();                                 // (1) weights + u/h ready

    // gates: thread (j = t%192, rp = t/192): gi AND gh for rows 2rp, 2rp+1
    int j = (t < 192) ? t : (t - 192);
    int rp = (t < 192) ? 0 : 1;
    {
        const float4* WI = (const float4*)(wbuf + j*68);
        const float4* WH = (const float4*)(wbuf + 13056 + j*68);
        const float4* U0 = (const float4*)(u_s + rp*128);
        const float4* U1 = (const float4*)(u_s + rp*128 + 64);
        const float4* H0 = (const float4*)(h_s + rp*128);
        const float4* H1 = (const float4*)(h_s + rp*128 + 64);
        float ai0 = 0.f, ai1 = 0.f, ah0 = 0.f, ah1 = 0.f;
        #pragma unroll
        for (int i = 0; i < 16; i++) {
            float4 wi = WI[i], wh = WH[i];
            ai0 += dot4(U0[i], wi); ai1 += dot4(U1[i], wi);
            ah0 += dot4(H0[i], wh); ah1 += dot4(H1[i], wh);
        }
        float bi = __ldg(bih + j), bh = __ldg(bhh + j);
        gi_s[(rp*2)*192 + j]   = ai0 + bi;
        gi_s[(rp*2+1)*192 + j] = ai1 + bi;
        gh_s[(rp*2)*192 + j]   = ah0 + bh;
        gh_s[(rp*2+1)*192 + j] = ah1 + bh;
    }
    __syncthreads();                                 // (2) gates done, wbuf reads done

    // ---- stage 2: w1 + w2 + Wq via cp.async (overlaps C + D) ----
    #pragma unroll
    for (int k = 0; k < 14; k++) {
        int idx = t + 384*k;                         // 0..5119
        if (idx < 2048) {
            int r = idx >> 4, c = (idx & 15) * 4;
            cp16(sb + (r*68 + c)*4, (const float4*)w1 + idx);
        } else if (idx < 4096) {
            int i2 = idx - 2048;
            int r = i2 >> 5, c = (i2 & 31) * 4;
            cp16(sb + (8704 + r*132 + c)*4, (const float4*)w2 + i2);
        } else if (idx < 5120) {
            int i3 = idx - 4096;
            int r = i3 >> 4, c = (i3 & 15) * 4;
            cp16(sb + (17152 + r*68 + c)*4, (const float4*)Wq + i3);
        }
    }
    asm volatile("cp.async.commit_group;");

    // Phase C: GRU combine
    if (t < 256) {
        int r = t >> 6, d = t & 63;
        float rr = sigf(gi_s[r*192 + d]       + gh_s[r*192 + d]);
        float z  = sigf(gi_s[r*192 + 64 + d]  + gh_s[r*192 + 64 + d]);
        float n  = tanhf(gi_s[r*192 + 128 + d] + rr * gh_s[r*192 + 128 + d]);
        hn_s[t] = (1.f - z)*n + z*h_s[t];
    }
    __syncthreads();                                 // (3) hn ready

    // Phase D: LayerNorm (mlp)
    if (t < 128) {
        int r = t >> 5, lane = t & 31;
        float x0 = hn_s[r*64 + lane], x1 = hn_s[r*64 + 32 + lane];
        float s = x0 + x1, ss = x0*x0 + x1*x1;
        #pragma unroll
        for (int o = 16; o > 0; o >>= 1) { s += __shfl_xor_sync(~0u, s, o); ss += __shfl_xor_sync(~0u, ss, o); }
        float mu = s * 0.015625f;
        float rstd = rsqrtf(ss * 0.015625f - mu*mu + 1e-5f);
        ln_s[r*64 + lane]      = (x0 - mu)*rstd*__ldg(lng+lane)    + __ldg(lnb+lane);
        ln_s[r*64 + 32 + lane] = (x1 - mu)*rstd*__ldg(lng+32+lane) + __ldg(lnb+32+lane);
    }
    asm volatile("cp.async.wait_group 0;" ::: "memory");
    __syncthreads();                                 // (4) ln_s + w1/w2/Wq ready

    // C_w1: t<128, 4 rows
    if (t < 128) {
        const float4* W  = (const float4*)(wbuf + t*68);
        const float4* X0 = (const float4*)(ln_s);
        const float4* X1 = (const float4*)(ln_s + 64);
        const float4* X2 = (const float4*)(ln_s + 128);
        const float4* X3 = (const float4*)(ln_s + 192);
        float e0 = 0.f, e1 = 0.f, e2 = 0.f, e3 = 0.f;
        #pragma unroll
        for (int i = 0; i < 16; i++) {
            float4 w = W[i];
            e0 += dot4(X0[i], w); e1 += dot4(X1[i], w);
            e2 += dot4(X2[i], w); e3 += dot4(X3[i], w);
        }
        float bias = __ldg(b1 + t);
        h1_s[t]       = fmaxf(e0 + bias, 0.f);
        h1_s[128 + t] = fmaxf(e1 + bias, 0.f);
        h1_s[256 + t] = fmaxf(e2 + bias, 0.f);
        h1_s[384 + t] = fmaxf(e3 + bias, 0.f);
    }
    __syncthreads();                                 // (5) h1 ready

    // C_w2: t<256 (row fr, output fo)
    int fr = (t >> 6) & 3, fo = t & 63;
    if (t < 256) {
        const float4* W = (const float4*)(wbuf + 8704 + fo*132);
        const float4* H = (const float4*)(h1_s + fr*128);
        float a = 0.f;
        #pragma unroll
        for (int i = 0; i < 32; i++) a += dot4(H[i], W[i]);
        a += __ldg(b2 + fo);
        float res = hn_s[fr*64 + fo] + a;
        int grow = grow0 + fr;
        g_slots[grow*64 + fo] = res;
        if (last) out[grow*64 + fo] = res;
        u_s[t] = res;
    }
    __syncthreads();                                 // (6) u_s ready
    if (last) return;

    // q-LN
    if (t < 128) {
        int r = t >> 5, lane = t & 31;
        float x0 = u_s[r*64 + lane], x1 = u_s[r*64 + 32 + lane];
        float s = x0 + x1, ss = x0*x0 + x1*x1;
        #pragma unroll
        for (int o = 16; o > 0; o >>= 1) { s += __shfl_xor_sync(~0u, s, o); ss += __shfl_xor_sync(~0u, ss, o); }
        float mu = s * 0.015625f;
        float rstd = rsqrtf(ss * 0.015625f - mu*mu + 1e-5f);
        ln_s[r*64 + lane]      = (x0 - mu)*rstd*__ldg(lng2+lane)    + __ldg(lnb2+lane);
        ln_s[r*64 + 32 + lane] = (x1 - mu)*rstd*__ldg(lng2+32+lane) + __ldg(lnb2+32+lane);
    }
    __syncthreads();                                 // (7) ln_s ready (Wq staged long ago)

    if (t < 256) {
        int r = t >> 6, e = t & 63;
        const float4* W = (const float4*)(wbuf + 17152 + e*68);
        const float4* X = (const float4*)(ln_s + r*64);
        float a = 0.f;
        #pragma unroll
        for (int i = 0; i < 16; i++) a += dot4(X[i], W[i]);
        int grow = grow0 + r;
        int b = grow >> 3, k = grow & 7;
        g_q[b*512 + e*8 + k] = a;
    }
}

extern "C" void kernel_launch(void* const* d_in, const int* in_sizes, int n_in,
                              void* d_out, int out_size) {
    const float* inputs = (const float*)d_in[0];
    const float* noise  = (const float*)d_in[1];
    const float* mu     = (const float*)d_in[2];
    const float* lsig   = (const float*)d_in[3];
    const float* Wq     = (const float*)d_in[4];
    const float* Wk     = (const float*)d_in[5];
    const float* Wv     = (const float*)d_in[6];
    const float* wih    = (const float*)d_in[7];
    const float* whh    = (const float*)d_in[8];
    const float* bih    = (const float*)d_in[9];
    const float* bhh    = (const float*)d_in[10];
    const float* w1     = (const float*)d_in[11];
    const float* b1     = (const float*)d_in[12];
    const float* w2     = (const float*)d_in[13];
    const float* b2     = (const float*)d_in[14];
    const float* ln_in_g   = (const float*)d_in[15];
    const float* ln_in_b   = (const float*)d_in[16];
    const float* ln_sl_g   = (const float*)d_in[17];
    const float* ln_sl_b   = (const float*)d_in[18];
    const float* ln_mlp_g  = (const float*)d_in[19];
    const float* ln_mlp_b  = (const float*)d_in[20];
    float* out = (float*)d_out;

    const int GRU_SMEM = 26112 * 4;   // 104.4 KB dynamic
    cudaFuncSetAttribute(gru_mlp, cudaFuncAttributeMaxDynamicSharedMemorySize, GRU_SMEM);

    prep<<<128, 256>>>(Wq, noise, mu, lsig, ln_sl_g, ln_sl_b);
    ln_kv<<<4096, 256>>>(inputs, Wk, Wv, ln_in_g, ln_in_b);
    for (int it = 0; it < 3; it++) {
        attn_kernel<<<dim3(8, 64), 256>>>();
        gru_mlp<<<128, 384, GRU_SMEM>>>(wih, whh, bih, bhh, w1, b1, w2, b2, Wq,
                                        ln_mlp_g, ln_mlp_b, ln_sl_g, ln_sl_b, out, it == 2);
    }
}